// round 2
// baseline (speedup 1.0000x reference)
#include <cuda_runtime.h>
#include <math.h>
#include <float.h>

#define Bn 2
#define Sn 1024
#define HIDn 2048
#define NHn 16
#define NKVn 8
#define Dn 128
#define Mn (Bn*Sn)
#define QNn (NHn*Dn)
#define KNn (NKVn*Dn)
#define FQEPS 1.5259021896696422e-09f
#define N_HS (Mn*HIDn)
#define N_Q  (Mn*QNn)
#define N_K  (Mn*KNn)
#define N_SC ((size_t)Bn*NHn*Sn*Sn)
#define NROWS (Bn*NHn*Sn)
#define OUT_MAIN (Mn*HIDn)

enum {S_HS=0,S_QLIN,S_QRMS,S_QRMS2,S_KLIN,S_KRMS,S_KRMS2,S_QP1,S_QP2,S_QSUM,
      S_KP1,S_KP2,S_KSUM,S_V,S_SC,S_AMIN,S_AMIN2,S_UNM,S_P,S_CTX,NSLOT};

__device__ float g_red[2*NSLOT];
__device__ float g_hsq[N_HS];
__device__ float g_Wqd[QNn*HIDn];
__device__ float g_Wkd[KNn*HIDn];
__device__ float g_Wvd[KNn*HIDn];
__device__ float g_Wod[HIDn*QNn];
__device__ float g_lin[N_Q];
__device__ float g_p1[N_Q];
__device__ float g_p2[N_Q];
__device__ float g_qr[N_Q];
__device__ float g_kr[N_K];
__device__ float g_v[N_K];
__device__ float g_ctx[N_Q];
__device__ float g_scores[N_SC];
__device__ float g_amin[NROWS];

__device__ __forceinline__ void atomicMinF(float* a,float v){
  int* ai=(int*)a; int cur=*ai;
  while(v<__int_as_float(cur)){int old=atomicCAS(ai,cur,__float_as_int(v)); if(old==cur)break; cur=old;}
}
__device__ __forceinline__ void atomicMaxF(float* a,float v){
  int* ai=(int*)a; int cur=*ai;
  while(v>__int_as_float(cur)){int old=atomicCAS(ai,cur,__float_as_int(v)); if(old==cur)break; cur=old;}
}
__device__ __forceinline__ float warp_min(float v){
  #pragma unroll
  for(int o=16;o;o>>=1) v=fminf(v,__shfl_xor_sync(0xffffffffu,v,o));
  return v;
}
__device__ __forceinline__ float warp_max(float v){
  #pragma unroll
  for(int o=16;o;o>>=1) v=fmaxf(v,__shfl_xor_sync(0xffffffffu,v,o));
  return v;
}
__device__ __forceinline__ float warp_sum(float v){
  #pragma unroll
  for(int o=16;o;o>>=1) v+=__shfl_xor_sync(0xffffffffu,v,o);
  return v;
}
__device__ __forceinline__ void red_minmax_atomic(float lmn,float lmx,int slot){
  __shared__ float smn[8],smx[8];
  lmn=warp_min(lmn); lmx=warp_max(lmx);
  int lane=threadIdx.x&31,w=threadIdx.x>>5,nw=(blockDim.x+31)>>5;
  __syncthreads();
  if(lane==0){smn[w]=lmn;smx[w]=lmx;}
  __syncthreads();
  if(w==0){
    lmn=(lane<nw)?smn[lane]:FLT_MAX;
    lmx=(lane<nw)?smx[lane]:-FLT_MAX;
    lmn=warp_min(lmn); lmx=warp_max(lmx);
    if(lane==0){atomicMinF(&g_red[2*slot],lmn); atomicMaxF(&g_red[2*slot+1],lmx);}
  }
}
__device__ __forceinline__ float blk_min_b(float v){
  __shared__ float sh[8]; __shared__ float r;
  v=warp_min(v);
  int lane=threadIdx.x&31,w=threadIdx.x>>5,nw=(blockDim.x+31)>>5;
  __syncthreads();
  if(lane==0) sh[w]=v;
  __syncthreads();
  if(threadIdx.x==0){float m=FLT_MAX; for(int i=0;i<nw;i++)m=fminf(m,sh[i]); r=m;}
  __syncthreads();
  return r;
}
__device__ __forceinline__ float blk_max_b(float v){
  __shared__ float sh[8]; __shared__ float r;
  v=warp_max(v);
  int lane=threadIdx.x&31,w=threadIdx.x>>5,nw=(blockDim.x+31)>>5;
  __syncthreads();
  if(lane==0) sh[w]=v;
  __syncthreads();
  if(threadIdx.x==0){float m=-FLT_MAX; for(int i=0;i<nw;i++)m=fmaxf(m,sh[i]); r=m;}
  __syncthreads();
  return r;
}
__device__ __forceinline__ float blk_sum_b(float v){
  __shared__ float sh[8]; __shared__ float r;
  v=warp_sum(v);
  int lane=threadIdx.x&31,w=threadIdx.x>>5,nw=(blockDim.x+31)>>5;
  __syncthreads();
  if(lane==0) sh[w]=v;
  __syncthreads();
  if(threadIdx.x==0){float m=0.f; for(int i=0;i<nw;i++)m+=sh[i]; r=m;}
  __syncthreads();
  return r;
}
__device__ __forceinline__ float fq_range_d(float x,float mn,float mx){
  float scale=fmaxf((mx-mn)/65535.0f,FQEPS);
  float zp=rintf(-mn/scale);
  float q=fminf(fmaxf(rintf(x/scale)+zp,0.0f),65535.0f);
  return (q-zp)*scale;
}
// transforms: 0 none, 1 fq16(slot), 2 fq16(slot) then fq8_sym (analytic absmax)
__device__ __forceinline__ void get_params(int t,int s,float&a0,float&a1,float&a2){
  if(t==0){a0=0;a1=0;a2=1;return;}
  float mn=g_red[2*s],mx=g_red[2*s+1];
  a0=fminf(mn,0.f); a1=fmaxf(mx,0.f); a2=1;
  if(t==2){
    float lo=fq_range_d(mn,a0,a1),hi=fq_range_d(mx,a0,a1);
    a2=fmaxf(fmaxf(fabsf(lo),fabsf(hi))/127.0f,1e-12f);
  }
}
__device__ __forceinline__ float xform(float v,int t,float a0,float a1,float a2){
  if(t==0) return v;
  v=fq_range_d(v,a0,a1);
  if(t==2) v=fminf(fmaxf(rintf(v/a2),-128.f),127.f)*a2;
  return v;
}

__global__ void k_init(){
  int i=threadIdx.x;
  if(i<NSLOT){g_red[2*i]=FLT_MAX; g_red[2*i+1]=-FLT_MAX;}
}
__global__ void k_wquant(const float* __restrict__ W,float* __restrict__ Wd){
  int g=blockIdx.x*blockDim.x+threadIdx.x;
  float w=W[g];
  float a=fabsf(w);
  #pragma unroll
  for(int o=16;o;o>>=1) a=fmaxf(a,__shfl_xor_sync(0xffffffffu,a,o));
  float s=fmaxf(a/7.0f,1e-12f);
  Wd[g]=fminf(fmaxf(rintf(w/s),-8.0f),7.0f)*s;
}
__global__ void k_minmax(const float* __restrict__ x,int n,int slot){
  int i=blockIdx.x*blockDim.x+threadIdx.x, st=gridDim.x*blockDim.x;
  float lmn=FLT_MAX,lmx=-FLT_MAX;
  for(;i<n;i+=st){float v=x[i]; lmn=fminf(lmn,v); lmx=fmaxf(lmx,v);}
  red_minmax_atomic(lmn,lmx,slot);
}
__global__ void k_fq(const float* __restrict__ in,float* __restrict__ out,int n,int sIn){
  float mn=fminf(g_red[2*sIn],0.f),mx=fmaxf(g_red[2*sIn+1],0.f);
  int i=blockIdx.x*blockDim.x+threadIdx.x, st=gridDim.x*blockDim.x;
  for(;i<n;i+=st) out[i]=fq_range_d(in[i],mn,mx);
}
__global__ void k_rms(float* __restrict__ x,const float* __restrict__ w,
                      int sIn,int sOut,int sOut2){
  int row=blockIdx.x,d=threadIdx.x;
  float mn=fminf(g_red[2*sIn],0.f),mx=fmaxf(g_red[2*sIn+1],0.f);
  size_t idx=(size_t)row*Dn+d;
  float v=fq_range_d(x[idx],mn,mx);
  float s=warp_sum(v*v);
  __shared__ float sh[4];
  if((d&31)==0) sh[d>>5]=s;
  __syncthreads();
  float var=(sh[0]+sh[1]+sh[2]+sh[3])*(1.0f/128.0f);
  float y=v*(1.0f/sqrtf(var+1e-6f))*w[d];
  x[idx]=y;
  red_minmax_atomic(y,y,sOut);
  float m2n=(d>=64)?y:FLT_MAX, m2x=(d>=64)?y:-FLT_MAX;
  red_minmax_atomic(m2n,m2x,sOut2);
}
__global__ void k_rope1(const float* __restrict__ y,const float* __restrict__ cosb,
                        const float* __restrict__ sinb,float* __restrict__ p1,
                        float* __restrict__ p2,int H,int n,
                        int sRMS,int sRMS2,int sP1,int sP2){
  float mnY=g_red[2*sRMS],mxY=g_red[2*sRMS+1];
  float c10=fminf(mnY,0.f),c11=fmaxf(mxY,0.f);
  float amn=fq_range_d(mnY,c10,c11),amx=fq_range_d(mxY,c10,c11);
  float c20=fminf(amn,0.f),c21=fmaxf(amx,0.f);
  float y2n=g_red[2*sRMS2],y2x=g_red[2*sRMS2+1];
  float x2n=fq_range_d(fq_range_d(y2n,c10,c11),c20,c21);
  float x2x=fq_range_d(fq_range_d(y2x,c10,c11),c20,c21);
  float nTn=-x2x,nTx=-x2n;
  float n0=fminf(nTn,0.f),n1=fmaxf(nTx,0.f);
  float negLo=fq_range_d(nTn,n0,n1),negHi=fq_range_d(nTx,n0,n1);
  float qbMn=fq_range_d(amn,c20,c21),qbMx=fq_range_d(amx,c20,c21);
  float cc0=fminf(fminf(qbMn,negLo),0.f),cc1=fmaxf(fmaxf(qbMx,negHi),0.f);
  int i0=blockIdx.x*blockDim.x+threadIdx.x, st=gridDim.x*blockDim.x;
  float l1n=FLT_MAX,l1x=-FLT_MAX,l2n=FLT_MAX,l2x=-FLT_MAX;
  for(int i=i0;i<n;i+=st){
    int d=i%Dn; int r=i/Dn; int s=(r/H)%Sn; int b=r/(H*Sn);
    float qb=fq_range_d(fq_range_d(y[i],c10,c11),c20,c21);
    float rot;
    if(d<64){
      float qbp=fq_range_d(fq_range_d(y[i+64],c10,c11),c20,c21);
      rot=fq_range_d(fq_range_d(-qbp,n0,n1),cc0,cc1);
    } else {
      float qbp=fq_range_d(fq_range_d(y[i-64],c10,c11),c20,c21);
      rot=fq_range_d(qbp,cc0,cc1);
    }
    int ci=(b*Sn+s)*Dn+d;
    float v1=qb*cosb[ci], v2=rot*sinb[ci];
    p1[i]=v1; p2[i]=v2;
    l1n=fminf(l1n,v1); l1x=fmaxf(l1x,v1);
    l2n=fminf(l2n,v2); l2x=fmaxf(l2x,v2);
  }
  red_minmax_atomic(l1n,l1x,sP1);
  red_minmax_atomic(l2n,l2x,sP2);
}
__global__ void k_rope2(const float* __restrict__ p1,const float* __restrict__ p2,
                        float* __restrict__ out,int H,int n,int sP1,int sP2,int sSum){
  float a0=fminf(g_red[2*sP1],0.f),a1=fmaxf(g_red[2*sP1+1],0.f);
  float b0=fminf(g_red[2*sP2],0.f),b1=fmaxf(g_red[2*sP2+1],0.f);
  int i0=blockIdx.x*blockDim.x+threadIdx.x, st=gridDim.x*blockDim.x;
  float lmn=FLT_MAX,lmx=-FLT_MAX;
  for(int i=i0;i<n;i+=st){
    float v=fq_range_d(p1[i],a0,a1)+fq_range_d(p2[i],b0,b1);
    int d=i%Dn; int r=i/Dn; int h=r%H; int s=(r/H)%Sn; int b=r/(H*Sn);
    out[((size_t)(b*H+h)*Sn+s)*Dn+d]=v;
    lmn=fminf(lmn,v); lmx=fmaxf(lmx,v);
  }
  red_minmax_atomic(lmn,lmx,sSum);
}
// C = A @ B^T ; A:MxK lda, B:NxK ldb, C:MxN ldc. mode 1 = QK batching over z.
__global__ void gemm_nt(const float* __restrict__ A,const float* __restrict__ B,
                        float* __restrict__ C,int M,int N,int K,
                        int lda,int ldb,int ldc,
                        int tA,int sA,int tB,int sB,int sOut,int mode){
  int z=blockIdx.z;
  if(mode==1){
    int b=z>>4,h=z&15;
    A+=(size_t)z*Sn*Dn;
    B+=(size_t)(b*NKVn+(h>>1))*Sn*Dn;
    C+=(size_t)z*Sn*Sn;
  }
  float a0,a1,a2,b0,b1,b2;
  get_params(tA,sA,a0,a1,a2);
  get_params(tB,sB,b0,b1,b2);
  __shared__ float As[16][64],Bs[16][64];
  int tx=threadIdx.x%16,ty=threadIdx.x/16;
  int m0=blockIdx.y*64,n0=blockIdx.x*64;
  float acc[4][4]={};
  int lr=threadIdx.x/4, lk=(threadIdx.x%4)*4;
  for(int k0=0;k0<K;k0+=16){
    #pragma unroll
    for(int i=0;i<4;i++){
      As[lk+i][lr]=xform(A[(size_t)(m0+lr)*lda+k0+lk+i],tA,a0,a1,a2);
      Bs[lk+i][lr]=xform(B[(size_t)(n0+lr)*ldb+k0+lk+i],tB,b0,b1,b2);
    }
    __syncthreads();
    #pragma unroll
    for(int k=0;k<16;k++){
      float av[4],bv[4];
      #pragma unroll
      for(int i=0;i<4;i++){av[i]=As[k][ty*4+i]; bv[i]=Bs[k][tx*4+i];}
      #pragma unroll
      for(int i=0;i<4;i++)
        #pragma unroll
        for(int j=0;j<4;j++) acc[i][j]=fmaf(av[i],bv[j],acc[i][j]);
    }
    __syncthreads();
  }
  float lmn=FLT_MAX,lmx=-FLT_MAX;
  #pragma unroll
  for(int i=0;i<4;i++)
    #pragma unroll
    for(int j=0;j<4;j++){
      float v=acc[i][j];
      C[(size_t)(m0+ty*4+i)*ldc+n0+tx*4+j]=v;
      lmn=fminf(lmn,v); lmx=fmaxf(lmx,v);
    }
  if(sOut>=0) red_minmax_atomic(lmn,lmx,sOut);
}
// AV: C[b,s,h*128+d] = sum_t P[b,h,s,t] * fq8(fq16(V[b,t,h2*128+d]))
__global__ void gemm_nn_av(const float* __restrict__ Pm,const float* __restrict__ Vm,
                           float* __restrict__ Cm){
  int z=blockIdx.z,b=z>>4,h=z&15,h2=h>>1;
  const float* A=Pm+(size_t)z*Sn*Sn;
  const float* Bv=Vm+(size_t)b*Sn*KNn+h2*Dn;
  float* C=Cm+(size_t)b*Sn*QNn+h*Dn;
  float b0,b1,b2;
  get_params(2,S_V,b0,b1,b2);
  __shared__ float As[16][64],Bs[16][64];
  int tx=threadIdx.x%16,ty=threadIdx.x/16;
  int m0=blockIdx.y*64,n0=blockIdx.x*64;
  float acc[4][4]={};
  int lr=threadIdx.x/4, lk=(threadIdx.x%4)*4;
  int bk=threadIdx.x/16, bn=(threadIdx.x%16)*4;
  for(int k0=0;k0<Sn;k0+=16){
    #pragma unroll
    for(int i=0;i<4;i++) As[lk+i][lr]=A[(size_t)(m0+lr)*Sn+k0+lk+i];
    #pragma unroll
    for(int i=0;i<4;i++)
      Bs[bk][bn+i]=xform(Bv[(size_t)(k0+bk)*KNn+n0+bn+i],2,b0,b1,b2);
    __syncthreads();
    #pragma unroll
    for(int k=0;k<16;k++){
      float av[4],bv[4];
      #pragma unroll
      for(int i=0;i<4;i++){av[i]=As[k][ty*4+i]; bv[i]=Bs[k][tx*4+i];}
      #pragma unroll
      for(int i=0;i<4;i++)
        #pragma unroll
        for(int j=0;j<4;j++) acc[i][j]=fmaf(av[i],bv[j],acc[i][j]);
    }
    __syncthreads();
  }
  float lmn=FLT_MAX,lmx=-FLT_MAX;
  #pragma unroll
  for(int i=0;i<4;i++)
    #pragma unroll
    for(int j=0;j<4;j++){
      float v=acc[i][j];
      C[(size_t)(m0+ty*4+i)*QNn+n0+tx*4+j]=v;
      lmn=fminf(lmn,v); lmx=fmaxf(lmx,v);
    }
  red_minmax_atomic(lmn,lmx,S_CTX);
}
__global__ void k_p1(float* __restrict__ sc,float* __restrict__ amin){
  int row=blockIdx.x; int s=row%Sn;
  float mnS=g_red[2*S_SC],mxS=g_red[2*S_SC+1];
  float q0=fminf(mnS,0.f),q1=fmaxf(mxS,0.f);
  float scal=(float)(0.08838834764831843);
  float scq=fq_range_d(scal,fminf(scal,0.f),fmaxf(scal,0.f));
  float lo=fq_range_d(mnS,q0,q1)*scq,hi=fq_range_d(mxS,q0,q1)*scq;
  float r0=fminf(lo,0.f),r1=fmaxf(hi,0.f);
  size_t base=(size_t)row*Sn;
  float rmn=FLT_MAX,umn=FLT_MAX,umx=-FLT_MAX;
  for(int t=threadIdx.x;t<Sn;t+=blockDim.x){
    float a=fq_range_d(fq_range_d(sc[base+t],q0,q1)*scq,r0,r1);
    sc[base+t]=a;
    rmn=fminf(rmn,a);
    if(t<=s){umn=fminf(umn,a); umx=fmaxf(umx,a);}
  }
  float am=blk_min_b(rmn);
  if(threadIdx.x==0){
    amin[row]=am;
    atomicMinF(&g_red[2*S_AMIN],am); atomicMaxF(&g_red[2*S_AMIN+1],am);
    if(s<Sn-1){atomicMinF(&g_red[2*S_AMIN2],am); atomicMaxF(&g_red[2*S_AMIN2+1],am);}
  }
  red_minmax_atomic(umn,umx,S_UNM);
}
__global__ void k_p2(float* __restrict__ sc,const float* __restrict__ amin){
  int row=blockIdx.x; int s=row%Sn;
  float an=g_red[2*S_AMIN],ax=g_red[2*S_AMIN+1];
  float a0=fminf(an,0.f),a1=fmaxf(ax,0.f);
  float c20=fq_range_d(-20.0f,-20.0f,0.0f);
  float tn=fq_range_d(an,a0,a1)+c20,tx2=fq_range_d(ax,a0,a1)+c20;
  float v0=fminf(tn,0.f),v1=fmaxf(tx2,0.f);
  float a2n=g_red[2*S_AMIN2],a2x=g_red[2*S_AMIN2+1];
  float vlo=fq_range_d(fq_range_d(a2n,a0,a1)+c20,v0,v1);
  float vhi=fq_range_d(fq_range_d(a2x,a0,a1)+c20,v0,v1);
  float un=g_red[2*S_UNM],ux=g_red[2*S_UNM+1];
  float m0=fminf(fminf(un,vlo),0.f),m1=fmaxf(fmaxf(ux,vhi),0.f);
  float vv=fq_range_d(fq_range_d(amin[row],a0,a1)+c20,v0,v1);
  float vm=fq_range_d(vv,m0,m1);
  size_t base=(size_t)row*Sn;
  float lmx=-FLT_MAX;
  for(int t=threadIdx.x;t<Sn;t+=blockDim.x){
    float x=(t<=s)?fq_range_d(sc[base+t],m0,m1):vm;
    sc[base+t]=x;
    lmx=fmaxf(lmx,x);
  }
  float m=blk_max_b(lmx);
  float ls=0.f;
  for(int t=threadIdx.x;t<Sn;t+=blockDim.x) ls+=expf(sc[base+t]-m);
  float sum=blk_sum_b(ls);
  float pn=FLT_MAX,px=-FLT_MAX;
  for(int t=threadIdx.x;t<Sn;t+=blockDim.x){
    float p=expf(sc[base+t]-m)/sum;
    sc[base+t]=p;
    pn=fminf(pn,p); px=fmaxf(px,p);
  }
  red_minmax_atomic(pn,px,S_P);
}
__global__ void k_p3(float* __restrict__ sc,float* __restrict__ outAttn,int wAttn){
  float p0=fminf(g_red[2*S_P],0.f),p1=fmaxf(g_red[2*S_P+1],0.f);
  size_t i=(size_t)blockIdx.x*blockDim.x+threadIdx.x;
  size_t st=(size_t)gridDim.x*blockDim.x;
  for(;i<N_SC;i+=st){
    float v=fq_range_d(sc[i],p0,p1);
    sc[i]=v;
    if(wAttn) outAttn[i]=v;
  }
}

extern "C" void kernel_launch(void* const* d_in,const int* in_sizes,int n_in,
                              void* d_out,int out_size){
  const float* hs  =(const float*)d_in[0];
  const float* cosb=(const float*)d_in[1];
  const float* sinb=(const float*)d_in[2];
  const float* Wq  =(const float*)d_in[4];
  const float* Wk  =(const float*)d_in[5];
  const float* Wv  =(const float*)d_in[6];
  const float* Wo  =(const float*)d_in[7];
  const float* qw  =(const float*)d_in[8];
  const float* kw  =(const float*)d_in[9];
  float* out=(float*)d_out;

  float *pHsq,*pWqd,*pWkd,*pWvd,*pWod,*pLin,*pP1,*pP2,*pQr,*pKr,*pV,*pCtx,*pSc,*pAmin;
  cudaGetSymbolAddress((void**)&pHsq,g_hsq);
  cudaGetSymbolAddress((void**)&pWqd,g_Wqd);
  cudaGetSymbolAddress((void**)&pWkd,g_Wkd);
  cudaGetSymbolAddress((void**)&pWvd,g_Wvd);
  cudaGetSymbolAddress((void**)&pWod,g_Wod);
  cudaGetSymbolAddress((void**)&pLin,g_lin);
  cudaGetSymbolAddress((void**)&pP1,g_p1);
  cudaGetSymbolAddress((void**)&pP2,g_p2);
  cudaGetSymbolAddress((void**)&pQr,g_qr);
  cudaGetSymbolAddress((void**)&pKr,g_kr);
  cudaGetSymbolAddress((void**)&pV,g_v);
  cudaGetSymbolAddress((void**)&pCtx,g_ctx);
  cudaGetSymbolAddress((void**)&pSc,g_scores);
  cudaGetSymbolAddress((void**)&pAmin,g_amin);

  k_init<<<1,64>>>();
  k_wquant<<<QNn*HIDn/256,256>>>(Wq,pWqd);
  k_wquant<<<KNn*HIDn/256,256>>>(Wk,pWkd);
  k_wquant<<<KNn*HIDn/256,256>>>(Wv,pWvd);
  k_wquant<<<HIDn*QNn/256,256>>>(Wo,pWod);
  k_minmax<<<1024,256>>>(hs,N_HS,S_HS);
  k_fq<<<2048,256>>>(hs,pHsq,N_HS,S_HS);
  // Q path
  gemm_nt<<<dim3(32,32,1),256>>>(pHsq,pWqd,pLin,Mn,QNn,HIDn,HIDn,HIDn,QNn,0,0,0,0,S_QLIN,0);
  k_rms<<<Mn*NHn,128>>>(pLin,qw,S_QLIN,S_QRMS,S_QRMS2);
  k_rope1<<<2048,256>>>(pLin,cosb,sinb,pP1,pP2,NHn,N_Q,S_QRMS,S_QRMS2,S_QP1,S_QP2);
  k_rope2<<<2048,256>>>(pP1,pP2,pQr,NHn,N_Q,S_QP1,S_QP2,S_QSUM);
  // K path
  gemm_nt<<<dim3(16,32,1),256>>>(pHsq,pWkd,pLin,Mn,KNn,HIDn,HIDn,HIDn,KNn,0,0,0,0,S_KLIN,0);
  k_rms<<<Mn*NKVn,128>>>(pLin,kw,S_KLIN,S_KRMS,S_KRMS2);
  k_rope1<<<1024,256>>>(pLin,cosb,sinb,pP1,pP2,NKVn,N_K,S_KRMS,S_KRMS2,S_KP1,S_KP2);
  k_rope2<<<1024,256>>>(pP1,pP2,pKr,NKVn,N_K,S_KP1,S_KP2,S_KSUM);
  // V path
  gemm_nt<<<dim3(16,32,1),256>>>(pHsq,pWvd,pV,Mn,KNn,HIDn,HIDn,HIDn,KNn,0,0,0,0,S_V,0);
  // scores
  gemm_nt<<<dim3(16,16,Bn*NHn),256>>>(pQr,pKr,pSc,Sn,Sn,Dn,Dn,Dn,Sn,1,S_QSUM,2,S_KSUM,S_SC,1);
  k_p1<<<NROWS,256>>>(pSc,pAmin);
  k_p2<<<NROWS,256>>>(pSc,pAmin);
  int wAttn=(out_size>=(int)(OUT_MAIN+N_SC))?1:0;
  k_p3<<<8192,256>>>(pSc,out+OUT_MAIN,wAttn);
  // AV + output proj
  gemm_nn_av<<<dim3(2,16,Bn*NHn),256>>>(pSc,pV,pCtx);
  gemm_nt<<<dim3(32,32,1),256>>>(pCtx,pWod,out,Mn,HIDn,QNn,QNn,QNn,HIDn,1,S_CTX,0,0,-1,0);
}

// round 3
// speedup vs baseline: 1.2851x; 1.2851x over previous
#include <cuda_runtime.h>
#include <math.h>
#include <float.h>

#define Bn 2
#define Sn 1024
#define HIDn 2048
#define NHn 16
#define NKVn 8
#define Dn 128
#define Mn (Bn*Sn)
#define QNn (NHn*Dn)
#define KNn (NKVn*Dn)
#define FQEPS 1.5259021896696422e-09f
#define N_HS (Mn*HIDn)
#define N_Q  (Mn*QNn)
#define N_K  (Mn*KNn)
#define N_SC ((size_t)Bn*NHn*Sn*Sn)
#define NROWS (Bn*NHn*Sn)
#define OUT_MAIN (Mn*HIDn)

enum {S_HS=0,S_QLIN,S_QRMS,S_QRMS2,S_KLIN,S_KRMS,S_KRMS2,S_QP1,S_QP2,S_QSUM,
      S_KP1,S_KP2,S_KSUM,S_V,S_SC,S_AMIN,S_AMIN2,S_UNM,S_P,S_CTX,NSLOT};

__device__ float g_red[2*NSLOT];
__device__ float g_hsq[N_HS];
__device__ float g_Wqd[QNn*HIDn];
__device__ float g_Wkd[KNn*HIDn];
__device__ float g_Wvd[KNn*HIDn];
__device__ float g_Wod[HIDn*QNn];
__device__ float g_lin[N_Q];
__device__ float g_p1[N_Q];
__device__ float g_p2[N_Q];
__device__ float g_qr[N_Q];
__device__ float g_kr[N_K];
__device__ float g_v[N_K];
__device__ float g_ctx[N_Q];
__device__ float g_scores[N_SC];
__device__ float g_amin[NROWS];

__device__ __forceinline__ void atomicMinF(float* a,float v){
  int* ai=(int*)a; int cur=*ai;
  while(v<__int_as_float(cur)){int old=atomicCAS(ai,cur,__float_as_int(v)); if(old==cur)break; cur=old;}
}
__device__ __forceinline__ void atomicMaxF(float* a,float v){
  int* ai=(int*)a; int cur=*ai;
  while(v>__int_as_float(cur)){int old=atomicCAS(ai,cur,__float_as_int(v)); if(old==cur)break; cur=old;}
}
__device__ __forceinline__ float warp_min(float v){
  #pragma unroll
  for(int o=16;o;o>>=1) v=fminf(v,__shfl_xor_sync(0xffffffffu,v,o));
  return v;
}
__device__ __forceinline__ float warp_max(float v){
  #pragma unroll
  for(int o=16;o;o>>=1) v=fmaxf(v,__shfl_xor_sync(0xffffffffu,v,o));
  return v;
}
__device__ __forceinline__ float warp_sum(float v){
  #pragma unroll
  for(int o=16;o;o>>=1) v+=__shfl_xor_sync(0xffffffffu,v,o);
  return v;
}
__device__ __forceinline__ void red_minmax_atomic(float lmn,float lmx,int slot){
  __shared__ float smn[8],smx[8];
  lmn=warp_min(lmn); lmx=warp_max(lmx);
  int lane=threadIdx.x&31,w=threadIdx.x>>5,nw=(blockDim.x+31)>>5;
  __syncthreads();
  if(lane==0){smn[w]=lmn;smx[w]=lmx;}
  __syncthreads();
  if(w==0){
    lmn=(lane<nw)?smn[lane]:FLT_MAX;
    lmx=(lane<nw)?smx[lane]:-FLT_MAX;
    lmn=warp_min(lmn); lmx=warp_max(lmx);
    if(lane==0){atomicMinF(&g_red[2*slot],lmn); atomicMaxF(&g_red[2*slot+1],lmx);}
  }
}
__device__ __forceinline__ float blk_min_b(float v){
  __shared__ float sh[8]; __shared__ float r;
  v=warp_min(v);
  int lane=threadIdx.x&31,w=threadIdx.x>>5,nw=(blockDim.x+31)>>5;
  __syncthreads();
  if(lane==0) sh[w]=v;
  __syncthreads();
  if(threadIdx.x==0){float m=FLT_MAX; for(int i=0;i<nw;i++)m=fminf(m,sh[i]); r=m;}
  __syncthreads();
  return r;
}
__device__ __forceinline__ float blk_max_b(float v){
  __shared__ float sh[8]; __shared__ float r;
  v=warp_max(v);
  int lane=threadIdx.x&31,w=threadIdx.x>>5,nw=(blockDim.x+31)>>5;
  __syncthreads();
  if(lane==0) sh[w]=v;
  __syncthreads();
  if(threadIdx.x==0){float m=-FLT_MAX; for(int i=0;i<nw;i++)m=fmaxf(m,sh[i]); r=m;}
  __syncthreads();
  return r;
}
__device__ __forceinline__ float blk_sum_b(float v){
  __shared__ float sh[8]; __shared__ float r;
  v=warp_sum(v);
  int lane=threadIdx.x&31,w=threadIdx.x>>5,nw=(blockDim.x+31)>>5;
  __syncthreads();
  if(lane==0) sh[w]=v;
  __syncthreads();
  if(threadIdx.x==0){float m=0.f; for(int i=0;i<nw;i++)m+=sh[i]; r=m;}
  __syncthreads();
  return r;
}
__device__ __forceinline__ float fq_range_d(float x,float mn,float mx){
  float scale=fmaxf((mx-mn)/65535.0f,FQEPS);
  float zp=rintf(-mn/scale);
  float q=fminf(fmaxf(rintf(x/scale)+zp,0.0f),65535.0f);
  return (q-zp)*scale;
}
__device__ __forceinline__ void get_params(int t,int s,float&a0,float&a1,float&a2){
  if(t==0){a0=0;a1=0;a2=1;return;}
  float mn=g_red[2*s],mx=g_red[2*s+1];
  a0=fminf(mn,0.f); a1=fmaxf(mx,0.f); a2=1;
  if(t==2){
    float lo=fq_range_d(mn,a0,a1),hi=fq_range_d(mx,a0,a1);
    a2=fmaxf(fmaxf(fabsf(lo),fabsf(hi))/127.0f,1e-12f);
  }
}
__device__ __forceinline__ float xform(float v,int t,float a0,float a1,float a2){
  if(t==0) return v;
  v=fq_range_d(v,a0,a1);
  if(t==2) v=fminf(fmaxf(rintf(v/a2),-128.f),127.f)*a2;
  return v;
}

__global__ void k_init(){
  int i=threadIdx.x;
  if(i<NSLOT){g_red[2*i]=FLT_MAX; g_red[2*i+1]=-FLT_MAX;}
}
__global__ void k_wquant(const float* __restrict__ W,float* __restrict__ Wd){
  int g=blockIdx.x*blockDim.x+threadIdx.x;
  float w=W[g];
  float a=fabsf(w);
  #pragma unroll
  for(int o=16;o;o>>=1) a=fmaxf(a,__shfl_xor_sync(0xffffffffu,a,o));
  float s=fmaxf(a/7.0f,1e-12f);
  Wd[g]=fminf(fmaxf(rintf(w/s),-8.0f),7.0f)*s;
}
__global__ void k_minmax(const float* __restrict__ x,int n,int slot){
  int i=blockIdx.x*blockDim.x+threadIdx.x, st=gridDim.x*blockDim.x;
  float lmn=FLT_MAX,lmx=-FLT_MAX;
  for(;i<n;i+=st){float v=x[i]; lmn=fminf(lmn,v); lmx=fmaxf(lmx,v);}
  red_minmax_atomic(lmn,lmx,slot);
}
__global__ void k_fq(const float* __restrict__ in,float* __restrict__ out,int n,int sIn){
  float mn=fminf(g_red[2*sIn],0.f),mx=fmaxf(g_red[2*sIn+1],0.f);
  int i=blockIdx.x*blockDim.x+threadIdx.x, st=gridDim.x*blockDim.x;
  for(;i<n;i+=st) out[i]=fq_range_d(in[i],mn,mx);
}
__global__ void k_rms(float* __restrict__ x,const float* __restrict__ w,
                      int sIn,int sOut,int sOut2){
  int row=blockIdx.x,d=threadIdx.x;
  float mn=fminf(g_red[2*sIn],0.f),mx=fmaxf(g_red[2*sIn+1],0.f);
  size_t idx=(size_t)row*Dn+d;
  float v=fq_range_d(x[idx],mn,mx);
  float s=warp_sum(v*v);
  __shared__ float sh[4];
  if((d&31)==0) sh[d>>5]=s;
  __syncthreads();
  float var=(sh[0]+sh[1]+sh[2]+sh[3])*(1.0f/128.0f);
  float y=v*(1.0f/sqrtf(var+1e-6f))*w[d];
  x[idx]=y;
  red_minmax_atomic(y,y,sOut);
  float m2n=(d>=64)?y:FLT_MAX, m2x=(d>=64)?y:-FLT_MAX;
  red_minmax_atomic(m2n,m2x,sOut2);
}
__global__ void k_rope1(const float* __restrict__ y,const float* __restrict__ cosb,
                        const float* __restrict__ sinb,float* __restrict__ p1,
                        float* __restrict__ p2,int H,int n,
                        int sRMS,int sRMS2,int sP1,int sP2){
  float mnY=g_red[2*sRMS],mxY=g_red[2*sRMS+1];
  float c10=fminf(mnY,0.f),c11=fmaxf(mxY,0.f);
  float amn=fq_range_d(mnY,c10,c11),amx=fq_range_d(mxY,c10,c11);
  float c20=fminf(amn,0.f),c21=fmaxf(amx,0.f);
  float y2n=g_red[2*sRMS2],y2x=g_red[2*sRMS2+1];
  float x2n=fq_range_d(fq_range_d(y2n,c10,c11),c20,c21);
  float x2x=fq_range_d(fq_range_d(y2x,c10,c11),c20,c21);
  float nTn=-x2x,nTx=-x2n;
  float n0=fminf(nTn,0.f),n1=fmaxf(nTx,0.f);
  float negLo=fq_range_d(nTn,n0,n1),negHi=fq_range_d(nTx,n0,n1);
  float qbMn=fq_range_d(amn,c20,c21),qbMx=fq_range_d(amx,c20,c21);
  float cc0=fminf(fminf(qbMn,negLo),0.f),cc1=fmaxf(fmaxf(qbMx,negHi),0.f);
  int i0=blockIdx.x*blockDim.x+threadIdx.x, st=gridDim.x*blockDim.x;
  float l1n=FLT_MAX,l1x=-FLT_MAX,l2n=FLT_MAX,l2x=-FLT_MAX;
  for(int i=i0;i<n;i+=st){
    int d=i%Dn; int r=i/Dn; int s=(r/H)%Sn; int b=r/(H*Sn);
    float qb=fq_range_d(fq_range_d(y[i],c10,c11),c20,c21);
    float rot;
    if(d<64){
      float qbp=fq_range_d(fq_range_d(y[i+64],c10,c11),c20,c21);
      rot=fq_range_d(fq_range_d(-qbp,n0,n1),cc0,cc1);
    } else {
      float qbp=fq_range_d(fq_range_d(y[i-64],c10,c11),c20,c21);
      rot=fq_range_d(qbp,cc0,cc1);
    }
    int ci=(b*Sn+s)*Dn+d;
    float v1=qb*cosb[ci], v2=rot*sinb[ci];
    p1[i]=v1; p2[i]=v2;
    l1n=fminf(l1n,v1); l1x=fmaxf(l1x,v1);
    l2n=fminf(l2n,v2); l2x=fmaxf(l2x,v2);
  }
  red_minmax_atomic(l1n,l1x,sP1);
  red_minmax_atomic(l2n,l2x,sP2);
}
__global__ void k_rope2(const float* __restrict__ p1,const float* __restrict__ p2,
                        float* __restrict__ out,int H,int n,int sP1,int sP2,int sSum){
  float a0=fminf(g_red[2*sP1],0.f),a1=fmaxf(g_red[2*sP1+1],0.f);
  float b0=fminf(g_red[2*sP2],0.f),b1=fmaxf(g_red[2*sP2+1],0.f);
  int i0=blockIdx.x*blockDim.x+threadIdx.x, st=gridDim.x*blockDim.x;
  float lmn=FLT_MAX,lmx=-FLT_MAX;
  for(int i=i0;i<n;i+=st){
    float v=fq_range_d(p1[i],a0,a1)+fq_range_d(p2[i],b0,b1);
    int d=i%Dn; int r=i/Dn; int h=r%H; int s=(r/H)%Sn; int b=r/(H*Sn);
    out[((size_t)(b*H+h)*Sn+s)*Dn+d]=v;
    lmn=fminf(lmn,v); lmx=fmaxf(lmx,v);
  }
  red_minmax_atomic(lmn,lmx,sSum);
}

// ---- 128x128 tiled NT GEMM: C = A @ B^T, 8x8 microtile (4+4 split) ----
__global__ __launch_bounds__(256)
void gemm_nt(const float* __restrict__ A,const float* __restrict__ B,
             float* __restrict__ C,int K,int lda,int ldb,int ldc,
             int tA,int sA,int tB,int sB,int sOut,int mode){
  int z=blockIdx.z;
  if(mode==1){
    int b=z>>4,h=z&15;
    A+=(size_t)z*Sn*Dn;
    B+=(size_t)(b*NKVn+(h>>1))*Sn*Dn;
    C+=(size_t)z*Sn*Sn;
  }
  float a0,a1,a2,b0,b1,b2;
  get_params(tA,sA,a0,a1,a2);
  get_params(tB,sB,b0,b1,b2);
  __shared__ float As[16][128];
  __shared__ float Bs[16][128];
  int tid=threadIdx.x;
  int m0=blockIdx.y*128, n0=blockIdx.x*128;
  int lr=tid>>1, kc=(tid&1)*8;
  int tx=tid&15, ty=tid>>4;
  float acc[8][8]={};
  for(int k0=0;k0<K;k0+=16){
    const float* Ap=&A[(size_t)(m0+lr)*lda + k0+kc];
    float4 av4=*(const float4*)Ap;
    float4 av5=*(const float4*)(Ap+4);
    As[kc+0][lr]=xform(av4.x,tA,a0,a1,a2);
    As[kc+1][lr]=xform(av4.y,tA,a0,a1,a2);
    As[kc+2][lr]=xform(av4.z,tA,a0,a1,a2);
    As[kc+3][lr]=xform(av4.w,tA,a0,a1,a2);
    As[kc+4][lr]=xform(av5.x,tA,a0,a1,a2);
    As[kc+5][lr]=xform(av5.y,tA,a0,a1,a2);
    As[kc+6][lr]=xform(av5.z,tA,a0,a1,a2);
    As[kc+7][lr]=xform(av5.w,tA,a0,a1,a2);
    const float* Bp=&B[(size_t)(n0+lr)*ldb + k0+kc];
    float4 bv4=*(const float4*)Bp;
    float4 bv5=*(const float4*)(Bp+4);
    Bs[kc+0][lr]=xform(bv4.x,tB,b0,b1,b2);
    Bs[kc+1][lr]=xform(bv4.y,tB,b0,b1,b2);
    Bs[kc+2][lr]=xform(bv4.z,tB,b0,b1,b2);
    Bs[kc+3][lr]=xform(bv4.w,tB,b0,b1,b2);
    Bs[kc+4][lr]=xform(bv5.x,tB,b0,b1,b2);
    Bs[kc+5][lr]=xform(bv5.y,tB,b0,b1,b2);
    Bs[kc+6][lr]=xform(bv5.z,tB,b0,b1,b2);
    Bs[kc+7][lr]=xform(bv5.w,tB,b0,b1,b2);
    __syncthreads();
    #pragma unroll
    for(int k=0;k<16;k++){
      float4 aA=*(const float4*)&As[k][ty*4];
      float4 aB=*(const float4*)&As[k][64+ty*4];
      float4 bA=*(const float4*)&Bs[k][tx*4];
      float4 bB=*(const float4*)&Bs[k][64+tx*4];
      float av[8]={aA.x,aA.y,aA.z,aA.w,aB.x,aB.y,aB.z,aB.w};
      float bv[8]={bA.x,bA.y,bA.z,bA.w,bB.x,bB.y,bB.z,bB.w};
      #pragma unroll
      for(int i=0;i<8;i++)
        #pragma unroll
        for(int j=0;j<8;j++) acc[i][j]=fmaf(av[i],bv[j],acc[i][j]);
    }
    __syncthreads();
  }
  float lmn=FLT_MAX,lmx=-FLT_MAX;
  #pragma unroll
  for(int i=0;i<8;i++){
    int r=m0+((i<4)?(ty*4+i):(64+ty*4+i-4));
    #pragma unroll
    for(int j=0;j<8;j++){
      int c=n0+((j<4)?(tx*4+j):(64+tx*4+j-4));
      float v=acc[i][j];
      C[(size_t)r*ldc+c]=v;
      lmn=fminf(lmn,v); lmx=fmaxf(lmx,v);
    }
  }
  if(sOut>=0) red_minmax_atomic(lmn,lmx,sOut);
}

// ---- AV: C[b,s,h*128+d] = sum_t fq16(P)[z,s,t] * fq8(fq16(V[b,t,h2*128+d])) ----
__global__ __launch_bounds__(256)
void gemm_nn_av(const float* __restrict__ Pm,const float* __restrict__ Vm,
                float* __restrict__ Cm){
  int z=blockIdx.z,b=z>>4,h=z&15,h2=h>>1;
  const float* A=Pm+(size_t)z*Sn*Sn;
  const float* Bv=Vm+(size_t)b*Sn*KNn+h2*Dn;
  float* C=Cm+(size_t)b*Sn*QNn+h*Dn;
  float p0,p1_,p2_,b0,b1,b2;
  get_params(1,S_P,p0,p1_,p2_);
  get_params(2,S_V,b0,b1,b2);
  __shared__ float As[16][128];
  __shared__ float Bs[16][128];
  int tid=threadIdx.x;
  int m0=blockIdx.y*128;
  int lr=tid>>1, kc=(tid&1)*8;
  int bkr=tid>>4, bnc=(tid&15)*8;
  int tx=tid&15, ty=tid>>4;
  float acc[8][8]={};
  for(int k0=0;k0<Sn;k0+=16){
    const float* Ap=&A[(size_t)(m0+lr)*Sn + k0+kc];
    float4 av4=*(const float4*)Ap;
    float4 av5=*(const float4*)(Ap+4);
    As[kc+0][lr]=xform(av4.x,1,p0,p1_,p2_);
    As[kc+1][lr]=xform(av4.y,1,p0,p1_,p2_);
    As[kc+2][lr]=xform(av4.z,1,p0,p1_,p2_);
    As[kc+3][lr]=xform(av4.w,1,p0,p1_,p2_);
    As[kc+4][lr]=xform(av5.x,1,p0,p1_,p2_);
    As[kc+5][lr]=xform(av5.y,1,p0,p1_,p2_);
    As[kc+6][lr]=xform(av5.z,1,p0,p1_,p2_);
    As[kc+7][lr]=xform(av5.w,1,p0,p1_,p2_);
    const float* Bp=&Bv[(size_t)(k0+bkr)*KNn + bnc];
    float4 bv4=*(const float4*)Bp;
    float4 bv5=*(const float4*)(Bp+4);
    Bs[bkr][bnc+0]=xform(bv4.x,2,b0,b1,b2);
    Bs[bkr][bnc+1]=xform(bv4.y,2,b0,b1,b2);
    Bs[bkr][bnc+2]=xform(bv4.z,2,b0,b1,b2);
    Bs[bkr][bnc+3]=xform(bv4.w,2,b0,b1,b2);
    Bs[bkr][bnc+4]=xform(bv5.x,2,b0,b1,b2);
    Bs[bkr][bnc+5]=xform(bv5.y,2,b0,b1,b2);
    Bs[bkr][bnc+6]=xform(bv5.z,2,b0,b1,b2);
    Bs[bkr][bnc+7]=xform(bv5.w,2,b0,b1,b2);
    __syncthreads();
    #pragma unroll
    for(int k=0;k<16;k++){
      float4 aA=*(const float4*)&As[k][ty*4];
      float4 aB=*(const float4*)&As[k][64+ty*4];
      float4 bA=*(const float4*)&Bs[k][tx*4];
      float4 bB=*(const float4*)&Bs[k][64+tx*4];
      float av[8]={aA.x,aA.y,aA.z,aA.w,aB.x,aB.y,aB.z,aB.w};
      float bv[8]={bA.x,bA.y,bA.z,bA.w,bB.x,bB.y,bB.z,bB.w};
      #pragma unroll
      for(int i=0;i<8;i++)
        #pragma unroll
        for(int j=0;j<8;j++) acc[i][j]=fmaf(av[i],bv[j],acc[i][j]);
    }
    __syncthreads();
  }
  float lmn=FLT_MAX,lmx=-FLT_MAX;
  #pragma unroll
  for(int i=0;i<8;i++){
    int r=m0+((i<4)?(ty*4+i):(64+ty*4+i-4));
    #pragma unroll
    for(int j=0;j<8;j++){
      int c=(j<4)?(tx*4+j):(64+tx*4+j-4);
      float v=acc[i][j];
      C[(size_t)r*QNn+c]=v;
      lmn=fminf(lmn,v); lmx=fmaxf(lmx,v);
    }
  }
  red_minmax_atomic(lmn,lmx,S_CTX);
}

__global__ void k_p1(float* __restrict__ sc,float* __restrict__ amin){
  int row=blockIdx.x; int s=row%Sn;
  float mnS=g_red[2*S_SC],mxS=g_red[2*S_SC+1];
  float q0=fminf(mnS,0.f),q1=fmaxf(mxS,0.f);
  float scal=(float)(0.08838834764831843);
  float scq=fq_range_d(scal,fminf(scal,0.f),fmaxf(scal,0.f));
  float lo=fq_range_d(mnS,q0,q1)*scq,hi=fq_range_d(mxS,q0,q1)*scq;
  float r0=fminf(lo,0.f),r1=fmaxf(hi,0.f);
  size_t base=(size_t)row*Sn;
  float rmn=FLT_MAX,umn=FLT_MAX,umx=-FLT_MAX;
  for(int t=threadIdx.x;t<Sn;t+=blockDim.x){
    float a=fq_range_d(fq_range_d(sc[base+t],q0,q1)*scq,r0,r1);
    sc[base+t]=a;
    rmn=fminf(rmn,a);
    if(t<=s){umn=fminf(umn,a); umx=fmaxf(umx,a);}
  }
  float am=blk_min_b(rmn);
  if(threadIdx.x==0){
    amin[row]=am;
    atomicMinF(&g_red[2*S_AMIN],am); atomicMaxF(&g_red[2*S_AMIN+1],am);
    if(s<Sn-1){atomicMinF(&g_red[2*S_AMIN2],am); atomicMaxF(&g_red[2*S_AMIN2+1],am);}
  }
  red_minmax_atomic(umn,umx,S_UNM);
}
__global__ void k_p2(float* __restrict__ sc,const float* __restrict__ amin){
  __shared__ float rowbuf[Sn];
  int row=blockIdx.x; int s=row%Sn;
  float an=g_red[2*S_AMIN],ax=g_red[2*S_AMIN+1];
  float a0=fminf(an,0.f),a1=fmaxf(ax,0.f);
  float c20=fq_range_d(-20.0f,-20.0f,0.0f);
  float tn=fq_range_d(an,a0,a1)+c20,tx2=fq_range_d(ax,a0,a1)+c20;
  float v0=fminf(tn,0.f),v1=fmaxf(tx2,0.f);
  float a2n=g_red[2*S_AMIN2],a2x=g_red[2*S_AMIN2+1];
  float vlo=fq_range_d(fq_range_d(a2n,a0,a1)+c20,v0,v1);
  float vhi=fq_range_d(fq_range_d(a2x,a0,a1)+c20,v0,v1);
  float un=g_red[2*S_UNM],ux=g_red[2*S_UNM+1];
  float m0=fminf(fminf(un,vlo),0.f),m1=fmaxf(fmaxf(ux,vhi),0.f);
  float vv=fq_range_d(fq_range_d(amin[row],a0,a1)+c20,v0,v1);
  float vm=fq_range_d(vv,m0,m1);
  size_t base=(size_t)row*Sn;
  float lmx=-FLT_MAX;
  for(int t=threadIdx.x;t<Sn;t+=blockDim.x){
    float x=(t<=s)?fq_range_d(sc[base+t],m0,m1):vm;
    rowbuf[t]=x;
    lmx=fmaxf(lmx,x);
  }
  float m=blk_max_b(lmx);
  float ls=0.f;
  for(int t=threadIdx.x;t<Sn;t+=blockDim.x){
    float e=expf(rowbuf[t]-m);
    rowbuf[t]=e;
    ls+=e;
  }
  float sum=blk_sum_b(ls);
  float pn=FLT_MAX,px=-FLT_MAX;
  for(int t=threadIdx.x;t<Sn;t+=blockDim.x){
    float p=rowbuf[t]/sum;
    sc[base+t]=p;
    pn=fminf(pn,p); px=fmaxf(px,p);
  }
  red_minmax_atomic(pn,px,S_P);
}
__global__ void k_p3(const float* __restrict__ sc,float* __restrict__ outAttn){
  float p0=fminf(g_red[2*S_P],0.f),p1=fmaxf(g_red[2*S_P+1],0.f);
  size_t i=(size_t)blockIdx.x*blockDim.x+threadIdx.x;
  size_t st=(size_t)gridDim.x*blockDim.x;
  for(;i<N_SC;i+=st) outAttn[i]=fq_range_d(sc[i],p0,p1);
}

extern "C" void kernel_launch(void* const* d_in,const int* in_sizes,int n_in,
                              void* d_out,int out_size){
  const float* hs  =(const float*)d_in[0];
  const float* cosb=(const float*)d_in[1];
  const float* sinb=(const float*)d_in[2];
  const float* Wq  =(const float*)d_in[4];
  const float* Wk  =(const float*)d_in[5];
  const float* Wv  =(const float*)d_in[6];
  const float* Wo  =(const float*)d_in[7];
  const float* qw  =(const float*)d_in[8];
  const float* kw  =(const float*)d_in[9];
  float* out=(float*)d_out;

  float *pHsq,*pWqd,*pWkd,*pWvd,*pWod,*pLin,*pP1,*pP2,*pQr,*pKr,*pV,*pCtx,*pSc,*pAmin;
  cudaGetSymbolAddress((void**)&pHsq,g_hsq);
  cudaGetSymbolAddress((void**)&pWqd,g_Wqd);
  cudaGetSymbolAddress((void**)&pWkd,g_Wkd);
  cudaGetSymbolAddress((void**)&pWvd,g_Wvd);
  cudaGetSymbolAddress((void**)&pWod,g_Wod);
  cudaGetSymbolAddress((void**)&pLin,g_lin);
  cudaGetSymbolAddress((void**)&pP1,g_p1);
  cudaGetSymbolAddress((void**)&pP2,g_p2);
  cudaGetSymbolAddress((void**)&pQr,g_qr);
  cudaGetSymbolAddress((void**)&pKr,g_kr);
  cudaGetSymbolAddress((void**)&pV,g_v);
  cudaGetSymbolAddress((void**)&pCtx,g_ctx);
  cudaGetSymbolAddress((void**)&pSc,g_scores);
  cudaGetSymbolAddress((void**)&pAmin,g_amin);

  k_init<<<1,64>>>();
  k_wquant<<<QNn*HIDn/256,256>>>(Wq,pWqd);
  k_wquant<<<KNn*HIDn/256,256>>>(Wk,pWkd);
  k_wquant<<<KNn*HIDn/256,256>>>(Wv,pWvd);
  k_wquant<<<HIDn*QNn/256,256>>>(Wo,pWod);
  k_minmax<<<1024,256>>>(hs,N_HS,S_HS);
  k_fq<<<2048,256>>>(hs,pHsq,N_HS,S_HS);
  // Q path
  gemm_nt<<<dim3(QNn/128,Mn/128,1),256>>>(pHsq,pWqd,pLin,HIDn,HIDn,HIDn,QNn,0,0,0,0,S_QLIN,0);
  k_rms<<<Mn*NHn,128>>>(pLin,qw,S_QLIN,S_QRMS,S_QRMS2);
  k_rope1<<<2048,256>>>(pLin,cosb,sinb,pP1,pP2,NHn,N_Q,S_QRMS,S_QRMS2,S_QP1,S_QP2);
  k_rope2<<<2048,256>>>(pP1,pP2,pQr,NHn,N_Q,S_QP1,S_QP2,S_QSUM);
  // K path
  gemm_nt<<<dim3(KNn/128,Mn/128,1),256>>>(pHsq,pWkd,pLin,HIDn,HIDn,HIDn,KNn,0,0,0,0,S_KLIN,0);
  k_rms<<<Mn*NKVn,128>>>(pLin,kw,S_KLIN,S_KRMS,S_KRMS2);
  k_rope1<<<1024,256>>>(pLin,cosb,sinb,pP1,pP2,NKVn,N_K,S_KRMS,S_KRMS2,S_KP1,S_KP2);
  k_rope2<<<1024,256>>>(pP1,pP2,pKr,NKVn,N_K,S_KP1,S_KP2,S_KSUM);
  // V path
  gemm_nt<<<dim3(KNn/128,Mn/128,1),256>>>(pHsq,pWvd,pV,HIDn,HIDn,HIDn,KNn,0,0,0,0,S_V,0);
  // scores
  gemm_nt<<<dim3(Sn/128,Sn/128,Bn*NHn),256>>>(pQr,pKr,pSc,Dn,Dn,Dn,Sn,1,S_QSUM,2,S_KSUM,S_SC,1);
  k_p1<<<NROWS,256>>>(pSc,pAmin);
  k_p2<<<NROWS,256>>>(pSc,pAmin);
  if(out_size>=(int)(OUT_MAIN+N_SC))
    k_p3<<<8192,256>>>(pSc,out+OUT_MAIN);
  // AV (fq16(P) and fq8(fq16(V)) applied in-load) + output proj
  gemm_nn_av<<<dim3(1,Sn/128,Bn*NHn),256>>>(pSc,pV,pCtx);
  gemm_nt<<<dim3(HIDn/128,Mn/128,1),256>>>(pCtx,pWod,out,QNn,QNn,QNn,HIDn,1,S_CTX,0,0,-1,0);
}

// round 4
// speedup vs baseline: 2.1846x; 1.7000x over previous
#include <cuda_runtime.h>
#include <cuda_bf16.h>
#include <math.h>
#include <float.h>

#define Bn 2
#define Sn 1024
#define HIDn 2048
#define NHn 16
#define NKVn 8
#define Dn 128
#define Mn (Bn*Sn)
#define QNn (NHn*Dn)
#define KNn (NKVn*Dn)
#define FQEPS 1.5259021896696422e-09f
#define N_HS (Mn*HIDn)
#define N_Q  (Mn*QNn)
#define N_K  (Mn*KNn)
#define N_SC ((size_t)Bn*NHn*Sn*Sn)
#define NROWS (Bn*NHn*Sn)
#define OUT_MAIN (Mn*HIDn)

enum {S_HS=0,S_QLIN,S_QRMS,S_QRMS2,S_KLIN,S_KRMS,S_KRMS2,S_QP1,S_QP2,S_QSUM,
      S_KP1,S_KP2,S_KSUM,S_V,S_SC,S_AMIN,S_AMIN2,S_UNM,S_P,S_CTX,NSLOT};

__device__ float g_red[2*NSLOT];
__device__ float g_lin[N_Q];
__device__ float g_p1b[N_Q];
__device__ float g_p2b[N_Q];
__device__ float g_qr[N_Q];
__device__ float g_kr[N_K];
__device__ float g_v[N_K];
__device__ float g_ctx[N_Q];
__device__ float g_scores[N_SC];
__device__ float g_amin[NROWS];
// bf16 split buffers
__device__ __nv_bfloat16 g_hsh[N_HS], g_hsl[N_HS];
__device__ __nv_bfloat16 g_wqh[QNn*HIDn], g_wql[QNn*HIDn];
__device__ __nv_bfloat16 g_wkh[KNn*HIDn], g_wkl[KNn*HIDn];
__device__ __nv_bfloat16 g_wvh[KNn*HIDn], g_wvl[KNn*HIDn];
__device__ __nv_bfloat16 g_woh[HIDn*QNn], g_wol[HIDn*QNn];
__device__ __nv_bfloat16 g_qh[N_Q], g_ql[N_Q];
__device__ __nv_bfloat16 g_kq8[N_K];
__device__ __nv_bfloat16 g_vq8[N_K];
__device__ __nv_bfloat16 g_ph[N_SC], g_pl[N_SC];
__device__ __nv_bfloat16 g_ch[N_Q], g_cl[N_Q];

__device__ __forceinline__ void atomicMinF(float* a,float v){
  int* ai=(int*)a; int cur=*ai;
  while(v<__int_as_float(cur)){int old=atomicCAS(ai,cur,__float_as_int(v)); if(old==cur)break; cur=old;}
}
__device__ __forceinline__ void atomicMaxF(float* a,float v){
  int* ai=(int*)a; int cur=*ai;
  while(v>__int_as_float(cur)){int old=atomicCAS(ai,cur,__float_as_int(v)); if(old==cur)break; cur=old;}
}
__device__ __forceinline__ float warp_min(float v){
  #pragma unroll
  for(int o=16;o;o>>=1) v=fminf(v,__shfl_xor_sync(0xffffffffu,v,o));
  return v;
}
__device__ __forceinline__ float warp_max(float v){
  #pragma unroll
  for(int o=16;o;o>>=1) v=fmaxf(v,__shfl_xor_sync(0xffffffffu,v,o));
  return v;
}
__device__ __forceinline__ float warp_sum(float v){
  #pragma unroll
  for(int o=16;o;o>>=1) v+=__shfl_xor_sync(0xffffffffu,v,o);
  return v;
}
__device__ __forceinline__ void red_minmax_atomic(float lmn,float lmx,int slot){
  __shared__ float smn[8],smx[8];
  lmn=warp_min(lmn); lmx=warp_max(lmx);
  int lane=threadIdx.x&31,w=threadIdx.x>>5,nw=(blockDim.x+31)>>5;
  __syncthreads();
  if(lane==0){smn[w]=lmn;smx[w]=lmx;}
  __syncthreads();
  if(w==0){
    lmn=(lane<nw)?smn[lane]:FLT_MAX;
    lmx=(lane<nw)?smx[lane]:-FLT_MAX;
    lmn=warp_min(lmn); lmx=warp_max(lmx);
    if(lane==0){atomicMinF(&g_red[2*slot],lmn); atomicMaxF(&g_red[2*slot+1],lmx);}
  }
}
__device__ __forceinline__ float blk_min_b(float v){
  __shared__ float sh[8]; __shared__ float r;
  v=warp_min(v);
  int lane=threadIdx.x&31,w=threadIdx.x>>5,nw=(blockDim.x+31)>>5;
  __syncthreads();
  if(lane==0) sh[w]=v;
  __syncthreads();
  if(threadIdx.x==0){float m=FLT_MAX; for(int i=0;i<nw;i++)m=fminf(m,sh[i]); r=m;}
  __syncthreads();
  return r;
}
__device__ __forceinline__ float blk_max_b(float v){
  __shared__ float sh[8]; __shared__ float r;
  v=warp_max(v);
  int lane=threadIdx.x&31,w=threadIdx.x>>5,nw=(blockDim.x+31)>>5;
  __syncthreads();
  if(lane==0) sh[w]=v;
  __syncthreads();
  if(threadIdx.x==0){float m=-FLT_MAX; for(int i=0;i<nw;i++)m=fmaxf(m,sh[i]); r=m;}
  __syncthreads();
  return r;
}
__device__ __forceinline__ float blk_sum_b(float v){
  __shared__ float sh[8]; __shared__ float r;
  v=warp_sum(v);
  int lane=threadIdx.x&31,w=threadIdx.x>>5,nw=(blockDim.x+31)>>5;
  __syncthreads();
  if(lane==0) sh[w]=v;
  __syncthreads();
  if(threadIdx.x==0){float m=0.f; for(int i=0;i<nw;i++)m+=sh[i]; r=m;}
  __syncthreads();
  return r;
}
__device__ __forceinline__ float fq_range_d(float x,float mn,float mx){
  float scale=fmaxf((mx-mn)/65535.0f,FQEPS);
  float zp=rintf(-mn/scale);
  float q=fminf(fmaxf(rintf(x/scale)+zp,0.0f),65535.0f);
  return (q-zp)*scale;
}
__device__ __forceinline__ void get_params(int t,int s,float&a0,float&a1,float&a2){
  float mn=g_red[2*s],mx=g_red[2*s+1];
  a0=fminf(mn,0.f); a1=fmaxf(mx,0.f); a2=1;
  if(t==2){
    float lo=fq_range_d(mn,a0,a1),hi=fq_range_d(mx,a0,a1);
    a2=fmaxf(fmaxf(fabsf(lo),fabsf(hi))/127.0f,1e-12f);
  }
}
__device__ __forceinline__ void split_bf(float v,__nv_bfloat16& h,__nv_bfloat16& l){
  h=__float2bfloat16_rn(v);
  l=__float2bfloat16_rn(v-__bfloat162float(h));
}
__device__ __forceinline__ unsigned sptr(const void* p){
  return (unsigned)__cvta_generic_to_shared(p);
}
__device__ __forceinline__ void ldsm4(unsigned* r, unsigned addr){
  asm volatile("ldmatrix.sync.aligned.m8n8.x4.shared.b16 {%0,%1,%2,%3},[%4];"
    : "=r"(r[0]),"=r"(r[1]),"=r"(r[2]),"=r"(r[3]) : "r"(addr));
}
__device__ __forceinline__ void ldsm4t(unsigned* r, unsigned addr){
  asm volatile("ldmatrix.sync.aligned.m8n8.x4.trans.shared.b16 {%0,%1,%2,%3},[%4];"
    : "=r"(r[0]),"=r"(r[1]),"=r"(r[2]),"=r"(r[3]) : "r"(addr));
}
#define MMA16816(d,a,b0,b1) \
  asm volatile("mma.sync.aligned.m16n8k16.row.col.f32.bf16.bf16.f32 " \
    "{%0,%1,%2,%3},{%4,%5,%6,%7},{%8,%9},{%0,%1,%2,%3};" \
    : "+f"(d[0]),"+f"(d[1]),"+f"(d[2]),"+f"(d[3]) \
    : "r"(a[0]),"r"(a[1]),"r"(a[2]),"r"(a[3]),"r"(b0),"r"(b1))

__global__ void k_init(){
  int i=threadIdx.x;
  if(i<NSLOT){g_red[2*i]=FLT_MAX; g_red[2*i+1]=-FLT_MAX;}
}
__global__ void k_wsplit(const float* __restrict__ W,__nv_bfloat16* __restrict__ wh,
                         __nv_bfloat16* __restrict__ wl){
  int g=blockIdx.x*blockDim.x+threadIdx.x;
  float w=W[g];
  float a=fabsf(w);
  #pragma unroll
  for(int o=16;o;o>>=1) a=fmaxf(a,__shfl_xor_sync(0xffffffffu,a,o));
  float s=fmaxf(a/7.0f,1e-12f);
  float v=fminf(fmaxf(rintf(w/s),-8.0f),7.0f)*s;
  split_bf(v,wh[g],wl[g]);
}
__global__ void k_minmax(const float* __restrict__ x,int n,int slot){
  int i=blockIdx.x*blockDim.x+threadIdx.x, st=gridDim.x*blockDim.x;
  float lmn=FLT_MAX,lmx=-FLT_MAX;
  for(;i<n;i+=st){float v=x[i]; lmn=fminf(lmn,v); lmx=fmaxf(lmx,v);}
  red_minmax_atomic(lmn,lmx,slot);
}
__global__ void k_fqsplit(const float* __restrict__ in,__nv_bfloat16* __restrict__ hi,
                          __nv_bfloat16* __restrict__ lo,int n,int slot){
  float a0,a1,a2; get_params(1,slot,a0,a1,a2);
  int i=blockIdx.x*blockDim.x+threadIdx.x, st=gridDim.x*blockDim.x;
  for(;i<n;i+=st){
    float v=fq_range_d(in[i],a0,a1);
    split_bf(v,hi[i],lo[i]);
  }
}
__global__ void k_fq8q(const float* __restrict__ in,__nv_bfloat16* __restrict__ q8,
                       int n,int slot){
  float a0,a1,a2; get_params(2,slot,a0,a1,a2);
  int i=blockIdx.x*blockDim.x+threadIdx.x, st=gridDim.x*blockDim.x;
  for(;i<n;i+=st){
    float v=fq_range_d(in[i],a0,a1);
    float q=fminf(fmaxf(rintf(v/a2),-128.f),127.f);
    q8[i]=__float2bfloat16_rn(q);
  }
}
__global__ void k_psplit(const float* __restrict__ in,__nv_bfloat16* __restrict__ hi,
                         __nv_bfloat16* __restrict__ lo,float* __restrict__ attn,int wAttn){
  float a0,a1,a2; get_params(1,S_P,a0,a1,a2);
  size_t i=(size_t)blockIdx.x*blockDim.x+threadIdx.x;
  size_t st=(size_t)gridDim.x*blockDim.x;
  for(;i<N_SC;i+=st){
    float v=fq_range_d(in[i],a0,a1);
    split_bf(v,hi[i],lo[i]);
    if(wAttn) attn[i]=v;
  }
}
__global__ void k_rms(float* __restrict__ x,const float* __restrict__ w,
                      int sIn,int sOut,int sOut2){
  int row=blockIdx.x,d=threadIdx.x;
  float mn=fminf(g_red[2*sIn],0.f),mx=fmaxf(g_red[2*sIn+1],0.f);
  size_t idx=(size_t)row*Dn+d;
  float v=fq_range_d(x[idx],mn,mx);
  float s=warp_sum(v*v);
  __shared__ float sh[4];
  if((d&31)==0) sh[d>>5]=s;
  __syncthreads();
  float var=(sh[0]+sh[1]+sh[2]+sh[3])*(1.0f/128.0f);
  float y=v*(1.0f/sqrtf(var+1e-6f))*w[d];
  x[idx]=y;
  red_minmax_atomic(y,y,sOut);
  float m2n=(d>=64)?y:FLT_MAX, m2x=(d>=64)?y:-FLT_MAX;
  red_minmax_atomic(m2n,m2x,sOut2);
}
__global__ void k_rope1(const float* __restrict__ y,const float* __restrict__ cosb,
                        const float* __restrict__ sinb,float* __restrict__ p1,
                        float* __restrict__ p2,int H,int n,
                        int sRMS,int sRMS2,int sP1,int sP2){
  float mnY=g_red[2*sRMS],mxY=g_red[2*sRMS+1];
  float c10=fminf(mnY,0.f),c11=fmaxf(mxY,0.f);
  float amn=fq_range_d(mnY,c10,c11),amx=fq_range_d(mxY,c10,c11);
  float c20=fminf(amn,0.f),c21=fmaxf(amx,0.f);
  float y2n=g_red[2*sRMS2],y2x=g_red[2*sRMS2+1];
  float x2n=fq_range_d(fq_range_d(y2n,c10,c11),c20,c21);
  float x2x=fq_range_d(fq_range_d(y2x,c10,c11),c20,c21);
  float nTn=-x2x,nTx=-x2n;
  float n0=fminf(nTn,0.f),n1=fmaxf(nTx,0.f);
  float negLo=fq_range_d(nTn,n0,n1),negHi=fq_range_d(nTx,n0,n1);
  float qbMn=fq_range_d(amn,c20,c21),qbMx=fq_range_d(amx,c20,c21);
  float cc0=fminf(fminf(qbMn,negLo),0.f),cc1=fmaxf(fmaxf(qbMx,negHi),0.f);
  int i0=blockIdx.x*blockDim.x+threadIdx.x, st=gridDim.x*blockDim.x;
  float l1n=FLT_MAX,l1x=-FLT_MAX,l2n=FLT_MAX,l2x=-FLT_MAX;
  for(int i=i0;i<n;i+=st){
    int d=i%Dn; int r=i/Dn; int s=(r/H)%Sn; int b=r/(H*Sn);
    float qb=fq_range_d(fq_range_d(y[i],c10,c11),c20,c21);
    float rot;
    if(d<64){
      float qbp=fq_range_d(fq_range_d(y[i+64],c10,c11),c20,c21);
      rot=fq_range_d(fq_range_d(-qbp,n0,n1),cc0,cc1);
    } else {
      float qbp=fq_range_d(fq_range_d(y[i-64],c10,c11),c20,c21);
      rot=fq_range_d(qbp,cc0,cc1);
    }
    int ci=(b*Sn+s)*Dn+d;
    float v1=qb*cosb[ci], v2=rot*sinb[ci];
    p1[i]=v1; p2[i]=v2;
    l1n=fminf(l1n,v1); l1x=fmaxf(l1x,v1);
    l2n=fminf(l2n,v2); l2x=fmaxf(l2x,v2);
  }
  red_minmax_atomic(l1n,l1x,sP1);
  red_minmax_atomic(l2n,l2x,sP2);
}
__global__ void k_rope2(const float* __restrict__ p1,const float* __restrict__ p2,
                        float* __restrict__ out,int H,int n,int sP1,int sP2,int sSum){
  float a0=fminf(g_red[2*sP1],0.f),a1=fmaxf(g_red[2*sP1+1],0.f);
  float b0=fminf(g_red[2*sP2],0.f),b1=fmaxf(g_red[2*sP2+1],0.f);
  int i0=blockIdx.x*blockDim.x+threadIdx.x, st=gridDim.x*blockDim.x;
  float lmn=FLT_MAX,lmx=-FLT_MAX;
  for(int i=i0;i<n;i+=st){
    float v=fq_range_d(p1[i],a0,a1)+fq_range_d(p2[i],b0,b1);
    int d=i%Dn; int r=i/Dn; int h=r%H; int s=(r/H)%Sn; int b=r/(H*Sn);
    out[((size_t)(b*H+h)*Sn+s)*Dn+d]=v;
    lmn=fminf(lmn,v); lmx=fmaxf(lmx,v);
  }
  red_minmax_atomic(lmn,lmx,sSum);
}

// ---------- bf16 mma.sync NT GEMM: C = (Ah+Al) @ (Bh[+Bl])^T * scale ----------
template<bool UBL>
__global__ __launch_bounds__(256) void mma_nt(
  const __nv_bfloat16* __restrict__ Ah,const __nv_bfloat16* __restrict__ Al,
  const __nv_bfloat16* __restrict__ Bh,const __nv_bfloat16* __restrict__ Bl,
  float* __restrict__ C,int K,int lda,int ldb,int ldc,
  int sOut,int scaleSlot,int batch)
{
  int z=blockIdx.z;
  if(batch==1){
    int b=z>>4,h=z&15;
    size_t ao=(size_t)z*Sn*Dn, bo=(size_t)(b*NKVn+(h>>1))*Sn*Dn, co=(size_t)z*Sn*Sn;
    Ah+=ao; Al+=ao; Bh+=bo; Bl+=bo; C+=co;
  }
  __shared__ __nv_bfloat16 As[2][128*40];
  __shared__ __nv_bfloat16 Bs[2][64*40];
  int tid=threadIdx.x, lane=tid&31, w=tid>>5;
  int wm=(w&3)*32, wn=(w>>2)*32;
  int g=lane>>2, t4=lane&3;
  int m0=blockIdx.y*128, n0=blockIdx.x*64;
  float acc[2][4][4];
  #pragma unroll
  for(int i=0;i<2;i++)
    #pragma unroll
    for(int j=0;j<4;j++)
      #pragma unroll
      for(int r=0;r<4;r++) acc[i][j][r]=0.f;
  int ar=tid>>1, ac=(tid&1)*16;
  int br=tid>>2, bc=(tid&3)*8;
  int mat=lane>>3, mrow=lane&7;
  for(int k0=0;k0<K;k0+=32){
    const uint4* pa0=(const uint4*)(Ah+(size_t)(m0+ar)*lda+k0+ac);
    const uint4* pa1=(const uint4*)(Al+(size_t)(m0+ar)*lda+k0+ac);
    *(uint4*)&As[0][ar*40+ac]=pa0[0];
    *(uint4*)&As[0][ar*40+ac+8]=pa0[1];
    *(uint4*)&As[1][ar*40+ac]=pa1[0];
    *(uint4*)&As[1][ar*40+ac+8]=pa1[1];
    *(uint4*)&Bs[0][br*40+bc]=*(const uint4*)(Bh+(size_t)(n0+br)*ldb+k0+bc);
    if(UBL) *(uint4*)&Bs[1][br*40+bc]=*(const uint4*)(Bl+(size_t)(n0+br)*ldb+k0+bc);
    __syncthreads();
    #pragma unroll
    for(int kk=0;kk<32;kk+=16){
      unsigned af[2][2][4];
      #pragma unroll
      for(int mt=0;mt<2;mt++)
        #pragma unroll
        for(int p=0;p<2;p++)
          ldsm4(af[mt][p],sptr(&As[p][(wm+mt*16+(mat&1)*8+mrow)*40 + kk + (mat>>1)*8]));
      unsigned bf[2][4][2];
      #pragma unroll
      for(int p=0;p<(UBL?2:1);p++)
        #pragma unroll
        for(int hf=0;hf<2;hf++){
          unsigned r[4];
          ldsm4(r,sptr(&Bs[p][(wn+hf*16+(mat&1)*8+mrow)*40 + kk + (mat>>1)*8]));
          bf[p][hf*2+0][0]=r[0]; bf[p][hf*2+1][0]=r[1];
          bf[p][hf*2+0][1]=r[2]; bf[p][hf*2+1][1]=r[3];
        }
      #pragma unroll
      for(int mt=0;mt<2;mt++)
        #pragma unroll
        for(int nt=0;nt<4;nt++){
          MMA16816(acc[mt][nt],af[mt][0],bf[0][nt][0],bf[0][nt][1]);
          if(UBL) MMA16816(acc[mt][nt],af[mt][0],bf[1][nt][0],bf[1][nt][1]);
          MMA16816(acc[mt][nt],af[mt][1],bf[0][nt][0],bf[0][nt][1]);
        }
    }
    __syncthreads();
  }
  float scl=1.f;
  if(scaleSlot>=0){float a0,a1,a2; get_params(2,scaleSlot,a0,a1,a2); scl=a2;}
  float lmn=FLT_MAX,lmx=-FLT_MAX;
  #pragma unroll
  for(int mt=0;mt<2;mt++)
    #pragma unroll
    for(int nt=0;nt<4;nt++){
      int r0=m0+wm+mt*16+g, c=n0+wn+nt*8+t4*2;
      float v0=acc[mt][nt][0]*scl, v1=acc[mt][nt][1]*scl;
      float v2=acc[mt][nt][2]*scl, v3=acc[mt][nt][3]*scl;
      C[(size_t)r0*ldc+c]=v0; C[(size_t)r0*ldc+c+1]=v1;
      C[(size_t)(r0+8)*ldc+c]=v2; C[(size_t)(r0+8)*ldc+c+1]=v3;
      lmn=fminf(fminf(lmn,fminf(v0,v1)),fminf(v2,v3));
      lmx=fmaxf(fmaxf(lmx,fmaxf(v0,v1)),fmaxf(v2,v3));
    }
  if(sOut>=0) red_minmax_atomic(lmn,lmx,sOut);
}

// ---------- AV (NN): C = (Ph+Pl) @ Vq * vs ----------
__global__ __launch_bounds__(256) void mma_av(
  const __nv_bfloat16* __restrict__ Ph,const __nv_bfloat16* __restrict__ Pl,
  const __nv_bfloat16* __restrict__ Vq,float* __restrict__ C)
{
  int z=blockIdx.z,b=z>>4,h=z&15,h2=h>>1;
  Ph+=(size_t)z*Sn*Sn; Pl+=(size_t)z*Sn*Sn;
  Vq+=(size_t)b*Sn*KNn + h2*Dn;
  C +=(size_t)b*Sn*QNn + h*Dn;
  __shared__ __nv_bfloat16 As[2][128*40];
  __shared__ __nv_bfloat16 Vs[32*72];
  int tid=threadIdx.x, lane=tid&31, w=tid>>5;
  int wm=(w&3)*32, wn=(w>>2)*32;
  int g=lane>>2, t4=lane&3;
  int m0=blockIdx.y*128, n0=blockIdx.x*64;
  float acc[2][4][4];
  #pragma unroll
  for(int i=0;i<2;i++)
    #pragma unroll
    for(int j=0;j<4;j++)
      #pragma unroll
      for(int r=0;r<4;r++) acc[i][j][r]=0.f;
  int ar=tid>>1, ac=(tid&1)*16;
  int vr=tid>>3, vc=(tid&7)*8;
  int mat=lane>>3, mrow=lane&7;
  for(int k0=0;k0<Sn;k0+=32){
    const uint4* pa0=(const uint4*)(Ph+(size_t)(m0+ar)*Sn+k0+ac);
    const uint4* pa1=(const uint4*)(Pl+(size_t)(m0+ar)*Sn+k0+ac);
    *(uint4*)&As[0][ar*40+ac]=pa0[0];
    *(uint4*)&As[0][ar*40+ac+8]=pa0[1];
    *(uint4*)&As[1][ar*40+ac]=pa1[0];
    *(uint4*)&As[1][ar*40+ac+8]=pa1[1];
    *(uint4*)&Vs[vr*72+vc]=*(const uint4*)(Vq+(size_t)(k0+vr)*KNn + n0 + vc);
    __syncthreads();
    #pragma unroll
    for(int kk=0;kk<32;kk+=16){
      unsigned af[2][2][4];
      #pragma unroll
      for(int mt=0;mt<2;mt++)
        #pragma unroll
        for(int p=0;p<2;p++)
          ldsm4(af[mt][p],sptr(&As[p][(wm+mt*16+(mat&1)*8+mrow)*40 + kk + (mat>>1)*8]));
      unsigned bf[4][2];
      #pragma unroll
      for(int hf=0;hf<2;hf++){
        unsigned r[4];
        ldsm4t(r,sptr(&Vs[(kk+(mat>>1)*8+mrow)*72 + wn + hf*16 + (mat&1)*8]));
        bf[hf*2+0][0]=r[0]; bf[hf*2+1][0]=r[1];
        bf[hf*2+0][1]=r[2]; bf[hf*2+1][1]=r[3];
      }
      #pragma unroll
      for(int mt=0;mt<2;mt++)
        #pragma unroll
        for(int nt=0;nt<4;nt++){
          MMA16816(acc[mt][nt],af[mt][0],bf[nt][0],bf[nt][1]);
          MMA16816(acc[mt][nt],af[mt][1],bf[nt][0],bf[nt][1]);
        }
    }
    __syncthreads();
  }
  float a0,a1,scl; get_params(2,S_V,a0,a1,scl);
  float lmn=FLT_MAX,lmx=-FLT_MAX;
  #pragma unroll
  for(int mt=0;mt<2;mt++)
    #pragma unroll
    for(int nt=0;nt<4;nt++){
      int r0=m0+wm+mt*16+g, c=n0+wn+nt*8+t4*2;
      float v0=acc[mt][nt][0]*scl, v1=acc[mt][nt][1]*scl;
      float v2=acc[mt][nt][2]*scl, v3=acc[mt][nt][3]*scl;
      C[(size_t)r0*QNn+c]=v0; C[(size_t)r0*QNn+c+1]=v1;
      C[(size_t)(r0+8)*QNn+c]=v2; C[(size_t)(r0+8)*QNn+c+1]=v3;
      lmn=fminf(fminf(lmn,fminf(v0,v1)),fminf(v2,v3));
      lmx=fmaxf(fmaxf(lmx,fmaxf(v0,v1)),fmaxf(v2,v3));
    }
  red_minmax_atomic(lmn,lmx,S_CTX);
}

__global__ void k_p1(float* __restrict__ sc,float* __restrict__ amin){
  int row=blockIdx.x; int s=row%Sn;
  float mnS=g_red[2*S_SC],mxS=g_red[2*S_SC+1];
  float q0=fminf(mnS,0.f),q1=fmaxf(mxS,0.f);
  float scal=(float)(0.08838834764831843);
  float scq=fq_range_d(scal,fminf(scal,0.f),fmaxf(scal,0.f));
  float lo=fq_range_d(mnS,q0,q1)*scq,hi=fq_range_d(mxS,q0,q1)*scq;
  float r0=fminf(lo,0.f),r1=fmaxf(hi,0.f);
  size_t base=(size_t)row*Sn;
  float rmn=FLT_MAX,umn=FLT_MAX,umx=-FLT_MAX;
  for(int t=threadIdx.x;t<Sn;t+=blockDim.x){
    float a=fq_range_d(fq_range_d(sc[base+t],q0,q1)*scq,r0,r1);
    sc[base+t]=a;
    rmn=fminf(rmn,a);
    if(t<=s){umn=fminf(umn,a); umx=fmaxf(umx,a);}
  }
  float am=blk_min_b(rmn);
  if(threadIdx.x==0){
    amin[row]=am;
    atomicMinF(&g_red[2*S_AMIN],am); atomicMaxF(&g_red[2*S_AMIN+1],am);
    if(s<Sn-1){atomicMinF(&g_red[2*S_AMIN2],am); atomicMaxF(&g_red[2*S_AMIN2+1],am);}
  }
  red_minmax_atomic(umn,umx,S_UNM);
}
__global__ void k_p2(float* __restrict__ sc,const float* __restrict__ amin){
  __shared__ float rowbuf[Sn];
  int row=blockIdx.x; int s=row%Sn;
  float an=g_red[2*S_AMIN],ax=g_red[2*S_AMIN+1];
  float a0=fminf(an,0.f),a1=fmaxf(ax,0.f);
  float c20=fq_range_d(-20.0f,-20.0f,0.0f);
  float tn=fq_range_d(an,a0,a1)+c20,tx2=fq_range_d(ax,a0,a1)+c20;
  float v0=fminf(tn,0.f),v1=fmaxf(tx2,0.f);
  float a2n=g_red[2*S_AMIN2],a2x=g_red[2*S_AMIN2+1];
  float vlo=fq_range_d(fq_range_d(a2n,a0,a1)+c20,v0,v1);
  float vhi=fq_range_d(fq_range_d(a2x,a0,a1)+c20,v0,v1);
  float un=g_red[2*S_UNM],ux=g_red[2*S_UNM+1];
  float m0=fminf(fminf(un,vlo),0.f),m1=fmaxf(fmaxf(ux,vhi),0.f);
  float vv=fq_range_d(fq_range_d(amin[row],a0,a1)+c20,v0,v1);
  float vm=fq_range_d(vv,m0,m1);
  size_t base=(size_t)row*Sn;
  float lmx=-FLT_MAX;
  for(int t=threadIdx.x;t<Sn;t+=blockDim.x){
    float x=(t<=s)?fq_range_d(sc[base+t],m0,m1):vm;
    rowbuf[t]=x;
    lmx=fmaxf(lmx,x);
  }
  float m=blk_max_b(lmx);
  float ls=0.f;
  for(int t=threadIdx.x;t<Sn;t+=blockDim.x){
    float e=expf(rowbuf[t]-m);
    rowbuf[t]=e;
    ls+=e;
  }
  float sum=blk_sum_b(ls);
  float pn=FLT_MAX,px=-FLT_MAX;
  for(int t=threadIdx.x;t<Sn;t+=blockDim.x){
    float p=rowbuf[t]/sum;
    sc[base+t]=p;
    pn=fminf(pn,p); px=fmaxf(px,p);
  }
  red_minmax_atomic(pn,px,S_P);
}

extern "C" void kernel_launch(void* const* d_in,const int* in_sizes,int n_in,
                              void* d_out,int out_size){
  const float* hs  =(const float*)d_in[0];
  const float* cosb=(const float*)d_in[1];
  const float* sinb=(const float*)d_in[2];
  const float* Wq  =(const float*)d_in[4];
  const float* Wk  =(const float*)d_in[5];
  const float* Wv  =(const float*)d_in[6];
  const float* Wo  =(const float*)d_in[7];
  const float* qw  =(const float*)d_in[8];
  const float* kw  =(const float*)d_in[9];
  float* out=(float*)d_out;

  float *pLin,*pP1,*pP2,*pQr,*pKr,*pV,*pCtx,*pSc,*pAmin;
  __nv_bfloat16 *pHsh,*pHsl,*pWqh,*pWql,*pWkh,*pWkl,*pWvh,*pWvl,*pWoh,*pWol;
  __nv_bfloat16 *pQh,*pQl,*pKq,*pVq,*pPh,*pPl,*pCh,*pCl;
  cudaGetSymbolAddress((void**)&pLin,g_lin);
  cudaGetSymbolAddress((void**)&pP1,g_p1b);
  cudaGetSymbolAddress((void**)&pP2,g_p2b);
  cudaGetSymbolAddress((void**)&pQr,g_qr);
  cudaGetSymbolAddress((void**)&pKr,g_kr);
  cudaGetSymbolAddress((void**)&pV,g_v);
  cudaGetSymbolAddress((void**)&pCtx,g_ctx);
  cudaGetSymbolAddress((void**)&pSc,g_scores);
  cudaGetSymbolAddress((void**)&pAmin,g_amin);
  cudaGetSymbolAddress((void**)&pHsh,g_hsh); cudaGetSymbolAddress((void**)&pHsl,g_hsl);
  cudaGetSymbolAddress((void**)&pWqh,g_wqh); cudaGetSymbolAddress((void**)&pWql,g_wql);
  cudaGetSymbolAddress((void**)&pWkh,g_wkh); cudaGetSymbolAddress((void**)&pWkl,g_wkl);
  cudaGetSymbolAddress((void**)&pWvh,g_wvh); cudaGetSymbolAddress((void**)&pWvl,g_wvl);
  cudaGetSymbolAddress((void**)&pWoh,g_woh); cudaGetSymbolAddress((void**)&pWol,g_wol);
  cudaGetSymbolAddress((void**)&pQh,g_qh); cudaGetSymbolAddress((void**)&pQl,g_ql);
  cudaGetSymbolAddress((void**)&pKq,g_kq8); cudaGetSymbolAddress((void**)&pVq,g_vq8);
  cudaGetSymbolAddress((void**)&pPh,g_ph); cudaGetSymbolAddress((void**)&pPl,g_pl);
  cudaGetSymbolAddress((void**)&pCh,g_ch); cudaGetSymbolAddress((void**)&pCl,g_cl);

  k_init<<<1,64>>>();
  k_wsplit<<<QNn*HIDn/256,256>>>(Wq,pWqh,pWql);
  k_wsplit<<<KNn*HIDn/256,256>>>(Wk,pWkh,pWkl);
  k_wsplit<<<KNn*HIDn/256,256>>>(Wv,pWvh,pWvl);
  k_wsplit<<<HIDn*QNn/256,256>>>(Wo,pWoh,pWol);
  k_minmax<<<1024,256>>>(hs,N_HS,S_HS);
  k_fqsplit<<<2048,256>>>(hs,pHsh,pHsl,N_HS,S_HS);
  // Q path
  mma_nt<true><<<dim3(QNn/64,Mn/128,1),256>>>(pHsh,pHsl,pWqh,pWql,pLin,HIDn,HIDn,HIDn,QNn,S_QLIN,-1,0);
  k_rms<<<Mn*NHn,128>>>(pLin,qw,S_QLIN,S_QRMS,S_QRMS2);
  k_rope1<<<2048,256>>>(pLin,cosb,sinb,pP1,pP2,NHn,N_Q,S_QRMS,S_QRMS2,S_QP1,S_QP2);
  k_rope2<<<2048,256>>>(pP1,pP2,pQr,NHn,N_Q,S_QP1,S_QP2,S_QSUM);
  k_fqsplit<<<2048,256>>>(pQr,pQh,pQl,N_Q,S_QSUM);
  // K path
  mma_nt<true><<<dim3(KNn/64,Mn/128,1),256>>>(pHsh,pHsl,pWkh,pWkl,pLin,HIDn,HIDn,HIDn,KNn,S_KLIN,-1,0);
  k_rms<<<Mn*NKVn,128>>>(pLin,kw,S_KLIN,S_KRMS,S_KRMS2);
  k_rope1<<<1024,256>>>(pLin,cosb,sinb,pP1,pP2,NKVn,N_K,S_KRMS,S_KRMS2,S_KP1,S_KP2);
  k_rope2<<<1024,256>>>(pP1,pP2,pKr,NKVn,N_K,S_KP1,S_KP2,S_KSUM);
  k_fq8q<<<1024,256>>>(pKr,pKq,N_K,S_KSUM);
  // V path
  mma_nt<true><<<dim3(KNn/64,Mn/128,1),256>>>(pHsh,pHsl,pWvh,pWvl,pV,HIDn,HIDn,HIDn,KNn,S_V,-1,0);
  k_fq8q<<<1024,256>>>(pV,pVq,N_K,S_V);
  // scores: q(2 parts) x kq(int8-exact) * ks
  mma_nt<false><<<dim3(Sn/64,Sn/128,Bn*NHn),256>>>(pQh,pQl,pKq,pKq,pSc,Dn,Dn,Dn,Sn,S_SC,S_KSUM,1);
  k_p1<<<NROWS,256>>>(pSc,pAmin);
  k_p2<<<NROWS,256>>>(pSc,pAmin);
  int wAttn=(out_size>=(int)(OUT_MAIN+N_SC))?1:0;
  k_psplit<<<8192,256>>>(pSc,pPh,pPl,out+OUT_MAIN,wAttn);
  // AV + output proj
  mma_av<<<dim3(Dn/64,Sn/128,Bn*NHn),256>>>(pPh,pPl,pVq,pCtx);
  k_fqsplit<<<2048,256>>>(pCtx,pCh,pCl,N_Q,S_CTX);
  mma_nt<true><<<dim3(HIDn/64,Mn/128,1),256>>>(pCh,pCl,pWoh,pWol,out,QNn,QNn,QNn,HIDn,-1,-1,0);
}

// round 5
// speedup vs baseline: 2.5421x; 1.1637x over previous
#include <cuda_runtime.h>
#include <cuda_bf16.h>
#include <math.h>
#include <float.h>

#define Bn 2
#define Sn 1024
#define HIDn 2048
#define NHn 16
#define NKVn 8
#define Dn 128
#define Mn (Bn*Sn)
#define QNn (NHn*Dn)
#define KNn (NKVn*Dn)
#define FQEPS 1.5259021896696422e-09f
#define N_HS (Mn*HIDn)
#define N_Q  (Mn*QNn)
#define N_K  (Mn*KNn)
#define N_SC ((size_t)Bn*NHn*Sn*Sn)
#define NROWS (Bn*NHn*Sn)
#define OUT_MAIN (Mn*HIDn)

enum {S_HS=0,S_QLIN,S_QRMS,S_QRMS2,S_KLIN,S_KRMS,S_KRMS2,S_QP1,S_QP2,S_QSUM,
      S_KP1,S_KP2,S_KSUM,S_V,S_SC,S_AMIN,S_AMIN2,S_UNM,S_P,S_CTX,NSLOT};

__device__ float g_red[2*NSLOT];
__device__ float g_lin[N_Q];
__device__ float g_p1b[N_Q];
__device__ float g_p2b[N_Q];
__device__ float g_qr[N_Q];
__device__ float g_kr[N_K];
__device__ float g_v[N_K];
__device__ float g_ctx[N_Q];
__device__ float g_scores[N_SC];
__device__ float g_amin[NROWS];
__device__ __nv_bfloat16 g_hsh[N_HS], g_hsl[N_HS];
__device__ __nv_bfloat16 g_wqh[QNn*HIDn], g_wql[QNn*HIDn];
__device__ __nv_bfloat16 g_wkh[KNn*HIDn], g_wkl[KNn*HIDn];
__device__ __nv_bfloat16 g_wvh[KNn*HIDn], g_wvl[KNn*HIDn];
__device__ __nv_bfloat16 g_woh[HIDn*QNn], g_wol[HIDn*QNn];
__device__ __nv_bfloat16 g_qh[N_Q], g_ql[N_Q];
__device__ __nv_bfloat16 g_kq8[N_K];
__device__ __nv_bfloat16 g_vq8[N_K];
__device__ __nv_bfloat16 g_ph[N_SC], g_pl[N_SC];
__device__ __nv_bfloat16 g_ch[N_Q], g_cl[N_Q];

__device__ __forceinline__ void atomicMinF(float* a,float v){
  int* ai=(int*)a; int cur=*ai;
  while(v<__int_as_float(cur)){int old=atomicCAS(ai,cur,__float_as_int(v)); if(old==cur)break; cur=old;}
}
__device__ __forceinline__ void atomicMaxF(float* a,float v){
  int* ai=(int*)a; int cur=*ai;
  while(v>__int_as_float(cur)){int old=atomicCAS(ai,cur,__float_as_int(v)); if(old==cur)break; cur=old;}
}
__device__ __forceinline__ float warp_min(float v){
  #pragma unroll
  for(int o=16;o;o>>=1) v=fminf(v,__shfl_xor_sync(0xffffffffu,v,o));
  return v;
}
__device__ __forceinline__ float warp_max(float v){
  #pragma unroll
  for(int o=16;o;o>>=1) v=fmaxf(v,__shfl_xor_sync(0xffffffffu,v,o));
  return v;
}
__device__ __forceinline__ float warp_sum(float v){
  #pragma unroll
  for(int o=16;o;o>>=1) v+=__shfl_xor_sync(0xffffffffu,v,o);
  return v;
}
__device__ __forceinline__ void red_minmax_atomic(float lmn,float lmx,int slot){
  __shared__ float smn[8],smx[8];
  lmn=warp_min(lmn); lmx=warp_max(lmx);
  int lane=threadIdx.x&31,w=threadIdx.x>>5,nw=(blockDim.x+31)>>5;
  __syncthreads();
  if(lane==0){smn[w]=lmn;smx[w]=lmx;}
  __syncthreads();
  if(w==0){
    lmn=(lane<nw)?smn[lane]:FLT_MAX;
    lmx=(lane<nw)?smx[lane]:-FLT_MAX;
    lmn=warp_min(lmn); lmx=warp_max(lmx);
    if(lane==0){atomicMinF(&g_red[2*slot],lmn); atomicMaxF(&g_red[2*slot+1],lmx);}
  }
}
__device__ __forceinline__ float blk_max_b(float v){
  __shared__ float sh[8]; __shared__ float r;
  v=warp_max(v);
  int lane=threadIdx.x&31,w=threadIdx.x>>5,nw=(blockDim.x+31)>>5;
  __syncthreads();
  if(lane==0) sh[w]=v;
  __syncthreads();
  if(threadIdx.x==0){float m=-FLT_MAX; for(int i=0;i<nw;i++)m=fmaxf(m,sh[i]); r=m;}
  __syncthreads();
  return r;
}
__device__ __forceinline__ float blk_min_b(float v){
  __shared__ float sh[8]; __shared__ float r;
  v=warp_min(v);
  int lane=threadIdx.x&31,w=threadIdx.x>>5,nw=(blockDim.x+31)>>5;
  __syncthreads();
  if(lane==0) sh[w]=v;
  __syncthreads();
  if(threadIdx.x==0){float m=FLT_MAX; for(int i=0;i<nw;i++)m=fminf(m,sh[i]); r=m;}
  __syncthreads();
  return r;
}
__device__ __forceinline__ float blk_sum_b(float v){
  __shared__ float sh[8]; __shared__ float r;
  v=warp_sum(v);
  int lane=threadIdx.x&31,w=threadIdx.x>>5,nw=(blockDim.x+31)>>5;
  __syncthreads();
  if(lane==0) sh[w]=v;
  __syncthreads();
  if(threadIdx.x==0){float m=0.f; for(int i=0;i<nw;i++)m+=sh[i]; r=m;}
  __syncthreads();
  return r;
}
__device__ __forceinline__ float fq_range_d(float x,float mn,float mx){
  float scale=fmaxf((mx-mn)/65535.0f,FQEPS);
  float zp=rintf(-mn/scale);
  float q=fminf(fmaxf(rintf(x/scale)+zp,0.0f),65535.0f);
  return (q-zp)*scale;
}
__device__ __forceinline__ void get_params(int t,int s,float&a0,float&a1,float&a2){
  float mn=g_red[2*s],mx=g_red[2*s+1];
  a0=fminf(mn,0.f); a1=fmaxf(mx,0.f); a2=1;
  if(t==2){
    float lo=fq_range_d(mn,a0,a1),hi=fq_range_d(mx,a0,a1);
    a2=fmaxf(fmaxf(fabsf(lo),fabsf(hi))/127.0f,1e-12f);
  }
}
__device__ __forceinline__ void split_bf(float v,__nv_bfloat16& h,__nv_bfloat16& l){
  h=__float2bfloat16_rn(v);
  l=__float2bfloat16_rn(v-__bfloat162float(h));
}
__device__ __forceinline__ unsigned sptr(const void* p){
  return (unsigned)__cvta_generic_to_shared(p);
}
__device__ __forceinline__ void ldsm4(unsigned* r, unsigned addr){
  asm volatile("ldmatrix.sync.aligned.m8n8.x4.shared.b16 {%0,%1,%2,%3},[%4];"
    : "=r"(r[0]),"=r"(r[1]),"=r"(r[2]),"=r"(r[3]) : "r"(addr));
}
__device__ __forceinline__ void ldsm4t(unsigned* r, unsigned addr){
  asm volatile("ldmatrix.sync.aligned.m8n8.x4.trans.shared.b16 {%0,%1,%2,%3},[%4];"
    : "=r"(r[0]),"=r"(r[1]),"=r"(r[2]),"=r"(r[3]) : "r"(addr));
}
__device__ __forceinline__ void cpa16(void* s,const void* g){
  asm volatile("cp.async.cg.shared.global [%0],[%1],16;"::"r"(sptr(s)),"l"(g));
}
#define CPCOMMIT() asm volatile("cp.async.commit_group;")
#define CPWAIT1()  asm volatile("cp.async.wait_group 1;")
#define MMA16816(d,a,b0,b1) \
  asm volatile("mma.sync.aligned.m16n8k16.row.col.f32.bf16.bf16.f32 " \
    "{%0,%1,%2,%3},{%4,%5,%6,%7},{%8,%9},{%0,%1,%2,%3};" \
    : "+f"(d[0]),"+f"(d[1]),"+f"(d[2]),"+f"(d[3]) \
    : "r"(a[0]),"r"(a[1]),"r"(a[2]),"r"(a[3]),"r"(b0),"r"(b1))

__global__ void k_init(){
  int i=threadIdx.x;
  if(i<NSLOT){g_red[2*i]=FLT_MAX; g_red[2*i+1]=-FLT_MAX;}
}
__global__ void k_wsplit(const float* __restrict__ W,__nv_bfloat16* __restrict__ wh,
                         __nv_bfloat16* __restrict__ wl){
  int g=blockIdx.x*blockDim.x+threadIdx.x;
  float w=W[g];
  float a=fabsf(w);
  #pragma unroll
  for(int o=16;o;o>>=1) a=fmaxf(a,__shfl_xor_sync(0xffffffffu,a,o));
  float s=fmaxf(a/7.0f,1e-12f);
  float v=fminf(fmaxf(rintf(w/s),-8.0f),7.0f)*s;
  split_bf(v,wh[g],wl[g]);
}
__global__ void k_minmax(const float* __restrict__ x,int n,int slot){
  int i=blockIdx.x*blockDim.x+threadIdx.x, st=gridDim.x*blockDim.x;
  float lmn=FLT_MAX,lmx=-FLT_MAX;
  for(;i<n;i+=st){float v=x[i]; lmn=fminf(lmn,v); lmx=fmaxf(lmx,v);}
  red_minmax_atomic(lmn,lmx,slot);
}
__global__ void k_fqsplit(const float* __restrict__ in,__nv_bfloat16* __restrict__ hi,
                          __nv_bfloat16* __restrict__ lo,int n,int slot){
  float a0,a1,a2; get_params(1,slot,a0,a1,a2);
  int i=blockIdx.x*blockDim.x+threadIdx.x, st=gridDim.x*blockDim.x;
  for(;i<n;i+=st){
    float v=fq_range_d(in[i],a0,a1);
    split_bf(v,hi[i],lo[i]);
  }
}
__global__ void k_fq8q(const float* __restrict__ in,__nv_bfloat16* __restrict__ q8,
                       int n,int slot){
  float a0,a1,a2; get_params(2,slot,a0,a1,a2);
  int i=blockIdx.x*blockDim.x+threadIdx.x, st=gridDim.x*blockDim.x;
  for(;i<n;i+=st){
    float v=fq_range_d(in[i],a0,a1);
    float q=fminf(fmaxf(rintf(v/a2),-128.f),127.f);
    q8[i]=__float2bfloat16_rn(q);
  }
}
__global__ void k_psplit(const float* __restrict__ in,__nv_bfloat16* __restrict__ hi,
                         __nv_bfloat16* __restrict__ lo,float* __restrict__ attn,int wAttn){
  float a0,a1,a2; get_params(1,S_P,a0,a1,a2);
  size_t i=((size_t)blockIdx.x*blockDim.x+threadIdx.x)*4;
  size_t st=(size_t)gridDim.x*blockDim.x*4;
  for(;i<N_SC;i+=st){
    float4 x=*(const float4*)&in[i];
    float v0=fq_range_d(x.x,a0,a1),v1=fq_range_d(x.y,a0,a1);
    float v2=fq_range_d(x.z,a0,a1),v3=fq_range_d(x.w,a0,a1);
    split_bf(v0,hi[i],lo[i]); split_bf(v1,hi[i+1],lo[i+1]);
    split_bf(v2,hi[i+2],lo[i+2]); split_bf(v3,hi[i+3],lo[i+3]);
    if(wAttn) *(float4*)&attn[i]=make_float4(v0,v1,v2,v3);
  }
}
__global__ void k_rms(float* __restrict__ x,const float* __restrict__ w,
                      int sIn,int sOut,int sOut2){
  int row=blockIdx.x,d=threadIdx.x;
  float mn=fminf(g_red[2*sIn],0.f),mx=fmaxf(g_red[2*sIn+1],0.f);
  size_t idx=(size_t)row*Dn+d;
  float v=fq_range_d(x[idx],mn,mx);
  float s=warp_sum(v*v);
  __shared__ float sh[4];
  if((d&31)==0) sh[d>>5]=s;
  __syncthreads();
  float var=(sh[0]+sh[1]+sh[2]+sh[3])*(1.0f/128.0f);
  float y=v*(1.0f/sqrtf(var+1e-6f))*w[d];
  x[idx]=y;
  red_minmax_atomic(y,y,sOut);
  float m2n=(d>=64)?y:FLT_MAX, m2x=(d>=64)?y:-FLT_MAX;
  red_minmax_atomic(m2n,m2x,sOut2);
}
__global__ void k_rope1(const float* __restrict__ y,const float* __restrict__ cosb,
                        const float* __restrict__ sinb,float* __restrict__ p1,
                        float* __restrict__ p2,int H,int n,
                        int sRMS,int sRMS2,int sP1,int sP2){
  float mnY=g_red[2*sRMS],mxY=g_red[2*sRMS+1];
  float c10=fminf(mnY,0.f),c11=fmaxf(mxY,0.f);
  float amn=fq_range_d(mnY,c10,c11),amx=fq_range_d(mxY,c10,c11);
  float c20=fminf(amn,0.f),c21=fmaxf(amx,0.f);
  float y2n=g_red[2*sRMS2],y2x=g_red[2*sRMS2+1];
  float x2n=fq_range_d(fq_range_d(y2n,c10,c11),c20,c21);
  float x2x=fq_range_d(fq_range_d(y2x,c10,c11),c20,c21);
  float nTn=-x2x,nTx=-x2n;
  float n0=fminf(nTn,0.f),n1=fmaxf(nTx,0.f);
  float negLo=fq_range_d(nTn,n0,n1),negHi=fq_range_d(nTx,n0,n1);
  float qbMn=fq_range_d(amn,c20,c21),qbMx=fq_range_d(amx,c20,c21);
  float cc0=fminf(fminf(qbMn,negLo),0.f),cc1=fmaxf(fmaxf(qbMx,negHi),0.f);
  int i0=blockIdx.x*blockDim.x+threadIdx.x, st=gridDim.x*blockDim.x;
  float l1n=FLT_MAX,l1x=-FLT_MAX,l2n=FLT_MAX,l2x=-FLT_MAX;
  for(int i=i0;i<n;i+=st){
    int d=i%Dn; int r=i/Dn; int s=(r/H)%Sn; int b=r/(H*Sn);
    float qb=fq_range_d(fq_range_d(y[i],c10,c11),c20,c21);
    float rot;
    if(d<64){
      float qbp=fq_range_d(fq_range_d(y[i+64],c10,c11),c20,c21);
      rot=fq_range_d(fq_range_d(-qbp,n0,n1),cc0,cc1);
    } else {
      float qbp=fq_range_d(fq_range_d(y[i-64],c10,c11),c20,c21);
      rot=fq_range_d(qbp,cc0,cc1);
    }
    int ci=(b*Sn+s)*Dn+d;
    float v1=qb*cosb[ci], v2=rot*sinb[ci];
    p1[i]=v1; p2[i]=v2;
    l1n=fminf(l1n,v1); l1x=fmaxf(l1x,v1);
    l2n=fminf(l2n,v2); l2x=fmaxf(l2x,v2);
  }
  red_minmax_atomic(l1n,l1x,sP1);
  red_minmax_atomic(l2n,l2x,sP2);
}
__global__ void k_rope2(const float* __restrict__ p1,const float* __restrict__ p2,
                        float* __restrict__ out,int H,int n,int sP1,int sP2,int sSum){
  float a0=fminf(g_red[2*sP1],0.f),a1=fmaxf(g_red[2*sP1+1],0.f);
  float b0=fminf(g_red[2*sP2],0.f),b1=fmaxf(g_red[2*sP2+1],0.f);
  int i0=blockIdx.x*blockDim.x+threadIdx.x, st=gridDim.x*blockDim.x;
  float lmn=FLT_MAX,lmx=-FLT_MAX;
  for(int i=i0;i<n;i+=st){
    float v=fq_range_d(p1[i],a0,a1)+fq_range_d(p2[i],b0,b1);
    int d=i%Dn; int r=i/Dn; int h=r%H; int s=(r/H)%Sn; int b=r/(H*Sn);
    out[((size_t)(b*H+h)*Sn+s)*Dn+d]=v;
    lmn=fminf(lmn,v); lmx=fmaxf(lmx,v);
  }
  red_minmax_atomic(lmn,lmx,sSum);
}

#define ASZ (128*40)
#define BSZ (64*40)
#define VSZ (32*72)

// ---------- double-buffered bf16 mma.sync NT GEMM ----------
template<bool UBL>
__global__ __launch_bounds__(256) void mma_nt(
  const __nv_bfloat16* __restrict__ Ah,const __nv_bfloat16* __restrict__ Al,
  const __nv_bfloat16* __restrict__ Bh,const __nv_bfloat16* __restrict__ Bl,
  float* __restrict__ C,int K,int lda,int ldb,int ldc,
  int sOut,int scaleSlot,int batch)
{
  extern __shared__ __nv_bfloat16 sm[];
  __nv_bfloat16* Abase=sm;          // [st*2+p]*ASZ, 4*ASZ
  __nv_bfloat16* Bbase=sm+4*ASZ;    // UBL: [st*2+p]*BSZ else [st]*BSZ
  int z=blockIdx.z;
  if(batch==1){
    int b=z>>4,h=z&15;
    size_t ao=(size_t)z*Sn*Dn, bo=(size_t)(b*NKVn+(h>>1))*Sn*Dn, co=(size_t)z*Sn*Sn;
    Ah+=ao; Al+=ao; Bh+=bo; Bl+=bo; C+=co;
  }
  int tid=threadIdx.x, lane=tid&31, w=tid>>5;
  int wm=(w&3)*32, wn=(w>>2)*32;
  int g=lane>>2, t4=lane&3;
  int m0=blockIdx.y*128, n0=blockIdx.x*64;
  int mat=lane>>3, mrow=lane&7;
  float acc[2][4][4];
  #pragma unroll
  for(int i=0;i<2;i++)
    #pragma unroll
    for(int j=0;j<4;j++)
      #pragma unroll
      for(int r=0;r<4;r++) acc[i][j][r]=0.f;

  auto loadST=[&](int st,int k0){
    #pragma unroll
    for(int rep=0;rep<2;rep++){
      int c=tid+rep*256; int row=c>>2, col=(c&3)*8;
      cpa16(&Abase[(st*2+0)*ASZ+row*40+col],Ah+(size_t)(m0+row)*lda+k0+col);
      cpa16(&Abase[(st*2+1)*ASZ+row*40+col],Al+(size_t)(m0+row)*lda+k0+col);
    }
    { int row=tid>>2, col=(tid&3)*8;
      cpa16(&Bbase[(UBL?(st*2):st)*BSZ+row*40+col],Bh+(size_t)(n0+row)*ldb+k0+col);
      if(UBL) cpa16(&Bbase[(st*2+1)*BSZ+row*40+col],Bl+(size_t)(n0+row)*ldb+k0+col);
    }
  };
  int niter=K/32;
  loadST(0,0); CPCOMMIT();
  loadST(1,32); CPCOMMIT();
  for(int i=0;i<niter;i++){
    CPWAIT1(); __syncthreads();
    int st=i&1;
    const __nv_bfloat16* As0=Abase+(st*2+0)*ASZ;
    const __nv_bfloat16* As1=Abase+(st*2+1)*ASZ;
    const __nv_bfloat16* Bs0=Bbase+(UBL?(st*2):st)*BSZ;
    const __nv_bfloat16* Bs1=UBL?(Bbase+(st*2+1)*BSZ):Bs0;
    #pragma unroll
    for(int kk=0;kk<32;kk+=16){
      unsigned af[2][2][4];
      #pragma unroll
      for(int mt=0;mt<2;mt++){
        ldsm4(af[mt][0],sptr(&As0[(wm+mt*16+(mat&1)*8+mrow)*40 + kk + (mat>>1)*8]));
        ldsm4(af[mt][1],sptr(&As1[(wm+mt*16+(mat&1)*8+mrow)*40 + kk + (mat>>1)*8]));
      }
      unsigned bf[2][4][2];
      #pragma unroll
      for(int hf=0;hf<2;hf++){
        unsigned r[4];
        ldsm4(r,sptr(&Bs0[(wn+hf*16+(mat&1)*8+mrow)*40 + kk + (mat>>1)*8]));
        bf[0][hf*2+0][0]=r[0]; bf[0][hf*2+1][0]=r[1];
        bf[0][hf*2+0][1]=r[2]; bf[0][hf*2+1][1]=r[3];
        if(UBL){
          ldsm4(r,sptr(&Bs1[(wn+hf*16+(mat&1)*8+mrow)*40 + kk + (mat>>1)*8]));
          bf[1][hf*2+0][0]=r[0]; bf[1][hf*2+1][0]=r[1];
          bf[1][hf*2+0][1]=r[2]; bf[1][hf*2+1][1]=r[3];
        }
      }
      #pragma unroll
      for(int mt=0;mt<2;mt++)
        #pragma unroll
        for(int nt=0;nt<4;nt++){
          MMA16816(acc[mt][nt],af[mt][0],bf[0][nt][0],bf[0][nt][1]);
          if(UBL) MMA16816(acc[mt][nt],af[mt][0],bf[1][nt][0],bf[1][nt][1]);
          MMA16816(acc[mt][nt],af[mt][1],bf[0][nt][0],bf[0][nt][1]);
        }
    }
    __syncthreads();
    if(i+2<niter) loadST(st,(i+2)*32);
    CPCOMMIT();
  }
  float scl=1.f;
  if(scaleSlot>=0){float a0,a1,a2; get_params(2,scaleSlot,a0,a1,a2); scl=a2;}
  float lmn=FLT_MAX,lmx=-FLT_MAX;
  #pragma unroll
  for(int mt=0;mt<2;mt++)
    #pragma unroll
    for(int nt=0;nt<4;nt++){
      int r0=m0+wm+mt*16+g, c=n0+wn+nt*8+t4*2;
      float v0=acc[mt][nt][0]*scl, v1=acc[mt][nt][1]*scl;
      float v2=acc[mt][nt][2]*scl, v3=acc[mt][nt][3]*scl;
      C[(size_t)r0*ldc+c]=v0; C[(size_t)r0*ldc+c+1]=v1;
      C[(size_t)(r0+8)*ldc+c]=v2; C[(size_t)(r0+8)*ldc+c+1]=v3;
      lmn=fminf(fminf(lmn,fminf(v0,v1)),fminf(v2,v3));
      lmx=fmaxf(fmaxf(lmx,fmaxf(v0,v1)),fmaxf(v2,v3));
    }
  if(sOut>=0) red_minmax_atomic(lmn,lmx,sOut);
}

// ---------- AV (NN), double-buffered ----------
__global__ __launch_bounds__(256) void mma_av(
  const __nv_bfloat16* __restrict__ Ph,const __nv_bfloat16* __restrict__ Pl,
  const __nv_bfloat16* __restrict__ Vq,float* __restrict__ C)
{
  extern __shared__ __nv_bfloat16 sm[];
  __nv_bfloat16* Abase=sm;          // 4*ASZ
  __nv_bfloat16* Vbase=sm+4*ASZ;    // 2*VSZ
  int z=blockIdx.z,b=z>>4,h=z&15,h2=h>>1;
  Ph+=(size_t)z*Sn*Sn; Pl+=(size_t)z*Sn*Sn;
  Vq+=(size_t)b*Sn*KNn + h2*Dn;
  C +=(size_t)b*Sn*QNn + h*Dn;
  int tid=threadIdx.x, lane=tid&31, w=tid>>5;
  int wm=(w&3)*32, wn=(w>>2)*32;
  int g=lane>>2, t4=lane&3;
  int m0=blockIdx.y*128, n0=blockIdx.x*64;
  int mat=lane>>3, mrow=lane&7;
  float acc[2][4][4];
  #pragma unroll
  for(int i=0;i<2;i++)
    #pragma unroll
    for(int j=0;j<4;j++)
      #pragma unroll
      for(int r=0;r<4;r++) acc[i][j][r]=0.f;

  auto loadST=[&](int st,int k0){
    #pragma unroll
    for(int rep=0;rep<2;rep++){
      int c=tid+rep*256; int row=c>>2, col=(c&3)*8;
      cpa16(&Abase[(st*2+0)*ASZ+row*40+col],Ph+(size_t)(m0+row)*Sn+k0+col);
      cpa16(&Abase[(st*2+1)*ASZ+row*40+col],Pl+(size_t)(m0+row)*Sn+k0+col);
    }
    { int row=tid>>3, col=(tid&7)*8;
      cpa16(&Vbase[st*VSZ+row*72+col],Vq+(size_t)(k0+row)*KNn+n0+col);
    }
  };
  loadST(0,0); CPCOMMIT();
  loadST(1,32); CPCOMMIT();
  int niter=Sn/32;
  for(int i=0;i<niter;i++){
    CPWAIT1(); __syncthreads();
    int st=i&1;
    const __nv_bfloat16* As0=Abase+(st*2+0)*ASZ;
    const __nv_bfloat16* As1=Abase+(st*2+1)*ASZ;
    const __nv_bfloat16* Vs=Vbase+st*VSZ;
    #pragma unroll
    for(int kk=0;kk<32;kk+=16){
      unsigned af[2][2][4];
      #pragma unroll
      for(int mt=0;mt<2;mt++){
        ldsm4(af[mt][0],sptr(&As0[(wm+mt*16+(mat&1)*8+mrow)*40 + kk + (mat>>1)*8]));
        ldsm4(af[mt][1],sptr(&As1[(wm+mt*16+(mat&1)*8+mrow)*40 + kk + (mat>>1)*8]));
      }
      unsigned bf[4][2];
      #pragma unroll
      for(int hf=0;hf<2;hf++){
        unsigned r[4];
        ldsm4t(r,sptr(&Vs[(kk+(mat>>1)*8+mrow)*72 + wn + hf*16 + (mat&1)*8]));
        bf[hf*2+0][0]=r[0]; bf[hf*2+1][0]=r[1];
        bf[hf*2+0][1]=r[2]; bf[hf*2+1][1]=r[3];
      }
      #pragma unroll
      for(int mt=0;mt<2;mt++)
        #pragma unroll
        for(int nt=0;nt<4;nt++){
          MMA16816(acc[mt][nt],af[mt][0],bf[nt][0],bf[nt][1]);
          MMA16816(acc[mt][nt],af[mt][1],bf[nt][0],bf[nt][1]);
        }
    }
    __syncthreads();
    if(i+2<niter) loadST(st,(i+2)*32);
    CPCOMMIT();
  }
  float a0,a1,scl; get_params(2,S_V,a0,a1,scl);
  float lmn=FLT_MAX,lmx=-FLT_MAX;
  #pragma unroll
  for(int mt=0;mt<2;mt++)
    #pragma unroll
    for(int nt=0;nt<4;nt++){
      int r0=m0+wm+mt*16+g, c=n0+wn+nt*8+t4*2;
      float v0=acc[mt][nt][0]*scl, v1=acc[mt][nt][1]*scl;
      float v2=acc[mt][nt][2]*scl, v3=acc[mt][nt][3]*scl;
      C[(size_t)r0*QNn+c]=v0; C[(size_t)r0*QNn+c+1]=v1;
      C[(size_t)(r0+8)*QNn+c]=v2; C[(size_t)(r0+8)*QNn+c+1]=v3;
      lmn=fminf(fminf(lmn,fminf(v0,v1)),fminf(v2,v3));
      lmx=fmaxf(fmaxf(lmx,fmaxf(v0,v1)),fmaxf(v2,v3));
    }
  red_minmax_atomic(lmn,lmx,S_CTX);
}

__global__ void k_p1(float* __restrict__ sc,float* __restrict__ amin){
  int row=blockIdx.x; int s=row%Sn;
  float mnS=g_red[2*S_SC],mxS=g_red[2*S_SC+1];
  float q0=fminf(mnS,0.f),q1=fmaxf(mxS,0.f);
  float scal=(float)(0.08838834764831843);
  float scq=fq_range_d(scal,fminf(scal,0.f),fmaxf(scal,0.f));
  float lo=fq_range_d(mnS,q0,q1)*scq,hi=fq_range_d(mxS,q0,q1)*scq;
  float r0=fminf(lo,0.f),r1=fmaxf(hi,0.f);
  size_t base=(size_t)row*Sn;
  int t0=threadIdx.x*4;
  float4 xv=*(const float4*)&sc[base+t0];
  float x[4]={xv.x,xv.y,xv.z,xv.w};
  float rmn=FLT_MAX,umn=FLT_MAX,umx=-FLT_MAX;
  #pragma unroll
  for(int j=0;j<4;j++){
    float a=fq_range_d(fq_range_d(x[j],q0,q1)*scq,r0,r1);
    x[j]=a;
    rmn=fminf(rmn,a);
    if(t0+j<=s){umn=fminf(umn,a); umx=fmaxf(umx,a);}
  }
  *(float4*)&sc[base+t0]=make_float4(x[0],x[1],x[2],x[3]);
  float am=blk_min_b(rmn);
  if(threadIdx.x==0){
    amin[row]=am;
    atomicMinF(&g_red[2*S_AMIN],am); atomicMaxF(&g_red[2*S_AMIN+1],am);
    if(s<Sn-1){atomicMinF(&g_red[2*S_AMIN2],am); atomicMaxF(&g_red[2*S_AMIN2+1],am);}
  }
  red_minmax_atomic(umn,umx,S_UNM);
}
__global__ void k_p2(float* __restrict__ sc,const float* __restrict__ amin){
  int row=blockIdx.x; int s=row%Sn;
  float an=g_red[2*S_AMIN],ax=g_red[2*S_AMIN+1];
  float a0=fminf(an,0.f),a1=fmaxf(ax,0.f);
  float c20=fq_range_d(-20.0f,-20.0f,0.0f);
  float tn=fq_range_d(an,a0,a1)+c20,tx2=fq_range_d(ax,a0,a1)+c20;
  float v0=fminf(tn,0.f),v1=fmaxf(tx2,0.f);
  float a2n=g_red[2*S_AMIN2],a2x=g_red[2*S_AMIN2+1];
  float vlo=fq_range_d(fq_range_d(a2n,a0,a1)+c20,v0,v1);
  float vhi=fq_range_d(fq_range_d(a2x,a0,a1)+c20,v0,v1);
  float un=g_red[2*S_UNM],ux=g_red[2*S_UNM+1];
  float m0=fminf(fminf(un,vlo),0.f),m1=fmaxf(fmaxf(ux,vhi),0.f);
  float vv=fq_range_d(fq_range_d(amin[row],a0,a1)+c20,v0,v1);
  float vm=fq_range_d(vv,m0,m1);
  size_t base=(size_t)row*Sn;
  int t0=threadIdx.x*4;
  float4 xv=*(const float4*)&sc[base+t0];
  float x[4]={xv.x,xv.y,xv.z,xv.w};
  float lmx=-FLT_MAX;
  #pragma unroll
  for(int j=0;j<4;j++){
    x[j]=(t0+j<=s)?fq_range_d(x[j],m0,m1):vm;
    lmx=fmaxf(lmx,x[j]);
  }
  float m=blk_max_b(lmx);
  float ls=0.f;
  #pragma unroll
  for(int j=0;j<4;j++){ x[j]=expf(x[j]-m); ls+=x[j]; }
  float sum=blk_sum_b(ls);
  float pn=FLT_MAX,px=-FLT_MAX;
  #pragma unroll
  for(int j=0;j<4;j++){
    float p=x[j]/sum; x[j]=p;
    pn=fminf(pn,p); px=fmaxf(px,p);
  }
  *(float4*)&sc[base+t0]=make_float4(x[0],x[1],x[2],x[3]);
  red_minmax_atomic(pn,px,S_P);
}

extern "C" void kernel_launch(void* const* d_in,const int* in_sizes,int n_in,
                              void* d_out,int out_size){
  const float* hs  =(const float*)d_in[0];
  const float* cosb=(const float*)d_in[1];
  const float* sinb=(const float*)d_in[2];
  const float* Wq  =(const float*)d_in[4];
  const float* Wk  =(const float*)d_in[5];
  const float* Wv  =(const float*)d_in[6];
  const float* Wo  =(const float*)d_in[7];
  const float* qw  =(const float*)d_in[8];
  const float* kw  =(const float*)d_in[9];
  float* out=(float*)d_out;

  static int smset=0;
  if(!smset){
    cudaFuncSetAttribute(mma_nt<true>, cudaFuncAttributeMaxDynamicSharedMemorySize, 4*ASZ*2+4*BSZ*2);
    cudaFuncSetAttribute(mma_nt<false>,cudaFuncAttributeMaxDynamicSharedMemorySize, 4*ASZ*2+2*BSZ*2);
    cudaFuncSetAttribute(mma_av,       cudaFuncAttributeMaxDynamicSharedMemorySize, 4*ASZ*2+2*VSZ*2);
    smset=1;
  }

  float *pLin,*pP1,*pP2,*pQr,*pKr,*pV,*pCtx,*pSc,*pAmin;
  __nv_bfloat16 *pHsh,*pHsl,*pWqh,*pWql,*pWkh,*pWkl,*pWvh,*pWvl,*pWoh,*pWol;
  __nv_bfloat16 *pQh,*pQl,*pKq,*pVq,*pPh,*pPl,*pCh,*pCl;
  cudaGetSymbolAddress((void**)&pLin,g_lin);
  cudaGetSymbolAddress((void**)&pP1,g_p1b);
  cudaGetSymbolAddress((void**)&pP2,g_p2b);
  cudaGetSymbolAddress((void**)&pQr,g_qr);
  cudaGetSymbolAddress((void**)&pKr,g_kr);
  cudaGetSymbolAddress((void**)&pV,g_v);
  cudaGetSymbolAddress((void**)&pCtx,g_ctx);
  cudaGetSymbolAddress((void**)&pSc,g_scores);
  cudaGetSymbolAddress((void**)&pAmin,g_amin);
  cudaGetSymbolAddress((void**)&pHsh,g_hsh); cudaGetSymbolAddress((void**)&pHsl,g_hsl);
  cudaGetSymbolAddress((void**)&pWqh,g_wqh); cudaGetSymbolAddress((void**)&pWql,g_wql);
  cudaGetSymbolAddress((void**)&pWkh,g_wkh); cudaGetSymbolAddress((void**)&pWkl,g_wkl);
  cudaGetSymbolAddress((void**)&pWvh,g_wvh); cudaGetSymbolAddress((void**)&pWvl,g_wvl);
  cudaGetSymbolAddress((void**)&pWoh,g_woh); cudaGetSymbolAddress((void**)&pWol,g_wol);
  cudaGetSymbolAddress((void**)&pQh,g_qh); cudaGetSymbolAddress((void**)&pQl,g_ql);
  cudaGetSymbolAddress((void**)&pKq,g_kq8); cudaGetSymbolAddress((void**)&pVq,g_vq8);
  cudaGetSymbolAddress((void**)&pPh,g_ph); cudaGetSymbolAddress((void**)&pPl,g_pl);
  cudaGetSymbolAddress((void**)&pCh,g_ch); cudaGetSymbolAddress((void**)&pCl,g_cl);

  int SM_T=4*ASZ*2+4*BSZ*2, SM_F=4*ASZ*2+2*BSZ*2, SM_AV=4*ASZ*2+2*VSZ*2;

  k_init<<<1,64>>>();
  k_wsplit<<<QNn*HIDn/256,256>>>(Wq,pWqh,pWql);
  k_wsplit<<<KNn*HIDn/256,256>>>(Wk,pWkh,pWkl);
  k_wsplit<<<KNn*HIDn/256,256>>>(Wv,pWvh,pWvl);
  k_wsplit<<<HIDn*QNn/256,256>>>(Wo,pWoh,pWol);
  k_minmax<<<1024,256>>>(hs,N_HS,S_HS);
  k_fqsplit<<<2048,256>>>(hs,pHsh,pHsl,N_HS,S_HS);
  // Q path
  mma_nt<true><<<dim3(QNn/64,Mn/128,1),256,SM_T>>>(pHsh,pHsl,pWqh,pWql,pLin,HIDn,HIDn,HIDn,QNn,S_QLIN,-1,0);
  k_rms<<<Mn*NHn,128>>>(pLin,qw,S_QLIN,S_QRMS,S_QRMS2);
  k_rope1<<<2048,256>>>(pLin,cosb,sinb,pP1,pP2,NHn,N_Q,S_QRMS,S_QRMS2,S_QP1,S_QP2);
  k_rope2<<<2048,256>>>(pP1,pP2,pQr,NHn,N_Q,S_QP1,S_QP2,S_QSUM);
  k_fqsplit<<<2048,256>>>(pQr,pQh,pQl,N_Q,S_QSUM);
  // K path
  mma_nt<true><<<dim3(KNn/64,Mn/128,1),256,SM_T>>>(pHsh,pHsl,pWkh,pWkl,pLin,HIDn,HIDn,HIDn,KNn,S_KLIN,-1,0);
  k_rms<<<Mn*NKVn,128>>>(pLin,kw,S_KLIN,S_KRMS,S_KRMS2);
  k_rope1<<<1024,256>>>(pLin,cosb,sinb,pP1,pP2,NKVn,N_K,S_KRMS,S_KRMS2,S_KP1,S_KP2);
  k_rope2<<<1024,256>>>(pP1,pP2,pKr,NKVn,N_K,S_KP1,S_KP2,S_KSUM);
  k_fq8q<<<1024,256>>>(pKr,pKq,N_K,S_KSUM);
  // V path
  mma_nt<true><<<dim3(KNn/64,Mn/128,1),256,SM_T>>>(pHsh,pHsl,pWvh,pWvl,pV,HIDn,HIDn,HIDn,KNn,S_V,-1,0);
  k_fq8q<<<1024,256>>>(pV,pVq,N_K,S_V);
  // scores
  mma_nt<false><<<dim3(Sn/64,Sn/128,Bn*NHn),256,SM_F>>>(pQh,pQl,pKq,pKq,pSc,Dn,Dn,Dn,Sn,S_SC,S_KSUM,1);
  k_p1<<<NROWS,256>>>(pSc,pAmin);
  k_p2<<<NROWS,256>>>(pSc,pAmin);
  int wAttn=(out_size>=(int)(OUT_MAIN+N_SC))?1:0;
  k_psplit<<<8192,256>>>(pSc,pPh,pPl,out+OUT_MAIN,wAttn);
  // AV + output proj
  mma_av<<<dim3(Dn/64,Sn/128,Bn*NHn),256,SM_AV>>>(pPh,pPl,pVq,pCtx);
  k_fqsplit<<<2048,256>>>(pCtx,pCh,pCl,N_Q,S_CTX);
  mma_nt<true><<<dim3(HIDn/64,Mn/128,1),256,SM_T>>>(pCh,pCl,pWoh,pWol,out,QNn,QNn,QNn,HIDn,-1,-1,0);
}

// round 7
// speedup vs baseline: 2.5949x; 1.0208x over previous
#include <cuda_runtime.h>
#include <cuda_bf16.h>
#include <math.h>
#include <float.h>

#define Bn 2
#define Sn 1024
#define HIDn 2048
#define NHn 16
#define NKVn 8
#define Dn 128
#define Mn (Bn*Sn)
#define QNn (NHn*Dn)
#define KNn (NKVn*Dn)
#define FQEPS 1.5259021896696422e-09f
#define N_HS (Mn*HIDn)
#define N_Q  (Mn*QNn)
#define N_K  (Mn*KNn)
#define N_SC ((size_t)Bn*NHn*Sn*Sn)
#define NROWS (Bn*NHn*Sn)
#define OUT_MAIN (Mn*HIDn)

enum {S_HS=0,S_QLIN,S_QRMS,S_QRMS2,S_KLIN,S_KRMS,S_KRMS2,S_QP1,S_QP2,S_QSUM,
      S_KP1,S_KP2,S_KSUM,S_V,S_SC,S_AMIN,S_AMIN2,S_UNM,S_P,S_CTX,NSLOT};

__device__ float g_red[2*NSLOT];
__device__ float g_lin[N_Q];
__device__ float g_p1b[N_Q];
__device__ float g_p2b[N_Q];
__device__ float g_qr[N_Q];
__device__ float g_kr[N_K];
__device__ float g_v[N_K];
__device__ float g_ctx[N_Q];
__device__ float g_scores[N_SC];
__device__ float g_amin[NROWS];
__device__ __nv_bfloat16 g_hsh[N_HS], g_hsl[N_HS];
__device__ __nv_bfloat16 g_wqh[QNn*HIDn], g_wql[QNn*HIDn];
__device__ __nv_bfloat16 g_wkh[KNn*HIDn], g_wkl[KNn*HIDn];
__device__ __nv_bfloat16 g_wvh[KNn*HIDn], g_wvl[KNn*HIDn];
__device__ __nv_bfloat16 g_woh[HIDn*QNn], g_wol[HIDn*QNn];
__device__ __nv_bfloat16 g_qh[N_Q], g_ql[N_Q];
__device__ __nv_bfloat16 g_kq8[N_K];
__device__ __nv_bfloat16 g_vq8[N_K];
__device__ __nv_bfloat16 g_ph[N_SC], g_pl[N_SC];
__device__ __nv_bfloat16 g_ch[N_Q], g_cl[N_Q];

__device__ __forceinline__ void atomicMinF(float* a,float v){
  int* ai=(int*)a; int cur=*ai;
  while(v<__int_as_float(cur)){int old=atomicCAS(ai,cur,__float_as_int(v)); if(old==cur)break; cur=old;}
}
__device__ __forceinline__ void atomicMaxF(float* a,float v){
  int* ai=(int*)a; int cur=*ai;
  while(v>__int_as_float(cur)){int old=atomicCAS(ai,cur,__float_as_int(v)); if(old==cur)break; cur=old;}
}
__device__ __forceinline__ float warp_min(float v){
  #pragma unroll
  for(int o=16;o;o>>=1) v=fminf(v,__shfl_xor_sync(0xffffffffu,v,o));
  return v;
}
__device__ __forceinline__ float warp_max(float v){
  #pragma unroll
  for(int o=16;o;o>>=1) v=fmaxf(v,__shfl_xor_sync(0xffffffffu,v,o));
  return v;
}
__device__ __forceinline__ float warp_sum(float v){
  #pragma unroll
  for(int o=16;o;o>>=1) v+=__shfl_xor_sync(0xffffffffu,v,o);
  return v;
}
__device__ __forceinline__ void red_minmax_atomic(float lmn,float lmx,int slot){
  __shared__ float smn[8],smx[8];
  lmn=warp_min(lmn); lmx=warp_max(lmx);
  int lane=threadIdx.x&31,w=threadIdx.x>>5,nw=(blockDim.x+31)>>5;
  __syncthreads();
  if(lane==0){smn[w]=lmn;smx[w]=lmx;}
  __syncthreads();
  if(w==0){
    lmn=(lane<nw)?smn[lane]:FLT_MAX;
    lmx=(lane<nw)?smx[lane]:-FLT_MAX;
    lmn=warp_min(lmn); lmx=warp_max(lmx);
    if(lane==0){atomicMinF(&g_red[2*slot],lmn); atomicMaxF(&g_red[2*slot+1],lmx);}
  }
}
__device__ __forceinline__ float blk_max_b(float v){
  __shared__ float sh[8]; __shared__ float r;
  v=warp_max(v);
  int lane=threadIdx.x&31,w=threadIdx.x>>5,nw=(blockDim.x+31)>>5;
  __syncthreads();
  if(lane==0) sh[w]=v;
  __syncthreads();
  if(threadIdx.x==0){float m=-FLT_MAX; for(int i=0;i<nw;i++)m=fmaxf(m,sh[i]); r=m;}
  __syncthreads();
  return r;
}
__device__ __forceinline__ float blk_min_b(float v){
  __shared__ float sh[8]; __shared__ float r;
  v=warp_min(v);
  int lane=threadIdx.x&31,w=threadIdx.x>>5,nw=(blockDim.x+31)>>5;
  __syncthreads();
  if(lane==0) sh[w]=v;
  __syncthreads();
  if(threadIdx.x==0){float m=FLT_MAX; for(int i=0;i<nw;i++)m=fminf(m,sh[i]); r=m;}
  __syncthreads();
  return r;
}
__device__ __forceinline__ float blk_sum_b(float v){
  __shared__ float sh[8]; __shared__ float r;
  v=warp_sum(v);
  int lane=threadIdx.x&31,w=threadIdx.x>>5,nw=(blockDim.x+31)>>5;
  __syncthreads();
  if(lane==0) sh[w]=v;
  __syncthreads();
  if(threadIdx.x==0){float m=0.f; for(int i=0;i<nw;i++)m+=sh[i]; r=m;}
  __syncthreads();
  return r;
}
__device__ __forceinline__ float fq_range_d(float x,float mn,float mx){
  float scale=fmaxf((mx-mn)/65535.0f,FQEPS);
  float zp=rintf(-mn/scale);
  float q=fminf(fmaxf(rintf(x/scale)+zp,0.0f),65535.0f);
  return (q-zp)*scale;
}
__device__ __forceinline__ void get_params(int t,int s,float&a0,float&a1,float&a2){
  float mn=g_red[2*s],mx=g_red[2*s+1];
  a0=fminf(mn,0.f); a1=fmaxf(mx,0.f); a2=1;
  if(t==2){
    float lo=fq_range_d(mn,a0,a1),hi=fq_range_d(mx,a0,a1);
    a2=fmaxf(fmaxf(fabsf(lo),fabsf(hi))/127.0f,1e-12f);
  }
}
__device__ __forceinline__ void split_bf(float v,__nv_bfloat16& h,__nv_bfloat16& l){
  h=__float2bfloat16_rn(v);
  l=__float2bfloat16_rn(v-__bfloat162float(h));
}
__device__ __forceinline__ unsigned sptr(const void* p){
  return (unsigned)__cvta_generic_to_shared(p);
}
__device__ __forceinline__ void ldsm4(unsigned* r, unsigned addr){
  asm volatile("ldmatrix.sync.aligned.m8n8.x4.shared.b16 {%0,%1,%2,%3},[%4];"
    : "=r"(r[0]),"=r"(r[1]),"=r"(r[2]),"=r"(r[3]) : "r"(addr));
}
__device__ __forceinline__ void ldsm4t(unsigned* r, unsigned addr){
  asm volatile("ldmatrix.sync.aligned.m8n8.x4.trans.shared.b16 {%0,%1,%2,%3},[%4];"
    : "=r"(r[0]),"=r"(r[1]),"=r"(r[2]),"=r"(r[3]) : "r"(addr));
}
__device__ __forceinline__ void cpa16(void* s,const void* g){
  asm volatile("cp.async.cg.shared.global [%0],[%1],16;"::"r"(sptr(s)),"l"(g));
}
#define CPCOMMIT() asm volatile("cp.async.commit_group;")
#define CPWAIT1()  asm volatile("cp.async.wait_group 1;")
#define MMA16816(d,a,b0,b1) \
  asm volatile("mma.sync.aligned.m16n8k16.row.col.f32.bf16.bf16.f32 " \
    "{%0,%1,%2,%3},{%4,%5,%6,%7},{%8,%9},{%0,%1,%2,%3};" \
    : "+f"(d[0]),"+f"(d[1]),"+f"(d[2]),"+f"(d[3]) \
    : "r"(a[0]),"r"(a[1]),"r"(a[2]),"r"(a[3]),"r"(b0),"r"(b1))

__global__ void k_init(){
  int i=threadIdx.x;
  if(i<NSLOT){g_red[2*i]=FLT_MAX; g_red[2*i+1]=-FLT_MAX;}
}
__global__ void k_wsplit(const float* __restrict__ W,__nv_bfloat16* __restrict__ wh,
                         __nv_bfloat16* __restrict__ wl){
  int g=blockIdx.x*blockDim.x+threadIdx.x;
  float w=W[g];
  float a=fabsf(w);
  #pragma unroll
  for(int o=16;o;o>>=1) a=fmaxf(a,__shfl_xor_sync(0xffffffffu,a,o));
  float s=fmaxf(a/7.0f,1e-12f);
  float v=fminf(fmaxf(rintf(w/s),-8.0f),7.0f)*s;
  split_bf(v,wh[g],wl[g]);
}
__global__ void k_minmax(const float* __restrict__ x,int n,int slot){
  int i=blockIdx.x*blockDim.x+threadIdx.x, st=gridDim.x*blockDim.x;
  float lmn=FLT_MAX,lmx=-FLT_MAX;
  for(;i<n;i+=st){float v=x[i]; lmn=fminf(lmn,v); lmx=fmaxf(lmx,v);}
  red_minmax_atomic(lmn,lmx,slot);
}
__global__ void k_fqsplit(const float* __restrict__ in,__nv_bfloat16* __restrict__ hi,
                          __nv_bfloat16* __restrict__ lo,int n,int slot){
  float a0,a1,a2; get_params(1,slot,a0,a1,a2);
  int i=blockIdx.x*blockDim.x+threadIdx.x, st=gridDim.x*blockDim.x;
  for(;i<n;i+=st){
    float v=fq_range_d(in[i],a0,a1);
    split_bf(v,hi[i],lo[i]);
  }
}
__global__ void k_fq8q(const float* __restrict__ in,__nv_bfloat16* __restrict__ q8,
                       int n,int slot){
  float a0,a1,a2; get_params(2,slot,a0,a1,a2);
  int i=blockIdx.x*blockDim.x+threadIdx.x, st=gridDim.x*blockDim.x;
  for(;i<n;i+=st){
    float v=fq_range_d(in[i],a0,a1);
    float q=fminf(fmaxf(rintf(v/a2),-128.f),127.f);
    q8[i]=__float2bfloat16_rn(q);
  }
}
__global__ void k_psplit(const float* __restrict__ in,__nv_bfloat16* __restrict__ hi,
                         __nv_bfloat16* __restrict__ lo,float* __restrict__ attn,int wAttn){
  float a0,a1,a2; get_params(1,S_P,a0,a1,a2);
  size_t i=((size_t)blockIdx.x*blockDim.x+threadIdx.x)*4;
  size_t st=(size_t)gridDim.x*blockDim.x*4;
  for(;i<N_SC;i+=st){
    float4 x=*(const float4*)&in[i];
    float v0=fq_range_d(x.x,a0,a1),v1=fq_range_d(x.y,a0,a1);
    float v2=fq_range_d(x.z,a0,a1),v3=fq_range_d(x.w,a0,a1);
    split_bf(v0,hi[i],lo[i]); split_bf(v1,hi[i+1],lo[i+1]);
    split_bf(v2,hi[i+2],lo[i+2]); split_bf(v3,hi[i+3],lo[i+3]);
    if(wAttn) *(float4*)&attn[i]=make_float4(v0,v1,v2,v3);
  }
}
__global__ void k_rms(float* __restrict__ x,const float* __restrict__ w,
                      int sIn,int sOut,int sOut2){
  int row=blockIdx.x,d=threadIdx.x;
  float mn=fminf(g_red[2*sIn],0.f),mx=fmaxf(g_red[2*sIn+1],0.f);
  size_t idx=(size_t)row*Dn+d;
  float v=fq_range_d(x[idx],mn,mx);
  float s=warp_sum(v*v);
  __shared__ float sh[4];
  if((d&31)==0) sh[d>>5]=s;
  __syncthreads();
  float var=(sh[0]+sh[1]+sh[2]+sh[3])*(1.0f/128.0f);
  float y=v*(1.0f/sqrtf(var+1e-6f))*w[d];
  x[idx]=y;
  red_minmax_atomic(y,y,sOut);
  float m2n=(d>=64)?y:FLT_MAX, m2x=(d>=64)?y:-FLT_MAX;
  red_minmax_atomic(m2n,m2x,sOut2);
}
__global__ void k_rope1(const float* __restrict__ y,const float* __restrict__ cosb,
                        const float* __restrict__ sinb,float* __restrict__ p1,
                        float* __restrict__ p2,int H,int n,
                        int sRMS,int sRMS2,int sP1,int sP2){
  float mnY=g_red[2*sRMS],mxY=g_red[2*sRMS+1];
  float c10=fminf(mnY,0.f),c11=fmaxf(mxY,0.f);
  float amn=fq_range_d(mnY,c10,c11),amx=fq_range_d(mxY,c10,c11);
  float c20=fminf(amn,0.f),c21=fmaxf(amx,0.f);
  float y2n=g_red[2*sRMS2],y2x=g_red[2*sRMS2+1];
  float x2n=fq_range_d(fq_range_d(y2n,c10,c11),c20,c21);
  float x2x=fq_range_d(fq_range_d(y2x,c10,c11),c20,c21);
  float nTn=-x2x,nTx=-x2n;
  float n0=fminf(nTn,0.f),n1=fmaxf(nTx,0.f);
  float negLo=fq_range_d(nTn,n0,n1),negHi=fq_range_d(nTx,n0,n1);
  float qbMn=fq_range_d(amn,c20,c21),qbMx=fq_range_d(amx,c20,c21);
  float cc0=fminf(fminf(qbMn,negLo),0.f),cc1=fmaxf(fmaxf(qbMx,negHi),0.f);
  int i0=blockIdx.x*blockDim.x+threadIdx.x, st=gridDim.x*blockDim.x;
  float l1n=FLT_MAX,l1x=-FLT_MAX,l2n=FLT_MAX,l2x=-FLT_MAX;
  for(int i=i0;i<n;i+=st){
    int d=i%Dn; int r=i/Dn; int s=(r/H)%Sn; int b=r/(H*Sn);
    float qb=fq_range_d(fq_range_d(y[i],c10,c11),c20,c21);
    float rot;
    if(d<64){
      float qbp=fq_range_d(fq_range_d(y[i+64],c10,c11),c20,c21);
      rot=fq_range_d(fq_range_d(-qbp,n0,n1),cc0,cc1);
    } else {
      float qbp=fq_range_d(fq_range_d(y[i-64],c10,c11),c20,c21);
      rot=fq_range_d(qbp,cc0,cc1);
    }
    int ci=(b*Sn+s)*Dn+d;
    float v1=qb*cosb[ci], v2=rot*sinb[ci];
    p1[i]=v1; p2[i]=v2;
    l1n=fminf(l1n,v1); l1x=fmaxf(l1x,v1);
    l2n=fminf(l2n,v2); l2x=fmaxf(l2x,v2);
  }
  red_minmax_atomic(l1n,l1x,sP1);
  red_minmax_atomic(l2n,l2x,sP2);
}
__global__ void k_rope2(const float* __restrict__ p1,const float* __restrict__ p2,
                        float* __restrict__ out,int H,int n,int sP1,int sP2,int sSum){
  float a0=fminf(g_red[2*sP1],0.f),a1=fmaxf(g_red[2*sP1+1],0.f);
  float b0=fminf(g_red[2*sP2],0.f),b1=fmaxf(g_red[2*sP2+1],0.f);
  int i0=blockIdx.x*blockDim.x+threadIdx.x, st=gridDim.x*blockDim.x;
  float lmn=FLT_MAX,lmx=-FLT_MAX;
  for(int i=i0;i<n;i+=st){
    float v=fq_range_d(p1[i],a0,a1)+fq_range_d(p2[i],b0,b1);
    int d=i%Dn; int r=i/Dn; int h=r%H; int s=(r/H)%Sn; int b=r/(H*Sn);
    out[((size_t)(b*H+h)*Sn+s)*Dn+d]=v;
    lmn=fminf(lmn,v); lmx=fmaxf(lmx,v);
  }
  red_minmax_atomic(lmn,lmx,sSum);
}

#define ASZ (128*40)
#define VSZ (32*136)

// ---------- 128x128 double-buffered bf16 mma.sync NT GEMM ----------
// C = (Ah+Al) @ (Bh[+Bl])^T [*scale]; 8 warps (4 m x 2 n), warp tile 32x64.
template<bool UBL>
__global__ __launch_bounds__(256) void mma_nt(
  const __nv_bfloat16* __restrict__ Ah,const __nv_bfloat16* __restrict__ Al,
  const __nv_bfloat16* __restrict__ Bh,const __nv_bfloat16* __restrict__ Bl,
  float* __restrict__ C,int K,int lda,int ldb,int ldc,
  int sOut,int scaleSlot,int batch)
{
  extern __shared__ __nv_bfloat16 sm[];
  __nv_bfloat16* Abase=sm;                 // 4*ASZ (2 stages x 2 parts)
  __nv_bfloat16* Bbase=sm+4*ASZ;           // UBL: 4*ASZ else 2*ASZ
  int z=blockIdx.z;
  if(batch==1){
    int b=z>>4,h=z&15;
    size_t ao=(size_t)z*Sn*Dn, bo=(size_t)(b*NKVn+(h>>1))*Sn*Dn, co=(size_t)z*Sn*Sn;
    Ah+=ao; Al+=ao; Bh+=bo; Bl+=bo; C+=co;
  }
  int tid=threadIdx.x, lane=tid&31, w=tid>>5;
  int wm=(w&3)*32, wn=(w>>2)*64;
  int g=lane>>2, t4=lane&3;
  int m0=blockIdx.y*128, n0=blockIdx.x*128;
  int mat=lane>>3, mrow=lane&7;
  float acc[2][8][4];
  #pragma unroll
  for(int i=0;i<2;i++)
    #pragma unroll
    for(int j=0;j<8;j++)
      #pragma unroll
      for(int r=0;r<4;r++) acc[i][j][r]=0.f;

  auto loadST=[&](int st,int k0){
    #pragma unroll
    for(int rep=0;rep<2;rep++){
      int c=tid+rep*256; int row=c>>2, col=(c&3)*8;
      cpa16(&Abase[(st*2+0)*ASZ+row*40+col],Ah+(size_t)(m0+row)*lda+k0+col);
      cpa16(&Abase[(st*2+1)*ASZ+row*40+col],Al+(size_t)(m0+row)*lda+k0+col);
      cpa16(&Bbase[(UBL?(st*2):st)*ASZ+row*40+col],Bh+(size_t)(n0+row)*ldb+k0+col);
      if(UBL) cpa16(&Bbase[(st*2+1)*ASZ+row*40+col],Bl+(size_t)(n0+row)*ldb+k0+col);
    }
  };
  int niter=K/32;
  loadST(0,0); CPCOMMIT();
  loadST(1,32); CPCOMMIT();
  for(int i=0;i<niter;i++){
    CPWAIT1(); __syncthreads();
    int st=i&1;
    const __nv_bfloat16* As0=Abase+(st*2+0)*ASZ;
    const __nv_bfloat16* As1=Abase+(st*2+1)*ASZ;
    const __nv_bfloat16* Bs0=Bbase+(UBL?(st*2):st)*ASZ;
    const __nv_bfloat16* Bs1=UBL?(Bbase+(st*2+1)*ASZ):Bs0;
    #pragma unroll
    for(int kk=0;kk<32;kk+=16){
      unsigned af[2][2][4];
      #pragma unroll
      for(int mt=0;mt<2;mt++){
        ldsm4(af[mt][0],sptr(&As0[(wm+mt*16+(mat&1)*8+mrow)*40 + kk + (mat>>1)*8]));
        ldsm4(af[mt][1],sptr(&As1[(wm+mt*16+(mat&1)*8+mrow)*40 + kk + (mat>>1)*8]));
      }
      unsigned bf[8][2];
      #pragma unroll
      for(int hf=0;hf<4;hf++){
        unsigned r[4];
        ldsm4(r,sptr(&Bs0[(wn+hf*16+(mat&1)*8+mrow)*40 + kk + (mat>>1)*8]));
        bf[hf*2+0][0]=r[0]; bf[hf*2+1][0]=r[1];
        bf[hf*2+0][1]=r[2]; bf[hf*2+1][1]=r[3];
      }
      #pragma unroll
      for(int mt=0;mt<2;mt++)
        #pragma unroll
        for(int nt=0;nt<8;nt++){
          MMA16816(acc[mt][nt],af[mt][0],bf[nt][0],bf[nt][1]);
          MMA16816(acc[mt][nt],af[mt][1],bf[nt][0],bf[nt][1]);
        }
      if(UBL){
        #pragma unroll
        for(int hf=0;hf<4;hf++){
          unsigned r[4];
          ldsm4(r,sptr(&Bs1[(wn+hf*16+(mat&1)*8+mrow)*40 + kk + (mat>>1)*8]));
          bf[hf*2+0][0]=r[0]; bf[hf*2+1][0]=r[1];
          bf[hf*2+0][1]=r[2]; bf[hf*2+1][1]=r[3];
        }
        #pragma unroll
        for(int mt=0;mt<2;mt++)
          #pragma unroll
          for(int nt=0;nt<8;nt++)
            MMA16816(acc[mt][nt],af[mt][0],bf[nt][0],bf[nt][1]);
      }
    }
    __syncthreads();
    if(i+2<niter) loadST(st,(i+2)*32);
    CPCOMMIT();
  }
  float scl=1.f;
  if(scaleSlot>=0){float a0,a1,a2; get_params(2,scaleSlot,a0,a1,a2); scl=a2;}
  float lmn=FLT_MAX,lmx=-FLT_MAX;
  #pragma unroll
  for(int mt=0;mt<2;mt++)
    #pragma unroll
    for(int nt=0;nt<8;nt++){
      int r0=m0+wm+mt*16+g, c=n0+wn+nt*8+t4*2;
      float v0=acc[mt][nt][0]*scl, v1=acc[mt][nt][1]*scl;
      float v2=acc[mt][nt][2]*scl, v3=acc[mt][nt][3]*scl;
      C[(size_t)r0*ldc+c]=v0; C[(size_t)r0*ldc+c+1]=v1;
      C[(size_t)(r0+8)*ldc+c]=v2; C[(size_t)(r0+8)*ldc+c+1]=v3;
      lmn=fminf(fminf(lmn,fminf(v0,v1)),fminf(v2,v3));
      lmx=fmaxf(fmaxf(lmx,fmaxf(v0,v1)),fmaxf(v2,v3));
    }
  if(sOut>=0) red_minmax_atomic(lmn,lmx,sOut);
}

// ---------- AV (NN), 128x128, double-buffered ----------
__global__ __launch_bounds__(256) void mma_av(
  const __nv_bfloat16* __restrict__ Ph,const __nv_bfloat16* __restrict__ Pl,
  const __nv_bfloat16* __restrict__ Vq,float* __restrict__ C)
{
  extern __shared__ __nv_bfloat16 sm[];
  __nv_bfloat16* Abase=sm;          // 4*ASZ
  __nv_bfloat16* Vbase=sm+4*ASZ;    // 2*VSZ
  int z=blockIdx.z,b=z>>4,h=z&15,h2=h>>1;
  Ph+=(size_t)z*Sn*Sn; Pl+=(size_t)z*Sn*Sn;
  Vq+=(size_t)b*Sn*KNn + h2*Dn;
  C +=(size_t)b*Sn*QNn + h*Dn;
  int tid=threadIdx.x, lane=tid&31, w=tid>>5;
  int wm=(w&3)*32, wn=(w>>2)*64;
  int g=lane>>2, t4=lane&3;
  int m0=blockIdx.y*128;
  int mat=lane>>3, mrow=lane&7;
  float acc[2][8][4];
  #pragma unroll
  for(int i=0;i<2;i++)
    #pragma unroll
    for(int j=0;j<8;j++)
      #pragma unroll
      for(int r=0;r<4;r++) acc[i][j][r]=0.f;

  auto loadST=[&](int st,int k0){
    #pragma unroll
    for(int rep=0;rep<2;rep++){
      int c=tid+rep*256; int row=c>>2, col=(c&3)*8;
      cpa16(&Abase[(st*2+0)*ASZ+row*40+col],Ph+(size_t)(m0+row)*Sn+k0+col);
      cpa16(&Abase[(st*2+1)*ASZ+row*40+col],Pl+(size_t)(m0+row)*Sn+k0+col);
      int vr=c>>4, vc=(c&15)*8;
      cpa16(&Vbase[st*VSZ+vr*136+vc],Vq+(size_t)(k0+vr)*KNn+vc);
    }
  };
  loadST(0,0); CPCOMMIT();
  loadST(1,32); CPCOMMIT();
  int niter=Sn/32;
  for(int i=0;i<niter;i++){
    CPWAIT1(); __syncthreads();
    int st=i&1;
    const __nv_bfloat16* As0=Abase+(st*2+0)*ASZ;
    const __nv_bfloat16* As1=Abase+(st*2+1)*ASZ;
    const __nv_bfloat16* Vs=Vbase+st*VSZ;
    #pragma unroll
    for(int kk=0;kk<32;kk+=16){
      unsigned af[2][2][4];
      #pragma unroll
      for(int mt=0;mt<2;mt++){
        ldsm4(af[mt][0],sptr(&As0[(wm+mt*16+(mat&1)*8+mrow)*40 + kk + (mat>>1)*8]));
        ldsm4(af[mt][1],sptr(&As1[(wm+mt*16+(mat&1)*8+mrow)*40 + kk + (mat>>1)*8]));
      }
      unsigned bf[8][2];
      #pragma unroll
      for(int hf=0;hf<4;hf++){
        unsigned r[4];
        ldsm4t(r,sptr(&Vs[(kk+(mat>>1)*8+mrow)*136 + wn + hf*16 + (mat&1)*8]));
        bf[hf*2+0][0]=r[0]; bf[hf*2+1][0]=r[1];
        bf[hf*2+0][1]=r[2]; bf[hf*2+1][1]=r[3];
      }
      #pragma unroll
      for(int mt=0;mt<2;mt++)
        #pragma unroll
        for(int nt=0;nt<8;nt++){
          MMA16816(acc[mt][nt],af[mt][0],bf[nt][0],bf[nt][1]);
          MMA16816(acc[mt][nt],af[mt][1],bf[nt][0],bf[nt][1]);
        }
    }
    __syncthreads();
    if(i+2<niter) loadST(st,(i+2)*32);
    CPCOMMIT();
  }
  float a0,a1,scl; get_params(2,S_V,a0,a1,scl);
  float lmn=FLT_MAX,lmx=-FLT_MAX;
  #pragma unroll
  for(int mt=0;mt<2;mt++)
    #pragma unroll
    for(int nt=0;nt<8;nt++){
      int r0=m0+wm+mt*16+g, c=wn+nt*8+t4*2;
      float v0=acc[mt][nt][0]*scl, v1=acc[mt][nt][1]*scl;
      float v2=acc[mt][nt][2]*scl, v3=acc[mt][nt][3]*scl;
      C[(size_t)r0*QNn+c]=v0; C[(size_t)r0*QNn+c+1]=v1;
      C[(size_t)(r0+8)*QNn+c]=v2; C[(size_t)(r0+8)*QNn+c+1]=v3;
      lmn=fminf(fminf(lmn,fminf(v0,v1)),fminf(v2,v3));
      lmx=fmaxf(fmaxf(lmx,fmaxf(v0,v1)),fmaxf(v2,v3));
    }
  red_minmax_atomic(lmn,lmx,S_CTX);
}

// k_p1: pure reduction pass (no writes to scores)
__global__ void k_p1(const float* __restrict__ sc,float* __restrict__ amin){
  int row=blockIdx.x; int s=row%Sn;
  float mnS=g_red[2*S_SC],mxS=g_red[2*S_SC+1];
  float q0=fminf(mnS,0.f),q1=fmaxf(mxS,0.f);
  float scal=(float)(0.08838834764831843);
  float scq=fq_range_d(scal,fminf(scal,0.f),fmaxf(scal,0.f));
  float lo=fq_range_d(mnS,q0,q1)*scq,hi=fq_range_d(mxS,q0,q1)*scq;
  float r0=fminf(lo,0.f),r1=fmaxf(hi,0.f);
  size_t base=(size_t)row*Sn;
  int t0=threadIdx.x*4;
  float4 xv=*(const float4*)&sc[base+t0];
  float x[4]={xv.x,xv.y,xv.z,xv.w};
  float rmn=FLT_MAX,umn=FLT_MAX,umx=-FLT_MAX;
  #pragma unroll
  for(int j=0;j<4;j++){
    float a=fq_range_d(fq_range_d(x[j],q0,q1)*scq,r0,r1);
    rmn=fminf(rmn,a);
    if(t0+j<=s){umn=fminf(umn,a); umx=fmaxf(umx,a);}
  }
  float am=blk_min_b(rmn);
  if(threadIdx.x==0){
    amin[row]=am;
    atomicMinF(&g_red[2*S_AMIN],am); atomicMaxF(&g_red[2*S_AMIN+1],am);
    if(s<Sn-1){atomicMinF(&g_red[2*S_AMIN2],am); atomicMaxF(&g_red[2*S_AMIN2+1],am);}
  }
  red_minmax_atomic(umn,umx,S_UNM);
}
// k_p2: recompute fq chain from raw scores, softmax, write probs
__global__ void k_p2(float* __restrict__ sc,const float* __restrict__ amin){
  int row=blockIdx.x; int s=row%Sn;
  float mnS=g_red[2*S_SC],mxS=g_red[2*S_SC+1];
  float q0=fminf(mnS,0.f),q1=fmaxf(mxS,0.f);
  float scal=(float)(0.08838834764831843);
  float scq=fq_range_d(scal,fminf(scal,0.f),fmaxf(scal,0.f));
  float lo=fq_range_d(mnS,q0,q1)*scq,hi=fq_range_d(mxS,q0,q1)*scq;
  float r0=fminf(lo,0.f),r1=fmaxf(hi,0.f);
  float an=g_red[2*S_AMIN],ax=g_red[2*S_AMIN+1];
  float a0=fminf(an,0.f),a1=fmaxf(ax,0.f);
  float c20=fq_range_d(-20.0f,-20.0f,0.0f);
  float tn=fq_range_d(an,a0,a1)+c20,tx2=fq_range_d(ax,a0,a1)+c20;
  float v0=fminf(tn,0.f),v1=fmaxf(tx2,0.f);
  float a2n=g_red[2*S_AMIN2],a2x=g_red[2*S_AMIN2+1];
  float vlo=fq_range_d(fq_range_d(a2n,a0,a1)+c20,v0,v1);
  float vhi=fq_range_d(fq_range_d(a2x,a0,a1)+c20,v0,v1);
  float un=g_red[2*S_UNM],ux=g_red[2*S_UNM+1];
  float m0=fminf(fminf(un,vlo),0.f),m1=fmaxf(fmaxf(ux,vhi),0.f);
  float vv=fq_range_d(fq_range_d(amin[row],a0,a1)+c20,v0,v1);
  float vm=fq_range_d(vv,m0,m1);
  size_t base=(size_t)row*Sn;
  int t0=threadIdx.x*4;
  float4 xv=*(const float4*)&sc[base+t0];
  float x[4]={xv.x,xv.y,xv.z,xv.w};
  float lmx=-FLT_MAX;
  #pragma unroll
  for(int j=0;j<4;j++){
    float a=fq_range_d(fq_range_d(x[j],q0,q1)*scq,r0,r1);
    x[j]=(t0+j<=s)?fq_range_d(a,m0,m1):vm;
    lmx=fmaxf(lmx,x[j]);
  }
  float m=blk_max_b(lmx);
  float ls=0.f;
  #pragma unroll
  for(int j=0;j<4;j++){ x[j]=expf(x[j]-m); ls+=x[j]; }
  float sum=blk_sum_b(ls);
  float pn=FLT_MAX,px=-FLT_MAX;
  #pragma unroll
  for(int j=0;j<4;j++){
    float p=x[j]/sum; x[j]=p;
    pn=fminf(pn,p); px=fmaxf(px,p);
  }
  *(float4*)&sc[base+t0]=make_float4(x[0],x[1],x[2],x[3]);
  red_minmax_atomic(pn,px,S_P);
}

extern "C" void kernel_launch(void* const* d_in,const int* in_sizes,int n_in,
                              void* d_out,int out_size){
  const float* hs  =(const float*)d_in[0];
  const float* cosb=(const float*)d_in[1];
  const float* sinb=(const float*)d_in[2];
  const float* Wq  =(const float*)d_in[4];
  const float* Wk  =(const float*)d_in[5];
  const float* Wv  =(const float*)d_in[6];
  const float* Wo  =(const float*)d_in[7];
  const float* qw  =(const float*)d_in[8];
  const float* kw  =(const float*)d_in[9];
  float* out=(float*)d_out;

  int SM_T=8*ASZ*2;                 // 81920 B
  int SM_F=6*ASZ*2;                 // 61440 B
  int SM_AV=4*ASZ*2+2*VSZ*2;        // 58368 B
  static int smset=0;
  if(!smset){
    cudaFuncSetAttribute(mma_nt<true>, cudaFuncAttributeMaxDynamicSharedMemorySize, SM_T);
    cudaFuncSetAttribute(mma_nt<false>,cudaFuncAttributeMaxDynamicSharedMemorySize, SM_F);
    cudaFuncSetAttribute(mma_av,       cudaFuncAttributeMaxDynamicSharedMemorySize, SM_AV);
    smset=1;
  }

  float *pLin,*pP1,*pP2,*pQr,*pKr,*pV,*pCtx,*pSc,*pAmin;
  __nv_bfloat16 *pHsh,*pHsl,*pWqh,*pWql,*pWkh,*pWkl,*pWvh,*pWvl,*pWoh,*pWol;
  __nv_bfloat16 *pQh,*pQl,*pKq,*pVq,*pPh,*pPl,*pCh,*pCl;
  cudaGetSymbolAddress((void**)&pLin,g_lin);
  cudaGetSymbolAddress((void**)&pP1,g_p1b);
  cudaGetSymbolAddress((void**)&pP2,g_p2b);
  cudaGetSymbolAddress((void**)&pQr,g_qr);
  cudaGetSymbolAddress((void**)&pKr,g_kr);
  cudaGetSymbolAddress((void**)&pV,g_v);
  cudaGetSymbolAddress((void**)&pCtx,g_ctx);
  cudaGetSymbolAddress((void**)&pSc,g_scores);
  cudaGetSymbolAddress((void**)&pAmin,g_amin);
  cudaGetSymbolAddress((void**)&pHsh,g_hsh); cudaGetSymbolAddress((void**)&pHsl,g_hsl);
  cudaGetSymbolAddress((void**)&pWqh,g_wqh); cudaGetSymbolAddress((void**)&pWql,g_wql);
  cudaGetSymbolAddress((void**)&pWkh,g_wkh); cudaGetSymbolAddress((void**)&pWkl,g_wkl);
  cudaGetSymbolAddress((void**)&pWvh,g_wvh); cudaGetSymbolAddress((void**)&pWvl,g_wvl);
  cudaGetSymbolAddress((void**)&pWoh,g_woh); cudaGetSymbolAddress((void**)&pWol,g_wol);
  cudaGetSymbolAddress((void**)&pQh,g_qh); cudaGetSymbolAddress((void**)&pQl,g_ql);
  cudaGetSymbolAddress((void**)&pKq,g_kq8); cudaGetSymbolAddress((void**)&pVq,g_vq8);
  cudaGetSymbolAddress((void**)&pPh,g_ph); cudaGetSymbolAddress((void**)&pPl,g_pl);
  cudaGetSymbolAddress((void**)&pCh,g_ch); cudaGetSymbolAddress((void**)&pCl,g_cl);

  k_init<<<1,64>>>();
  k_wsplit<<<QNn*HIDn/256,256>>>(Wq,pWqh,pWql);
  k_wsplit<<<KNn*HIDn/256,256>>>(Wk,pWkh,pWkl);
  k_wsplit<<<KNn*HIDn/256,256>>>(Wv,pWvh,pWvl);
  k_wsplit<<<HIDn*QNn/256,256>>>(Wo,pWoh,pWol);
  k_minmax<<<1024,256>>>(hs,N_HS,S_HS);
  k_fqsplit<<<2048,256>>>(hs,pHsh,pHsl,N_HS,S_HS);
  // Q path
  mma_nt<true><<<dim3(QNn/128,Mn/128,1),256,SM_T>>>(pHsh,pHsl,pWqh,pWql,pLin,HIDn,HIDn,HIDn,QNn,S_QLIN,-1,0);
  k_rms<<<Mn*NHn,128>>>(pLin,qw,S_QLIN,S_QRMS,S_QRMS2);
  k_rope1<<<2048,256>>>(pLin,cosb,sinb,pP1,pP2,NHn,N_Q,S_QRMS,S_QRMS2,S_QP1,S_QP2);
  k_rope2<<<2048,256>>>(pP1,pP2,pQr,NHn,N_Q,S_QP1,S_QP2,S_QSUM);
  k_fqsplit<<<2048,256>>>(pQr,pQh,pQl,N_Q,S_QSUM);
  // K path
  mma_nt<true><<<dim3(KNn/128,Mn/128,1),256,SM_T>>>(pHsh,pHsl,pWkh,pWkl,pLin,HIDn,HIDn,HIDn,KNn,S_KLIN,-1,0);
  k_rms<<<Mn*NKVn,128>>>(pLin,kw,S_KLIN,S_KRMS,S_KRMS2);
  k_rope1<<<1024,256>>>(pLin,cosb,sinb,pP1,pP2,NKVn,N_K,S_KRMS,S_KRMS2,S_KP1,S_KP2);
  k_rope2<<<1024,256>>>(pP1,pP2,pKr,NKVn,N_K,S_KP1,S_KP2,S_KSUM);
  k_fq8q<<<1024,256>>>(pKr,pKq,N_K,S_KSUM);
  // V path
  mma_nt<true><<<dim3(KNn/128,Mn/128,1),256,SM_T>>>(pHsh,pHsl,pWvh,pWvl,pV,HIDn,HIDn,HIDn,KNn,S_V,-1,0);
  k_fq8q<<<1024,256>>>(pV,pVq,N_K,S_V);
  // scores: q(2 parts) x kq(int8-exact) * ks
  mma_nt<false><<<dim3(Sn/128,Sn/128,Bn*NHn),256,SM_F>>>(pQh,pQl,pKq,pKq,pSc,Dn,Dn,Dn,Sn,S_SC,S_KSUM,1);
  k_p1<<<NROWS,256>>>(pSc,pAmin);
  k_p2<<<NROWS,256>>>(pSc,pAmin);
  int wAttn=(out_size>=(int)(OUT_MAIN+N_SC))?1:0;
  k_psplit<<<8192,256>>>(pSc,pPh,pPl,out+OUT_MAIN,wAttn);
  // AV + output proj
  mma_av<<<dim3(1,Sn/128,Bn*NHn),256,SM_AV>>>(pPh,pPl,pVq,pCtx);
  k_fqsplit<<<2048,256>>>(pCtx,pCh,pCl,N_Q,S_CTX);
  mma_nt<true><<<dim3(HIDn/128,Mn/128,1),256,SM_T>>>(pCh,pCl,pWoh,pWol,out,QNn,QNn,QNn,HIDn,-1,-1,0);
}

// round 8
// speedup vs baseline: 2.6056x; 1.0041x over previous
#include <cuda_runtime.h>
#include <cuda_bf16.h>
#include <math.h>
#include <float.h>

#define Bn 2
#define Sn 1024
#define HIDn 2048
#define NHn 16
#define NKVn 8
#define Dn 128
#define Mn (Bn*Sn)
#define QNn (NHn*Dn)
#define KNn (NKVn*Dn)
#define FQEPS 1.5259021896696422e-09f
#define N_HS (Mn*HIDn)
#define N_Q  (Mn*QNn)
#define N_K  (Mn*KNn)
#define N_SC ((size_t)Bn*NHn*Sn*Sn)
#define NROWS (Bn*NHn*Sn)
#define OUT_MAIN (Mn*HIDn)

enum {S_HS=0,S_QLIN,S_QRMS,S_QRMS2,S_KLIN,S_KRMS,S_KRMS2,S_QP1,S_QP2,S_QSUM,
      S_KP1,S_KP2,S_KSUM,S_V,S_SC,S_AMIN,S_AMIN2,S_UNM,S_P,S_CTX,NSLOT};

__device__ float g_red[2*NSLOT];
__device__ float g_lin[N_Q];
__device__ float g_qr[N_Q];
__device__ float g_kr[N_K];
__device__ float g_v[N_K];
__device__ float g_ctx[N_Q];
__device__ float g_scores[N_SC];
__device__ float g_amin[NROWS];
__device__ __nv_bfloat16 g_hsh[N_HS], g_hsl[N_HS];
__device__ __nv_bfloat16 g_wqh[QNn*HIDn], g_wql[QNn*HIDn];
__device__ __nv_bfloat16 g_wkh[KNn*HIDn], g_wkl[KNn*HIDn];
__device__ __nv_bfloat16 g_wvh[KNn*HIDn], g_wvl[KNn*HIDn];
__device__ __nv_bfloat16 g_woh[HIDn*QNn], g_wol[HIDn*QNn];
__device__ __nv_bfloat16 g_qh[N_Q], g_ql[N_Q];
__device__ __nv_bfloat16 g_kq8[N_K];
__device__ __nv_bfloat16 g_vq8[N_K];
__device__ __nv_bfloat16 g_ch[N_Q], g_cl[N_Q];

__device__ __forceinline__ void atomicMinF(float* a,float v){
  int* ai=(int*)a; int cur=*ai;
  while(v<__int_as_float(cur)){int old=atomicCAS(ai,cur,__float_as_int(v)); if(old==cur)break; cur=old;}
}
__device__ __forceinline__ void atomicMaxF(float* a,float v){
  int* ai=(int*)a; int cur=*ai;
  while(v>__int_as_float(cur)){int old=atomicCAS(ai,cur,__float_as_int(v)); if(old==cur)break; cur=old;}
}
__device__ __forceinline__ float warp_min(float v){
  #pragma unroll
  for(int o=16;o;o>>=1) v=fminf(v,__shfl_xor_sync(0xffffffffu,v,o));
  return v;
}
__device__ __forceinline__ float warp_max(float v){
  #pragma unroll
  for(int o=16;o;o>>=1) v=fmaxf(v,__shfl_xor_sync(0xffffffffu,v,o));
  return v;
}
__device__ __forceinline__ float warp_sum(float v){
  #pragma unroll
  for(int o=16;o;o>>=1) v+=__shfl_xor_sync(0xffffffffu,v,o);
  return v;
}
__device__ __forceinline__ void red_minmax_atomic(float lmn,float lmx,int slot){
  __shared__ float smn[8],smx[8];
  lmn=warp_min(lmn); lmx=warp_max(lmx);
  int lane=threadIdx.x&31,w=threadIdx.x>>5,nw=(blockDim.x+31)>>5;
  __syncthreads();
  if(lane==0){smn[w]=lmn;smx[w]=lmx;}
  __syncthreads();
  if(w==0){
    lmn=(lane<nw)?smn[lane]:FLT_MAX;
    lmx=(lane<nw)?smx[lane]:-FLT_MAX;
    lmn=warp_min(lmn); lmx=warp_max(lmx);
    if(lane==0){atomicMinF(&g_red[2*slot],lmn); atomicMaxF(&g_red[2*slot+1],lmx);}
  }
}
__device__ __forceinline__ float blk_max_b(float v){
  __shared__ float sh[8]; __shared__ float r;
  v=warp_max(v);
  int lane=threadIdx.x&31,w=threadIdx.x>>5,nw=(blockDim.x+31)>>5;
  __syncthreads();
  if(lane==0) sh[w]=v;
  __syncthreads();
  if(threadIdx.x==0){float m=-FLT_MAX; for(int i=0;i<nw;i++)m=fmaxf(m,sh[i]); r=m;}
  __syncthreads();
  return r;
}
__device__ __forceinline__ float blk_sum_b(float v){
  __shared__ float sh[8]; __shared__ float r;
  v=warp_sum(v);
  int lane=threadIdx.x&31,w=threadIdx.x>>5,nw=(blockDim.x+31)>>5;
  __syncthreads();
  if(lane==0) sh[w]=v;
  __syncthreads();
  if(threadIdx.x==0){float m=0.f; for(int i=0;i<nw;i++)m+=sh[i]; r=m;}
  __syncthreads();
  return r;
}
__device__ __forceinline__ float fq_range_d(float x,float mn,float mx){
  float scale=fmaxf((mx-mn)/65535.0f,FQEPS);
  float zp=rintf(-mn/scale);
  float q=fminf(fmaxf(rintf(x/scale)+zp,0.0f),65535.0f);
  return (q-zp)*scale;
}
__device__ __forceinline__ void get_params(int t,int s,float&a0,float&a1,float&a2){
  float mn=g_red[2*s],mx=g_red[2*s+1];
  a0=fminf(mn,0.f); a1=fmaxf(mx,0.f); a2=1;
  if(t==2){
    float lo=fq_range_d(mn,a0,a1),hi=fq_range_d(mx,a0,a1);
    a2=fmaxf(fmaxf(fabsf(lo),fabsf(hi))/127.0f,1e-12f);
  }
}
__device__ __forceinline__ void split_bf(float v,__nv_bfloat16& h,__nv_bfloat16& l){
  h=__float2bfloat16_rn(v);
  l=__float2bfloat16_rn(v-__bfloat162float(h));
}
__device__ __forceinline__ unsigned sptr(const void* p){
  return (unsigned)__cvta_generic_to_shared(p);
}
__device__ __forceinline__ void ldsm4(unsigned* r, unsigned addr){
  asm volatile("ldmatrix.sync.aligned.m8n8.x4.shared.b16 {%0,%1,%2,%3},[%4];"
    : "=r"(r[0]),"=r"(r[1]),"=r"(r[2]),"=r"(r[3]) : "r"(addr));
}
__device__ __forceinline__ void ldsm4t(unsigned* r, unsigned addr){
  asm volatile("ldmatrix.sync.aligned.m8n8.x4.trans.shared.b16 {%0,%1,%2,%3},[%4];"
    : "=r"(r[0]),"=r"(r[1]),"=r"(r[2]),"=r"(r[3]) : "r"(addr));
}
__device__ __forceinline__ void cpa16(void* s,const void* g){
  asm volatile("cp.async.cg.shared.global [%0],[%1],16;"::"r"(sptr(s)),"l"(g));
}
#define CPCOMMIT() asm volatile("cp.async.commit_group;")
#define CPWAIT1()  asm volatile("cp.async.wait_group 1;")
#define MMA16816(d,a,b0,b1) \
  asm volatile("mma.sync.aligned.m16n8k16.row.col.f32.bf16.bf16.f32 " \
    "{%0,%1,%2,%3},{%4,%5,%6,%7},{%8,%9},{%0,%1,%2,%3};" \
    : "+f"(d[0]),"+f"(d[1]),"+f"(d[2]),"+f"(d[3]) \
    : "r"(a[0]),"r"(a[1]),"r"(a[2]),"r"(a[3]),"r"(b0),"r"(b1))

__global__ void k_init(float* __restrict__ amin){
  int gid=blockIdx.x*256+threadIdx.x;
  if(gid<NSLOT){g_red[2*gid]=FLT_MAX; g_red[2*gid+1]=-FLT_MAX;}
  amin[gid]=FLT_MAX;
}
__global__ void k_wsplit(const float* __restrict__ W,__nv_bfloat16* __restrict__ wh,
                         __nv_bfloat16* __restrict__ wl){
  int g=blockIdx.x*blockDim.x+threadIdx.x;
  float w=W[g];
  float a=fabsf(w);
  #pragma unroll
  for(int o=16;o;o>>=1) a=fmaxf(a,__shfl_xor_sync(0xffffffffu,a,o));
  float s=fmaxf(a/7.0f,1e-12f);
  float v=fminf(fmaxf(rintf(w/s),-8.0f),7.0f)*s;
  split_bf(v,wh[g],wl[g]);
}
__global__ void k_minmax(const float* __restrict__ x,int n,int slot){
  int i=blockIdx.x*blockDim.x+threadIdx.x, st=gridDim.x*blockDim.x;
  float lmn=FLT_MAX,lmx=-FLT_MAX;
  for(;i<n;i+=st){float v=x[i]; lmn=fminf(lmn,v); lmx=fmaxf(lmx,v);}
  red_minmax_atomic(lmn,lmx,slot);
}
__global__ void k_fqsplit(const float* __restrict__ in,__nv_bfloat16* __restrict__ hi,
                          __nv_bfloat16* __restrict__ lo,int n,int slot){
  float a0,a1,a2; get_params(1,slot,a0,a1,a2);
  int i=blockIdx.x*blockDim.x+threadIdx.x, st=gridDim.x*blockDim.x;
  for(;i<n;i+=st){
    float v=fq_range_d(in[i],a0,a1);
    split_bf(v,hi[i],lo[i]);
  }
}
__global__ void k_fq8q(const float* __restrict__ in,__nv_bfloat16* __restrict__ q8,
                       int n,int slot){
  float a0,a1,a2; get_params(2,slot,a0,a1,a2);
  int i=blockIdx.x*blockDim.x+threadIdx.x, st=gridDim.x*blockDim.x;
  for(;i<n;i+=st){
    float v=fq_range_d(in[i],a0,a1);
    float q=fminf(fmaxf(rintf(v/a2),-128.f),127.f);
    q8[i]=__float2bfloat16_rn(q);
  }
}
__global__ void k_pattn(const float* __restrict__ sc,float* __restrict__ attn){
  float a0,a1,a2; get_params(1,S_P,a0,a1,a2);
  size_t i=((size_t)blockIdx.x*blockDim.x+threadIdx.x)*4;
  size_t st=(size_t)gridDim.x*blockDim.x*4;
  for(;i<N_SC;i+=st){
    float4 x=*(const float4*)&sc[i];
    *(float4*)&attn[i]=make_float4(fq_range_d(x.x,a0,a1),fq_range_d(x.y,a0,a1),
                                   fq_range_d(x.z,a0,a1),fq_range_d(x.w,a0,a1));
  }
}
__global__ void k_rms(float* __restrict__ x,const float* __restrict__ w,
                      int sIn,int sOut,int sOut2){
  int row=blockIdx.x,d=threadIdx.x;
  float mn=fminf(g_red[2*sIn],0.f),mx=fmaxf(g_red[2*sIn+1],0.f);
  size_t idx=(size_t)row*Dn+d;
  float v=fq_range_d(x[idx],mn,mx);
  float s=warp_sum(v*v);
  __shared__ float sh[4];
  if((d&31)==0) sh[d>>5]=s;
  __syncthreads();
  float var=(sh[0]+sh[1]+sh[2]+sh[3])*(1.0f/128.0f);
  float y=v*(1.0f/sqrtf(var+1e-6f))*w[d];
  x[idx]=y;
  red_minmax_atomic(y,y,sOut);
  float m2n=(d>=64)?y:FLT_MAX, m2x=(d>=64)?y:-FLT_MAX;
  red_minmax_atomic(m2n,m2x,sOut2);
}
// rope constant prologue shared by rope1/rope2
#define ROPE_CONSTS \
  float mnY=g_red[2*sRMS],mxY=g_red[2*sRMS+1]; \
  float c10=fminf(mnY,0.f),c11=fmaxf(mxY,0.f); \
  float amn=fq_range_d(mnY,c10,c11),amx=fq_range_d(mxY,c10,c11); \
  float c20=fminf(amn,0.f),c21=fmaxf(amx,0.f); \
  float y2n=g_red[2*sRMS2],y2x=g_red[2*sRMS2+1]; \
  float x2n=fq_range_d(fq_range_d(y2n,c10,c11),c20,c21); \
  float x2x=fq_range_d(fq_range_d(y2x,c10,c11),c20,c21); \
  float nTn=-x2x,nTx=-x2n; \
  float n0=fminf(nTn,0.f),n1=fmaxf(nTx,0.f); \
  float negLo=fq_range_d(nTn,n0,n1),negHi=fq_range_d(nTx,n0,n1); \
  float qbMn=fq_range_d(amn,c20,c21),qbMx=fq_range_d(amx,c20,c21); \
  float cc0=fminf(fminf(qbMn,negLo),0.f),cc1=fmaxf(fmaxf(qbMx,negHi),0.f);
#define ROPE_BODY(QB,ROT) \
    float QB=fq_range_d(fq_range_d(y[i],c10,c11),c20,c21); \
    float ROT; \
    if(d<64){ \
      float qbp=fq_range_d(fq_range_d(y[i+64],c10,c11),c20,c21); \
      ROT=fq_range_d(fq_range_d(-qbp,n0,n1),cc0,cc1); \
    } else { \
      float qbp=fq_range_d(fq_range_d(y[i-64],c10,c11),c20,c21); \
      ROT=fq_range_d(qbp,cc0,cc1); \
    }
// rope1: pure reduction (no writes)
__global__ void k_rope1(const float* __restrict__ y,const float* __restrict__ cosb,
                        const float* __restrict__ sinb,int H,int n,
                        int sRMS,int sRMS2,int sP1,int sP2){
  ROPE_CONSTS
  int i0=blockIdx.x*blockDim.x+threadIdx.x, st=gridDim.x*blockDim.x;
  float l1n=FLT_MAX,l1x=-FLT_MAX,l2n=FLT_MAX,l2x=-FLT_MAX;
  for(int i=i0;i<n;i+=st){
    int d=i%Dn; int r=i/Dn; int s=(r/H)%Sn; int b=r/(H*Sn);
    ROPE_BODY(qb,rot)
    int ci=(b*Sn+s)*Dn+d;
    float v1=qb*cosb[ci], v2=rot*sinb[ci];
    l1n=fminf(l1n,v1); l1x=fmaxf(l1x,v1);
    l2n=fminf(l2n,v2); l2x=fmaxf(l2x,v2);
  }
  red_minmax_atomic(l1n,l1x,sP1);
  red_minmax_atomic(l2n,l2x,sP2);
}
// rope2: recompute products, fq+add, transpose-write
__global__ void k_rope2(const float* __restrict__ y,const float* __restrict__ cosb,
                        const float* __restrict__ sinb,float* __restrict__ out,
                        int H,int n,int sRMS,int sRMS2,int sP1,int sP2,int sSum){
  ROPE_CONSTS
  float a0=fminf(g_red[2*sP1],0.f),a1=fmaxf(g_red[2*sP1+1],0.f);
  float b0=fminf(g_red[2*sP2],0.f),b1=fmaxf(g_red[2*sP2+1],0.f);
  int i0=blockIdx.x*blockDim.x+threadIdx.x, st=gridDim.x*blockDim.x;
  float lmn=FLT_MAX,lmx=-FLT_MAX;
  for(int i=i0;i<n;i+=st){
    int d=i%Dn; int r=i/Dn; int h=r%H; int s=(r/H)%Sn; int b=r/(H*Sn);
    ROPE_BODY(qb,rot)
    int ci=(b*Sn+s)*Dn+d;
    float v1=qb*cosb[ci], v2=rot*sinb[ci];
    float v=fq_range_d(v1,a0,a1)+fq_range_d(v2,b0,b1);
    out[((size_t)(b*H+h)*Sn+s)*Dn+d]=v;
    lmn=fminf(lmn,v); lmx=fmaxf(lmx,v);
  }
  red_minmax_atomic(lmn,lmx,sSum);
}

#define ASZ (128*40)
#define VSZ (32*136)
#define FSZ (128*32)

// ---------- 128x128 double-buffered bf16 mma.sync NT GEMM ----------
template<bool UBL>
__global__ __launch_bounds__(256) void mma_nt(
  const __nv_bfloat16* __restrict__ Ah,const __nv_bfloat16* __restrict__ Al,
  const __nv_bfloat16* __restrict__ Bh,const __nv_bfloat16* __restrict__ Bl,
  float* __restrict__ C,int K,int lda,int ldb,int ldc,
  int sOut,int scaleSlot,int batch)
{
  extern __shared__ __nv_bfloat16 sm[];
  __nv_bfloat16* Abase=sm;
  __nv_bfloat16* Bbase=sm+4*ASZ;
  int z=blockIdx.z;
  if(batch==1){
    int b=z>>4,h=z&15;
    size_t ao=(size_t)z*Sn*Dn, bo=(size_t)(b*NKVn+(h>>1))*Sn*Dn, co=(size_t)z*Sn*Sn;
    Ah+=ao; Al+=ao; Bh+=bo; Bl+=bo; C+=co;
  }
  int tid=threadIdx.x, lane=tid&31, w=tid>>5;
  int wm=(w&3)*32, wn=(w>>2)*64;
  int g=lane>>2, t4=lane&3;
  int m0=blockIdx.y*128, n0=blockIdx.x*128;
  int mat=lane>>3, mrow=lane&7;
  float acc[2][8][4];
  #pragma unroll
  for(int i=0;i<2;i++)
    #pragma unroll
    for(int j=0;j<8;j++)
      #pragma unroll
      for(int r=0;r<4;r++) acc[i][j][r]=0.f;

  auto loadST=[&](int st,int k0){
    #pragma unroll
    for(int rep=0;rep<2;rep++){
      int c=tid+rep*256; int row=c>>2, col=(c&3)*8;
      cpa16(&Abase[(st*2+0)*ASZ+row*40+col],Ah+(size_t)(m0+row)*lda+k0+col);
      cpa16(&Abase[(st*2+1)*ASZ+row*40+col],Al+(size_t)(m0+row)*lda+k0+col);
      cpa16(&Bbase[(UBL?(st*2):st)*ASZ+row*40+col],Bh+(size_t)(n0+row)*ldb+k0+col);
      if(UBL) cpa16(&Bbase[(st*2+1)*ASZ+row*40+col],Bl+(size_t)(n0+row)*ldb+k0+col);
    }
  };
  int niter=K/32;
  loadST(0,0); CPCOMMIT();
  loadST(1,32); CPCOMMIT();
  for(int i=0;i<niter;i++){
    CPWAIT1(); __syncthreads();
    int st=i&1;
    const __nv_bfloat16* As0=Abase+(st*2+0)*ASZ;
    const __nv_bfloat16* As1=Abase+(st*2+1)*ASZ;
    const __nv_bfloat16* Bs0=Bbase+(UBL?(st*2):st)*ASZ;
    const __nv_bfloat16* Bs1=UBL?(Bbase+(st*2+1)*ASZ):Bs0;
    #pragma unroll
    for(int kk=0;kk<32;kk+=16){
      unsigned af[2][2][4];
      #pragma unroll
      for(int mt=0;mt<2;mt++){
        ldsm4(af[mt][0],sptr(&As0[(wm+mt*16+(mat&1)*8+mrow)*40 + kk + (mat>>1)*8]));
        ldsm4(af[mt][1],sptr(&As1[(wm+mt*16+(mat&1)*8+mrow)*40 + kk + (mat>>1)*8]));
      }
      unsigned bf[8][2];
      #pragma unroll
      for(int hf=0;hf<4;hf++){
        unsigned r[4];
        ldsm4(r,sptr(&Bs0[(wn+hf*16+(mat&1)*8+mrow)*40 + kk + (mat>>1)*8]));
        bf[hf*2+0][0]=r[0]; bf[hf*2+1][0]=r[1];
        bf[hf*2+0][1]=r[2]; bf[hf*2+1][1]=r[3];
      }
      #pragma unroll
      for(int mt=0;mt<2;mt++)
        #pragma unroll
        for(int nt=0;nt<8;nt++){
          MMA16816(acc[mt][nt],af[mt][0],bf[nt][0],bf[nt][1]);
          MMA16816(acc[mt][nt],af[mt][1],bf[nt][0],bf[nt][1]);
        }
      if(UBL){
        #pragma unroll
        for(int hf=0;hf<4;hf++){
          unsigned r[4];
          ldsm4(r,sptr(&Bs1[(wn+hf*16+(mat&1)*8+mrow)*40 + kk + (mat>>1)*8]));
          bf[hf*2+0][0]=r[0]; bf[hf*2+1][0]=r[1];
          bf[hf*2+0][1]=r[2]; bf[hf*2+1][1]=r[3];
        }
        #pragma unroll
        for(int mt=0;mt<2;mt++)
          #pragma unroll
          for(int nt=0;nt<8;nt++)
            MMA16816(acc[mt][nt],af[mt][0],bf[nt][0],bf[nt][1]);
      }
    }
    __syncthreads();
    if(i+2<niter) loadST(st,(i+2)*32);
    CPCOMMIT();
  }
  float scl=1.f;
  if(scaleSlot>=0){float a0,a1,a2; get_params(2,scaleSlot,a0,a1,a2); scl=a2;}
  float lmn=FLT_MAX,lmx=-FLT_MAX;
  float umn=FLT_MAX,umx=-FLT_MAX;   // masked (causal) raw minmax, batch==1 only
  #pragma unroll
  for(int mt=0;mt<2;mt++){
    float rmnA=FLT_MAX,rmnB=FLT_MAX;  // raw row minima for rows rA, rA+8
    int rA=m0+wm+mt*16+g;
    #pragma unroll
    for(int nt=0;nt<8;nt++){
      int c=n0+wn+nt*8+t4*2;
      float v0=acc[mt][nt][0]*scl, v1=acc[mt][nt][1]*scl;
      float v2=acc[mt][nt][2]*scl, v3=acc[mt][nt][3]*scl;
      C[(size_t)rA*ldc+c]=v0; C[(size_t)rA*ldc+c+1]=v1;
      C[(size_t)(rA+8)*ldc+c]=v2; C[(size_t)(rA+8)*ldc+c+1]=v3;
      lmn=fminf(fminf(lmn,fminf(v0,v1)),fminf(v2,v3));
      lmx=fmaxf(fmaxf(lmx,fmaxf(v0,v1)),fmaxf(v2,v3));
      if(batch==1){
        rmnA=fminf(rmnA,fminf(v0,v1)); rmnB=fminf(rmnB,fminf(v2,v3));
        if(c<=rA){umn=fminf(umn,v0);umx=fmaxf(umx,v0);}
        if(c+1<=rA){umn=fminf(umn,v1);umx=fmaxf(umx,v1);}
        if(c<=rA+8){umn=fminf(umn,v2);umx=fmaxf(umx,v2);}
        if(c+1<=rA+8){umn=fminf(umn,v3);umx=fmaxf(umx,v3);}
      }
    }
    if(batch==1){
      rmnA=fminf(rmnA,__shfl_xor_sync(0xffffffffu,rmnA,1));
      rmnA=fminf(rmnA,__shfl_xor_sync(0xffffffffu,rmnA,2));
      rmnB=fminf(rmnB,__shfl_xor_sync(0xffffffffu,rmnB,1));
      rmnB=fminf(rmnB,__shfl_xor_sync(0xffffffffu,rmnB,2));
      if(t4==0){
        atomicMinF(&g_amin[z*Sn+rA],rmnA);
        atomicMinF(&g_amin[z*Sn+rA+8],rmnB);
      }
    }
  }
  if(sOut>=0) red_minmax_atomic(lmn,lmx,sOut);
  if(batch==1) red_minmax_atomic(umn,umx,S_UNM);
}

// ---------- AV (NN): A = raw probs f32, fq+split in-kernel ----------
__global__ __launch_bounds__(256) void mma_av(
  const float* __restrict__ Praw,const __nv_bfloat16* __restrict__ Vq,
  float* __restrict__ C)
{
  extern __shared__ __nv_bfloat16 sm[];
  __nv_bfloat16* Abase=sm;                         // 4*ASZ bf16
  __nv_bfloat16* Vbase=sm+4*ASZ;                   // 2*VSZ bf16
  float* Fbase=(float*)(sm+4*ASZ+2*VSZ);           // 2*FSZ f32 staging
  int z=blockIdx.z,b=z>>4,h=z&15,h2=h>>1;
  Praw+=(size_t)z*Sn*Sn;
  Vq+=(size_t)b*Sn*KNn + h2*Dn;
  C +=(size_t)b*Sn*QNn + h*Dn;
  int tid=threadIdx.x, lane=tid&31, w=tid>>5;
  int wm=(w&3)*32, wn=(w>>2)*64;
  int g=lane>>2, t4=lane&3;
  int m0=blockIdx.y*128;
  int mat=lane>>3, mrow=lane&7;
  float p0,p1_,pd; get_params(1,S_P,p0,p1_,pd);
  float acc[2][8][4];
  #pragma unroll
  for(int i=0;i<2;i++)
    #pragma unroll
    for(int j=0;j<8;j++)
      #pragma unroll
      for(int r=0;r<4;r++) acc[i][j][r]=0.f;

  auto loadST=[&](int st,int k0){
    #pragma unroll
    for(int rep=0;rep<4;rep++){
      int c=tid+rep*256; int row=c>>3, cc=(c&7)*4;
      cpa16(&Fbase[st*FSZ+row*32+cc],Praw+(size_t)(m0+row)*Sn+k0+cc);
    }
    #pragma unroll
    for(int rep=0;rep<2;rep++){
      int c=tid+rep*256; int vr=c>>4, vc=(c&15)*8;
      cpa16(&Vbase[st*VSZ+vr*136+vc],Vq+(size_t)(k0+vr)*KNn+vc);
    }
  };
  loadST(0,0); CPCOMMIT();
  loadST(1,32); CPCOMMIT();
  int niter=Sn/32;
  for(int i=0;i<niter;i++){
    CPWAIT1(); __syncthreads();
    int st=i&1;
    // convert raw f32 probs -> fq -> bf16 hi/lo in smem
    #pragma unroll
    for(int rep=0;rep<16;rep++){
      int c=tid+rep*256; int row=c>>5, k=c&31;
      float p=Fbase[st*FSZ+row*32+k];
      float v=fq_range_d(p,p0,p1_);
      __nv_bfloat16 hh,ll; split_bf(v,hh,ll);
      Abase[(st*2+0)*ASZ+row*40+k]=hh;
      Abase[(st*2+1)*ASZ+row*40+k]=ll;
    }
    __syncthreads();
    const __nv_bfloat16* As0=Abase+(st*2+0)*ASZ;
    const __nv_bfloat16* As1=Abase+(st*2+1)*ASZ;
    const __nv_bfloat16* Vs=Vbase+st*VSZ;
    #pragma unroll
    for(int kk=0;kk<32;kk+=16){
      unsigned af[2][2][4];
      #pragma unroll
      for(int mt=0;mt<2;mt++){
        ldsm4(af[mt][0],sptr(&As0[(wm+mt*16+(mat&1)*8+mrow)*40 + kk + (mat>>1)*8]));
        ldsm4(af[mt][1],sptr(&As1[(wm+mt*16+(mat&1)*8+mrow)*40 + kk + (mat>>1)*8]));
      }
      unsigned bf[8][2];
      #pragma unroll
      for(int hf=0;hf<4;hf++){
        unsigned r[4];
        ldsm4t(r,sptr(&Vs[(kk+(mat>>1)*8+mrow)*136 + wn + hf*16 + (mat&1)*8]));
        bf[hf*2+0][0]=r[0]; bf[hf*2+1][0]=r[1];
        bf[hf*2+0][1]=r[2]; bf[hf*2+1][1]=r[3];
      }
      #pragma unroll
      for(int mt=0;mt<2;mt++)
        #pragma unroll
        for(int nt=0;nt<8;nt++){
          MMA16816(acc[mt][nt],af[mt][0],bf[nt][0],bf[nt][1]);
          MMA16816(acc[mt][nt],af[mt][1],bf[nt][0],bf[nt][1]);
        }
    }
    __syncthreads();
    if(i+2<niter) loadST(st,(i+2)*32);
    CPCOMMIT();
  }
  float a0,a1,scl; get_params(2,S_V,a0,a1,scl);
  float lmn=FLT_MAX,lmx=-FLT_MAX;
  #pragma unroll
  for(int mt=0;mt<2;mt++)
    #pragma unroll
    for(int nt=0;nt<8;nt++){
      int r0=m0+wm+mt*16+g, c=wn+nt*8+t4*2;
      float v0=acc[mt][nt][0]*scl, v1=acc[mt][nt][1]*scl;
      float v2=acc[mt][nt][2]*scl, v3=acc[mt][nt][3]*scl;
      C[(size_t)r0*QNn+c]=v0; C[(size_t)r0*QNn+c+1]=v1;
      C[(size_t)(r0+8)*QNn+c]=v2; C[(size_t)(r0+8)*QNn+c+1]=v3;
      lmn=fminf(fminf(lmn,fminf(v0,v1)),fminf(v2,v3));
      lmx=fmaxf(fmaxf(lmx,fmaxf(v0,v1)),fmaxf(v2,v3));
    }
  red_minmax_atomic(lmn,lmx,S_CTX);
}

// reduce raw per-row minima -> S_AMIN / S_AMIN2 (raw)
__global__ void k_aminred(const float* __restrict__ amin){
  int i=blockIdx.x*256+threadIdx.x;
  float v=amin[i];
  red_minmax_atomic(v,v,S_AMIN);
  int s=i%Sn;
  float m2n=(s<Sn-1)?v:FLT_MAX, m2x=(s<Sn-1)?v:-FLT_MAX;
  red_minmax_atomic(m2n,m2x,S_AMIN2);
}

// k_p2: recompute fq chain from raw scores (T1), softmax, write raw probs
__global__ void k_p2(float* __restrict__ sc,const float* __restrict__ amin){
  int row=blockIdx.x; int s=row%Sn;
  float mnS=g_red[2*S_SC],mxS=g_red[2*S_SC+1];
  float q0=fminf(mnS,0.f),q1=fmaxf(mxS,0.f);
  float scal=(float)(0.08838834764831843);
  float scq=fq_range_d(scal,fminf(scal,0.f),fmaxf(scal,0.f));
  float lo=fq_range_d(mnS,q0,q1)*scq,hi=fq_range_d(mxS,q0,q1)*scq;
  float r0=fminf(lo,0.f),r1=fmaxf(hi,0.f);
  // T1(x) = fq(fq(x,q0,q1)*scq, r0,r1)
  float anr=g_red[2*S_AMIN],axr=g_red[2*S_AMIN+1];
  float an=fq_range_d(fq_range_d(anr,q0,q1)*scq,r0,r1);
  float ax=fq_range_d(fq_range_d(axr,q0,q1)*scq,r0,r1);
  float a0=fminf(an,0.f),a1=fmaxf(ax,0.f);
  float c20=fq_range_d(-20.0f,-20.0f,0.0f);
  float tn=fq_range_d(an,a0,a1)+c20,tx2=fq_range_d(ax,a0,a1)+c20;
  float v0=fminf(tn,0.f),v1=fmaxf(tx2,0.f);
  float a2nr=g_red[2*S_AMIN2],a2xr=g_red[2*S_AMIN2+1];
  float a2n=fq_range_d(fq_range_d(a2nr,q0,q1)*scq,r0,r1);
  float a2x=fq_range_d(fq_range_d(a2xr,q0,q1)*scq,r0,r1);
  float vlo=fq_range_d(fq_range_d(a2n,a0,a1)+c20,v0,v1);
  float vhi=fq_range_d(fq_range_d(a2x,a0,a1)+c20,v0,v1);
  float unr=g_red[2*S_UNM],uxr=g_red[2*S_UNM+1];
  float un=fq_range_d(fq_range_d(unr,q0,q1)*scq,r0,r1);
  float ux=fq_range_d(fq_range_d(uxr,q0,q1)*scq,r0,r1);
  float m0=fminf(fminf(un,vlo),0.f),m1=fmaxf(fmaxf(ux,vhi),0.f);
  float am=fq_range_d(fq_range_d(amin[row],q0,q1)*scq,r0,r1);
  float vv=fq_range_d(fq_range_d(am,a0,a1)+c20,v0,v1);
  float vm=fq_range_d(vv,m0,m1);
  size_t base=(size_t)row*Sn;
  int t0=threadIdx.x*4;
  float4 xv=*(const float4*)&sc[base+t0];
  float x[4]={xv.x,xv.y,xv.z,xv.w};
  float lmx=-FLT_MAX;
  #pragma unroll
  for(int j=0;j<4;j++){
    float a=fq_range_d(fq_range_d(x[j],q0,q1)*scq,r0,r1);
    x[j]=(t0+j<=s)?fq_range_d(a,m0,m1):vm;
    lmx=fmaxf(lmx,x[j]);
  }
  float m=blk_max_b(lmx);
  float ls=0.f;
  #pragma unroll
  for(int j=0;j<4;j++){ x[j]=expf(x[j]-m); ls+=x[j]; }
  float sum=blk_sum_b(ls);
  float pn=FLT_MAX,px=-FLT_MAX;
  #pragma unroll
  for(int j=0;j<4;j++){
    float p=x[j]/sum; x[j]=p;
    pn=fminf(pn,p); px=fmaxf(px,p);
  }
  *(float4*)&sc[base+t0]=make_float4(x[0],x[1],x[2],x[3]);
  red_minmax_atomic(pn,px,S_P);
}

extern "C" void kernel_launch(void* const* d_in,const int* in_sizes,int n_in,
                              void* d_out,int out_size){
  const float* hs  =(const float*)d_in[0];
  const float* cosb=(const float*)d_in[1];
  const float* sinb=(const float*)d_in[2];
  const float* Wq  =(const float*)d_in[4];
  const float* Wk  =(const float*)d_in[5];
  const float* Wv  =(const float*)d_in[6];
  const float* Wo  =(const float*)d_in[7];
  const float* qw  =(const float*)d_in[8];
  const float* kw  =(const float*)d_in[9];
  float* out=(float*)d_out;

  int SM_T=8*ASZ*2;                           // 81920 B
  int SM_F=6*ASZ*2;                           // 61440 B
  int SM_AV=4*ASZ*2+2*VSZ*2+2*FSZ*4;          // 91136 B
  static int smset=0;
  if(!smset){
    cudaFuncSetAttribute(mma_nt<true>, cudaFuncAttributeMaxDynamicSharedMemorySize, SM_T);
    cudaFuncSetAttribute(mma_nt<false>,cudaFuncAttributeMaxDynamicSharedMemorySize, SM_F);
    cudaFuncSetAttribute(mma_av,       cudaFuncAttributeMaxDynamicSharedMemorySize, SM_AV);
    smset=1;
  }

  float *pLin,*pQr,*pKr,*pV,*pCtx,*pSc,*pAmin;
  __nv_bfloat16 *pHsh,*pHsl,*pWqh,*pWql,*pWkh,*pWkl,*pWvh,*pWvl,*pWoh,*pWol;
  __nv_bfloat16 *pQh,*pQl,*pKq,*pVq,*pCh,*pCl;
  cudaGetSymbolAddress((void**)&pLin,g_lin);
  cudaGetSymbolAddress((void**)&pQr,g_qr);
  cudaGetSymbolAddress((void**)&pKr,g_kr);
  cudaGetSymbolAddress((void**)&pV,g_v);
  cudaGetSymbolAddress((void**)&pCtx,g_ctx);
  cudaGetSymbolAddress((void**)&pSc,g_scores);
  cudaGetSymbolAddress((void**)&pAmin,g_amin);
  cudaGetSymbolAddress((void**)&pHsh,g_hsh); cudaGetSymbolAddress((void**)&pHsl,g_hsl);
  cudaGetSymbolAddress((void**)&pWqh,g_wqh); cudaGetSymbolAddress((void**)&pWql,g_wql);
  cudaGetSymbolAddress((void**)&pWkh,g_wkh); cudaGetSymbolAddress((void**)&pWkl,g_wkl);
  cudaGetSymbolAddress((void**)&pWvh,g_wvh); cudaGetSymbolAddress((void**)&pWvl,g_wvl);
  cudaGetSymbolAddress((void**)&pWoh,g_woh); cudaGetSymbolAddress((void**)&pWol,g_wol);
  cudaGetSymbolAddress((void**)&pQh,g_qh); cudaGetSymbolAddress((void**)&pQl,g_ql);
  cudaGetSymbolAddress((void**)&pKq,g_kq8); cudaGetSymbolAddress((void**)&pVq,g_vq8);
  cudaGetSymbolAddress((void**)&pCh,g_ch); cudaGetSymbolAddress((void**)&pCl,g_cl);

  k_init<<<NROWS/256,256>>>(pAmin);
  k_wsplit<<<QNn*HIDn/256,256>>>(Wq,pWqh,pWql);
  k_wsplit<<<KNn*HIDn/256,256>>>(Wk,pWkh,pWkl);
  k_wsplit<<<KNn*HIDn/256,256>>>(Wv,pWvh,pWvl);
  k_wsplit<<<HIDn*QNn/256,256>>>(Wo,pWoh,pWol);
  k_minmax<<<1024,256>>>(hs,N_HS,S_HS);
  k_fqsplit<<<2048,256>>>(hs,pHsh,pHsl,N_HS,S_HS);
  // Q path
  mma_nt<true><<<dim3(QNn/128,Mn/128,1),256,SM_T>>>(pHsh,pHsl,pWqh,pWql,pLin,HIDn,HIDn,HIDn,QNn,S_QLIN,-1,0);
  k_rms<<<Mn*NHn,128>>>(pLin,qw,S_QLIN,S_QRMS,S_QRMS2);
  k_rope1<<<2048,256>>>(pLin,cosb,sinb,NHn,N_Q,S_QRMS,S_QRMS2,S_QP1,S_QP2);
  k_rope2<<<2048,256>>>(pLin,cosb,sinb,pQr,NHn,N_Q,S_QRMS,S_QRMS2,S_QP1,S_QP2,S_QSUM);
  k_fqsplit<<<2048,256>>>(pQr,pQh,pQl,N_Q,S_QSUM);
  // K path
  mma_nt<true><<<dim3(KNn/128,Mn/128,1),256,SM_T>>>(pHsh,pHsl,pWkh,pWkl,pLin,HIDn,HIDn,HIDn,KNn,S_KLIN,-1,0);
  k_rms<<<Mn*NKVn,128>>>(pLin,kw,S_KLIN,S_KRMS,S_KRMS2);
  k_rope1<<<1024,256>>>(pLin,cosb,sinb,NKVn,N_K,S_KRMS,S_KRMS2,S_KP1,S_KP2);
  k_rope2<<<1024,256>>>(pLin,cosb,sinb,pKr,NKVn,N_K,S_KRMS,S_KRMS2,S_KP1,S_KP2,S_KSUM);
  k_fq8q<<<1024,256>>>(pKr,pKq,N_K,S_KSUM);
  // V path
  mma_nt<true><<<dim3(KNn/128,Mn/128,1),256,SM_T>>>(pHsh,pHsl,pWvh,pWvl,pV,HIDn,HIDn,HIDn,KNn,S_V,-1,0);
  k_fq8q<<<1024,256>>>(pV,pVq,N_K,S_V);
  // scores GEMM with fused raw row-min / masked-minmax reductions
  mma_nt<false><<<dim3(Sn/128,Sn/128,Bn*NHn),256,SM_F>>>(pQh,pQl,pKq,pKq,pSc,Dn,Dn,Dn,Sn,S_SC,S_KSUM,1);
  k_aminred<<<NROWS/256,256>>>(pAmin);
  k_p2<<<NROWS,256>>>(pSc,pAmin);
  if(out_size>=(int)(OUT_MAIN+N_SC))
    k_pattn<<<8192,256>>>(pSc,out+OUT_MAIN);
  // AV (reads raw probs; fq+split in-kernel) + output proj
  mma_av<<<dim3(1,Sn/128,Bn*NHn),256,SM_AV>>>(pSc,pVq,pCtx);
  k_fqsplit<<<2048,256>>>(pCtx,pCh,pCl,N_Q,S_CTX);
  mma_nt<true><<<dim3(HIDn/128,Mn/128,1),256,SM_T>>>(pCh,pCl,pWoh,pWol,out,QNn,QNn,QNn,HIDn,-1,-1,0);
}